// round 4
// baseline (speedup 1.0000x reference)
#include <cuda_runtime.h>
#include <cuda_fp16.h>
#include <math.h>
#include <stdint.h>

#define SQ 2048
#define HDIM 3584
#define NH 16
#define NKV 8
#define HD 256
#define QKVD 8192           // 4096 q + 2048 k + 2048 v
#define QD 4096
#define IDIM 14336

// ---------------- scratch (allocation-free: __device__ globals) ----------------
static __device__ float g_h[SQ*HDIM];
static __device__ float g_qkv[SQ*QKVD];
static __device__ float g_attn[SQ*QD];
static __device__ float g_proj[SQ*HDIM];
static __device__ float g_x1[SQ*HDIM];
static __device__ float g_gu[(size_t)SQ*2*IDIM];
static __device__ float g_down[SQ*HDIM];
static __device__ __half g_act[(size_t)SQ*2*IDIM];        // A' = [Ah|Al], up to [2048, 28672]
static __device__ __half g_wt[(size_t)(2*IDIM)*HDIM];     // B' K-major, up to [28672, 3584]

// ---------------- PTX helpers (arch-agnostic only: sm_80-level) ----------------
__device__ __forceinline__ uint32_t smem_u32(const void* p) {
    uint32_t a;
    asm("{ .reg .u64 t; cvta.to.shared.u64 t, %1; cvt.u32.u64 %0, t; }" : "=r"(a) : "l"(p));
    return a;
}
__device__ __forceinline__ void ldx4(uint32_t& r0, uint32_t& r1, uint32_t& r2, uint32_t& r3, uint32_t a) {
    asm volatile("ldmatrix.sync.aligned.m8n8.x4.shared.b16 {%0,%1,%2,%3}, [%4];"
                 : "=r"(r0), "=r"(r1), "=r"(r2), "=r"(r3) : "r"(a));
}
__device__ __forceinline__ void hmma(float* c, uint32_t a0, uint32_t a1, uint32_t a2, uint32_t a3,
                                     uint32_t b0, uint32_t b1) {
    asm volatile("mma.sync.aligned.m16n8k16.row.col.f32.f16.f16.f32 "
                 "{%0,%1,%2,%3},{%4,%5,%6,%7},{%8,%9},{%0,%1,%2,%3};"
                 : "+f"(c[0]), "+f"(c[1]), "+f"(c[2]), "+f"(c[3])
                 : "r"(a0), "r"(a1), "r"(a2), "r"(a3), "r"(b0), "r"(b1));
}
#define CP_ASYNC16(dst, src) \
    asm volatile("cp.async.cg.shared.global [%0], [%1], 16;" :: "r"(dst), "l"(src))
#define CP_COMMIT() asm volatile("cp.async.commit_group;" ::: "memory")
#define CP_WAIT(n)  asm volatile("cp.async.wait_group %0;" :: "n"(n) : "memory")

// ============ HMMA fp16 split GEMM: C[M,N] = (Ah+Al)[M,2K] @ B'[N,K]^T ============
// A' row-major [M, 2K] fp16 ([Ah | Al]); B' K-major [N, K] fp16. fp32 accumulate.
// CTA tile 128x256x32, 8 warps (warp tile 64x64), 4-stage cp.async, 1 CTA/SM.
#define BM 128
#define BN 256
#define BK 32
#define STG 4
#define ROWH 40                               // halves per smem row (32 + 8 pad)
#define STAGE_A (BM*ROWH*2)                   // 10240
#define STAGE_B (STAGE_A + BN*ROWH*2)         // 30720 per stage
#define SMEM_MMA (STG*STAGE_B)                // 122880

__global__ void __launch_bounds__(256, 1)
gemm_mma(const __half* __restrict__ A, const __half* __restrict__ B,
         float* __restrict__ C, int N, int K) {
    extern __shared__ char smem[];
    uint32_t sbase = smem_u32(smem);
    const int K2 = 2 * K;
    int tid = threadIdx.x, lane = tid & 31, wid = tid >> 5;
    int m0 = blockIdx.x * BM, n0 = blockIdx.y * BN;
    int wm = (wid & 1) * 64, wn = (wid >> 1) * 64;
    int ntiles = K2 / BK;

    // cp.async mapping: thread -> (row = tid/4, 16B seg = tid%4)
    int lr = tid >> 2;
    int lc = (tid & 3) * 8;
    const __half* gA0 = A + (size_t)(m0 + lr) * K2 + lc;
    const __half* gB0 = B + (size_t)(n0 + lr) * K + lc;
    uint32_t sOff = (uint32_t)(lr * ROWH + lc) * 2;

    // ldmatrix fragment addressing (no .trans; same for A and B)
    uint32_t foff = (uint32_t)(((lane & 15) * ROWH) + ((lane >> 4) * 8)) * 2;

    float acc[4][8][4];
#pragma unroll
    for (int a = 0; a < 4; a++)
#pragma unroll
        for (int b = 0; b < 8; b++)
#pragma unroll
            for (int c = 0; c < 4; c++) acc[a][b][c] = 0.f;

    auto LOAD = [&](int kt, int s) {
        int ak = kt * BK;
        int bk = (ak < K) ? ak : ak - K;      // B wraps: [Ah|Al] both hit same B
        uint32_t sA = sbase + s * STAGE_B;
        uint32_t sB = sA + STAGE_A;
#pragma unroll
        for (int h = 0; h < 2; h++)
            CP_ASYNC16(sA + sOff + h * 64 * ROWH * 2, gA0 + (size_t)h * 64 * K2 + ak);
#pragma unroll
        for (int h = 0; h < 4; h++)
            CP_ASYNC16(sB + sOff + h * 64 * ROWH * 2, gB0 + (size_t)h * 64 * K + bk);
    };

#pragma unroll
    for (int s = 0; s < STG - 1; s++) {
        if (s < ntiles) LOAD(s, s);
        CP_COMMIT();
    }

    for (int i = 0; i < ntiles; i++) {
        int pf = i + STG - 1;
        if (pf < ntiles) LOAD(pf, pf % STG);
        CP_COMMIT();
        CP_WAIT(STG - 1);
        __syncthreads();

        int s = i % STG;
        uint32_t aB = sbase + s * STAGE_B;
        uint32_t bB = aB + STAGE_A;
        uint32_t aAddr = aB + (uint32_t)wm * ROWH * 2 + foff;
        uint32_t bAddr = bB + (uint32_t)wn * ROWH * 2 + foff;
#pragma unroll
        for (int ks = 0; ks < 2; ks++) {
            uint32_t af[4][4];
#pragma unroll
            for (int fm = 0; fm < 4; fm++)
                ldx4(af[fm][0], af[fm][1], af[fm][2], af[fm][3],
                     aAddr + (uint32_t)fm * 16 * ROWH * 2 + ks * 32);
            uint32_t b0[8], b1[8];
#pragma unroll
            for (int f2 = 0; f2 < 4; f2++) {
                uint32_t t0, t1, t2, t3;
                ldx4(t0, t1, t2, t3, bAddr + (uint32_t)f2 * 16 * ROWH * 2 + ks * 32);
                b0[f2 * 2] = t0; b1[f2 * 2] = t2;
                b0[f2 * 2 + 1] = t1; b1[f2 * 2 + 1] = t3;
            }
#pragma unroll
            for (int fm = 0; fm < 4; fm++)
#pragma unroll
                for (int fn = 0; fn < 8; fn++)
                    hmma(acc[fm][fn], af[fm][0], af[fm][1], af[fm][2], af[fm][3],
                         b0[fn], b1[fn]);
        }
        __syncthreads();
    }

#pragma unroll
    for (int fm = 0; fm < 4; fm++) {
        int r = m0 + wm + fm * 16 + (lane >> 2);
#pragma unroll
        for (int fn = 0; fn < 8; fn++) {
            int c = n0 + wn + fn * 8 + (lane & 3) * 2;
            *(float2*)&C[(size_t)r * N + c]       = make_float2(acc[fm][fn][0], acc[fm][fn][1]);
            *(float2*)&C[(size_t)(r + 8) * N + c] = make_float2(acc[fm][fn][2], acc[fm][fn][3]);
        }
    }
}

// ================= fp32 -> fp16 split conversions =================
// A' = [Ah | Al], row length 2K
__global__ void convert_act(const float* __restrict__ src, __half* __restrict__ dst, int K) {
    int K4 = K >> 2;
    int idx = blockIdx.x * 256 + threadIdx.x;
    int m = idx / K4, k4 = (idx - m * K4) * 4;
    float4 a = *(const float4*)(src + (size_t)m * K + k4);
    __half h0 = __float2half(a.x), h1 = __float2half(a.y);
    __half h2 = __float2half(a.z), h3 = __float2half(a.w);
    __half l0 = __float2half(a.x - __half2float(h0));
    __half l1 = __float2half(a.y - __half2float(h1));
    __half l2 = __float2half(a.z - __half2float(h2));
    __half l3 = __float2half(a.w - __half2float(h3));
    size_t base = (size_t)m * 2 * K + k4;
    *(__half2*)(dst + base)         = __halves2half2(h0, h1);
    *(__half2*)(dst + base + 2)     = __halves2half2(h2, h3);
    *(__half2*)(dst + base + K)     = __halves2half2(l0, l1);
    *(__half2*)(dst + base + K + 2) = __halves2half2(l2, l3);
}

// W[K,N] fp32 -> out[n_off+n][k] fp16 K-major (transpose)
__global__ void convert_wt(const float* __restrict__ W, __half* __restrict__ out,
                           int K, int N, int n_off) {
    __shared__ float tile[32][33];
    int n0 = blockIdx.x * 32, k0 = blockIdx.y * 32;
    int tx = threadIdx.x, ty = threadIdx.y;   // 32 x 8
#pragma unroll
    for (int r = 0; r < 4; r++)
        tile[ty + r * 8][tx] = W[(size_t)(k0 + ty + r * 8) * N + n0 + tx];
    __syncthreads();
#pragma unroll
    for (int r = 0; r < 4; r++) {
        int n = ty + r * 8;
        out[(size_t)(n_off + n0 + n) * K + k0 + tx] = __float2half(tile[tx][n]);
    }
}

// ================= RMSNorm (optional fused residual) =================
__global__ void rmsnorm_kernel(const float* __restrict__ in, const float* __restrict__ w,
                               const float* __restrict__ resid, float* __restrict__ out) {
    int row = blockIdx.x;
    const float* x = in + (size_t)row * HDIM;
    float ss = 0.f;
    for (int c = threadIdx.x; c < HDIM; c += 256) { float v = x[c]; ss += v * v; }
    __shared__ float red[256];
    red[threadIdx.x] = ss;
    __syncthreads();
    for (int s = 128; s > 0; s >>= 1) {
        if (threadIdx.x < s) red[threadIdx.x] += red[threadIdx.x + s];
        __syncthreads();
    }
    float scale = rsqrtf(red[0] / (float)HDIM + 1e-6f);
    for (int c = threadIdx.x; c < HDIM; c += 256) {
        float v = x[c] * scale * w[c];
        if (resid) v += resid[(size_t)row * HDIM + c];
        out[(size_t)row * HDIM + c] = v;
    }
}

// ================= RoPE in-place on qkv [2048, 8192] (q heads + k heads) =================
__global__ void rope_kernel(float* __restrict__ x) {
    int idx = blockIdx.x * 256 + threadIdx.x;   // over 2048*24*128
    int d = idx & 127;
    int hh = (idx >> 7) % 24;
    int s = idx / (128 * 24);
    float invf = (float)exp(-((double)(2 * d) / (double)HD) * log(10000.0));
    float ang = (float)s * invf;
    float c = (float)cos((double)ang);
    float si = (float)sin((double)ang);
    int col = (hh < 16) ? hh * 256 : 4096 + (hh - 16) * 256;
    size_t base = (size_t)s * QKVD + col;
    float x1 = x[base + d], x2 = x[base + d + 128];
    x[base + d]       = x1 * c - x2 * si;
    x[base + d + 128] = x2 * c + x1 * si;
}

// ================= flash attention w/ softcap (p = exp(s-50)), causal =================
#define BQ 64
#define QS_STR 68
#define VS_STR 260

__global__ void attn_kernel(const float* __restrict__ qkv, float* __restrict__ o) {
    extern __shared__ float sm[];
    float* Qs = sm;
    float* Ks = Qs + 256 * QS_STR;
    float* Vs = Ks + 256 * QS_STR;
    float* Ss = Vs + 64 * VS_STR;

    int qb = blockIdx.x;
    int head = blockIdx.y;
    int kvh = head >> 1;
    int t = threadIdx.x;

    for (int idx = t; idx < 64 * 64; idx += 256) {
        int i = idx >> 6, c = (idx & 63) * 4;
        float4 val = *(const float4*)&qkv[(size_t)(qb * BQ + i) * QKVD + head * HD + c];
        Qs[(c + 0) * QS_STR + i] = val.x;
        Qs[(c + 1) * QS_STR + i] = val.y;
        Qs[(c + 2) * QS_STR + i] = val.z;
        Qs[(c + 3) * QS_STR + i] = val.w;
    }

    float acc[64];
#pragma unroll
    for (int c = 0; c < 64; c++) acc[c] = 0.f;
    float lsum = 0.f;
    int oi = t & 63;
    int od = (t >> 6) * 64;
    int ti = (t >> 4) * 4;
    int tj = (t & 15) * 4;

    for (int kb = 0; kb <= qb; kb++) {
        __syncthreads();
        for (int idx = t; idx < 64 * 64; idx += 256) {
            int j = idx >> 6, c = (idx & 63) * 4;
            size_t gk = (size_t)(kb * BQ + j) * QKVD + 4096 + kvh * HD + c;
            size_t gv = (size_t)(kb * BQ + j) * QKVD + 6144 + kvh * HD + c;
            float4 kv = *(const float4*)&qkv[gk];
            Ks[(c + 0) * QS_STR + j] = kv.x;
            Ks[(c + 1) * QS_STR + j] = kv.y;
            Ks[(c + 2) * QS_STR + j] = kv.z;
            Ks[(c + 3) * QS_STR + j] = kv.w;
            *(float4*)&Vs[j * VS_STR + c] = *(const float4*)&qkv[gv];
        }
        __syncthreads();

        float s4[4][4];
#pragma unroll
        for (int i = 0; i < 4; i++)
#pragma unroll
            for (int j = 0; j < 4; j++) s4[i][j] = 0.f;
#pragma unroll 4
        for (int d = 0; d < 256; d++) {
            float4 a = *(const float4*)&Qs[d * QS_STR + ti];
            float4 b = *(const float4*)&Ks[d * QS_STR + tj];
            float av[4] = {a.x, a.y, a.z, a.w};
            float bv[4] = {b.x, b.y, b.z, b.w};
#pragma unroll
            for (int i = 0; i < 4; i++)
#pragma unroll
                for (int j = 0; j < 4; j++) s4[i][j] += av[i] * bv[j];
        }
#pragma unroll
        for (int i = 0; i < 4; i++) {
            int ig = qb * BQ + ti + i;
#pragma unroll
            for (int j = 0; j < 4; j++) {
                int jg = kb * BQ + tj + j;
                float sc = s4[i][j] * 0.0625f;
                sc = tanhf(sc * 0.02f) * 50.f;
                float p = (jg <= ig) ? __expf(sc - 50.f) : 0.f;
                Ss[(ti + i) * QS_STR + tj + j] = p;
            }
        }
        __syncthreads();

        const float* srow = &Ss[oi * QS_STR];
        for (int j = 0; j < 64; j++) {
            float p = srow[j];
            lsum += p;
            const float4* vrow = (const float4*)&Vs[j * VS_STR + od];
#pragma unroll
            for (int c = 0; c < 16; c++) {
                float4 vv = vrow[c];
                acc[c * 4 + 0] += p * vv.x;
                acc[c * 4 + 1] += p * vv.y;
                acc[c * 4 + 2] += p * vv.z;
                acc[c * 4 + 3] += p * vv.w;
            }
        }
    }

    float inv = 1.f / lsum;
    float* orow = &o[(size_t)(qb * BQ + oi) * QD + head * HD + od];
#pragma unroll
    for (int c = 0; c < 16; c++) {
        *(float4*)&orow[c * 4] = make_float4(acc[c*4+0]*inv, acc[c*4+1]*inv,
                                             acc[c*4+2]*inv, acc[c*4+3]*inv);
    }
}

// ===== SwiGLU fused with fp16-split convert: act[m] = split(gelu_tanh(g)*u) =====
__global__ void swiglu_conv_kernel(const float* __restrict__ gu, __half* __restrict__ dst) {
    int idx = blockIdx.x * 256 + threadIdx.x;    // over 2048*14336/2
    int m = idx / (IDIM / 2), c = (idx - m * (IDIM / 2)) * 2;
    const float* row = gu + (size_t)m * 2 * IDIM;
    float2 g = *(const float2*)(row + c);
    float2 u = *(const float2*)(row + IDIM + c);
    float t0 = tanhf(0.7978845608028654f * (g.x + 0.044715f * g.x * g.x * g.x));
    float t1 = tanhf(0.7978845608028654f * (g.y + 0.044715f * g.y * g.y * g.y));
    float v0 = 0.5f * g.x * (1.f + t0) * u.x;
    float v1 = 0.5f * g.y * (1.f + t1) * u.y;
    __half h0 = __float2half(v0), h1 = __float2half(v1);
    __half l0 = __float2half(v0 - __half2float(h0));
    __half l1 = __float2half(v1 - __half2float(h1));
    size_t base = (size_t)m * 2 * IDIM + c;
    *(__half2*)(dst + base)        = __halves2half2(h0, h1);
    *(__half2*)(dst + base + IDIM) = __halves2half2(l0, l1);
}

extern "C" void kernel_launch(void* const* d_in, const int* in_sizes, int n_in,
                              void* d_out, int out_size) {
    const float* hidden      = (const float*)d_in[0];
    const float* w_in        = (const float*)d_in[3];
    const float* w_post_attn = (const float*)d_in[4];
    const float* w_pre_ff    = (const float*)d_in[5];
    const float* w_post_ff   = (const float*)d_in[6];
    const float* wq          = (const float*)d_in[7];
    const float* wk          = (const float*)d_in[8];
    const float* wv          = (const float*)d_in[9];
    const float* wo          = (const float*)d_in[10];
    const float* w_gate      = (const float*)d_in[11];
    const float* w_up        = (const float*)d_in[12];
    const float* w_down      = (const float*)d_in[13];
    float* out = (float*)d_out;

    float *h, *qkv, *attn, *proj, *x1, *gu, *down;
    __half *act, *wt;
    cudaGetSymbolAddress((void**)&h, g_h);
    cudaGetSymbolAddress((void**)&qkv, g_qkv);
    cudaGetSymbolAddress((void**)&attn, g_attn);
    cudaGetSymbolAddress((void**)&proj, g_proj);
    cudaGetSymbolAddress((void**)&x1, g_x1);
    cudaGetSymbolAddress((void**)&gu, g_gu);
    cudaGetSymbolAddress((void**)&down, g_down);
    cudaGetSymbolAddress((void**)&act, g_act);
    cudaGetSymbolAddress((void**)&wt, g_wt);

    cudaFuncSetAttribute(gemm_mma, cudaFuncAttributeMaxDynamicSharedMemorySize, SMEM_MMA);
    const int smem_attn = (256 * QS_STR * 2 + 64 * VS_STR + 64 * QS_STR) * 4;
    cudaFuncSetAttribute(attn_kernel, cudaFuncAttributeMaxDynamicSharedMemorySize, smem_attn);

    dim3 wtb(32, 8);

    // ---- attention block ----
    rmsnorm_kernel<<<SQ, 256>>>(hidden, w_in, nullptr, h);
    convert_act<<<SQ * (HDIM/4) / 256, 256>>>(h, act, HDIM);
    convert_wt<<<dim3(QD/32,   HDIM/32), wtb>>>(wq, wt, HDIM, QD,   0);
    convert_wt<<<dim3(2048/32, HDIM/32), wtb>>>(wk, wt, HDIM, 2048, 4096);
    convert_wt<<<dim3(2048/32, HDIM/32), wtb>>>(wv, wt, HDIM, 2048, 6144);
    gemm_mma<<<dim3(SQ/BM, QKVD/BN), 256, SMEM_MMA>>>(act, wt, qkv, QKVD, HDIM);
    rope_kernel<<<SQ * 24 * 128 / 256, 256>>>(qkv);
    attn_kernel<<<dim3(SQ/BQ, NH), 256, smem_attn>>>(qkv, attn);
    convert_act<<<SQ * (QD/4) / 256, 256>>>(attn, act, QD);
    convert_wt<<<dim3(HDIM/32, QD/32), wtb>>>(wo, wt, QD, HDIM, 0);
    gemm_mma<<<dim3(SQ/BM, HDIM/BN), 256, SMEM_MMA>>>(act, wt, proj, HDIM, QD);
    rmsnorm_kernel<<<SQ, 256>>>(proj, w_post_attn, hidden, x1);

    // ---- MLP block ----
    rmsnorm_kernel<<<SQ, 256>>>(x1, w_pre_ff, nullptr, h);
    convert_act<<<SQ * (HDIM/4) / 256, 256>>>(h, act, HDIM);
    convert_wt<<<dim3(IDIM/32, HDIM/32), wtb>>>(w_gate, wt, HDIM, IDIM, 0);
    convert_wt<<<dim3(IDIM/32, HDIM/32), wtb>>>(w_up,   wt, HDIM, IDIM, IDIM);
    gemm_mma<<<dim3(SQ/BM, 2*IDIM/BN), 256, SMEM_MMA>>>(act, wt, gu, 2*IDIM, HDIM);
    swiglu_conv_kernel<<<SQ * (IDIM/2) / 256, 256>>>(gu, act);
    convert_wt<<<dim3(HDIM/32, IDIM/32), wtb>>>(w_down, wt, IDIM, HDIM, 0);
    gemm_mma<<<dim3(SQ/BM, HDIM/BN), 256, SMEM_MMA>>>(act, wt, down, HDIM, IDIM);
    rmsnorm_kernel<<<SQ, 256>>>(down, w_post_ff, x1, out);
}

// round 5
// speedup vs baseline: 1.1386x; 1.1386x over previous
#include <cuda_runtime.h>
#include <cuda_fp16.h>
#include <math.h>
#include <stdint.h>

#define SQ 2048
#define HDIM 3584
#define NH 16
#define NKV 8
#define HD 256
#define QKVD 8192           // 4096 q + 2048 k + 2048 v
#define QD 4096
#define IDIM 14336

// ---------------- scratch (allocation-free: __device__ globals) ----------------
static __device__ float g_h[SQ*HDIM];
static __device__ float g_qkv[SQ*QKVD];
static __device__ float g_attn[SQ*QD];
static __device__ float g_proj[SQ*HDIM];
static __device__ float g_x1[SQ*HDIM];
static __device__ float g_gu[(size_t)SQ*2*IDIM];
static __device__ float g_down[SQ*HDIM];
static __device__ __half g_act[(size_t)SQ*2*IDIM];        // A' = [Ah|Al], up to [2048, 28672]
static __device__ __half g_wt[(size_t)(2*IDIM)*HDIM];     // B' K-major, up to [28672, 3584]

// ---------------- PTX helpers (arch-agnostic only: sm_80-level) ----------------
__device__ __forceinline__ uint32_t smem_u32(const void* p) {
    uint32_t a;
    asm("{ .reg .u64 t; cvta.to.shared.u64 t, %1; cvt.u32.u64 %0, t; }" : "=r"(a) : "l"(p));
    return a;
}
__device__ __forceinline__ void ldx4(uint32_t& r0, uint32_t& r1, uint32_t& r2, uint32_t& r3, uint32_t a) {
    asm volatile("ldmatrix.sync.aligned.m8n8.x4.shared.b16 {%0,%1,%2,%3}, [%4];"
                 : "=r"(r0), "=r"(r1), "=r"(r2), "=r"(r3) : "r"(a));
}
__device__ __forceinline__ void hmma(float* c, uint32_t a0, uint32_t a1, uint32_t a2, uint32_t a3,
                                     uint32_t b0, uint32_t b1) {
    asm volatile("mma.sync.aligned.m16n8k16.row.col.f32.f16.f16.f32 "
                 "{%0,%1,%2,%3},{%4,%5,%6,%7},{%8,%9},{%0,%1,%2,%3};"
                 : "+f"(c[0]), "+f"(c[1]), "+f"(c[2]), "+f"(c[3])
                 : "r"(a0), "r"(a1), "r"(a2), "r"(a3), "r"(b0), "r"(b1));
}
#define CP_ASYNC16(dst, src) \
    asm volatile("cp.async.cg.shared.global [%0], [%1], 16;" :: "r"(dst), "l"(src))
#define CP_COMMIT() asm volatile("cp.async.commit_group;" ::: "memory")
#define CP_WAIT(n)  asm volatile("cp.async.wait_group %0;" :: "n"(n) : "memory")

// ============ HMMA fp16 split GEMM: C[M,N] = (Ah+Al)[M,2K] @ B'[N,K]^T ============
// A' row-major [M, 2K] fp16 ([Ah | Al]); B' K-major [N, K] fp16. fp32 accumulate.
// CTA tile 128x128x32, 8 warps (warp tile 64x32), 4-stage cp.async, 2 CTA/SM,
// single __syncthreads per mainloop iteration (cutlass sm80 ordering).
#define BM 128
#define BN 128
#define BK 32
#define STG 4
#define ROWH 40                               // halves per smem row (32 + 8 pad)
#define STAGE_A (BM*ROWH*2)                   // 10240
#define STAGE_B (STAGE_A + BN*ROWH*2)         // 20480 per stage
#define SMEM_MMA (STG*STAGE_B)                // 81920

__global__ void __launch_bounds__(256, 2)
gemm_mma(const __half* __restrict__ A, const __half* __restrict__ B,
         float* __restrict__ C, int N, int K) {
    extern __shared__ char smem[];
    uint32_t sbase = smem_u32(smem);
    const int K2 = 2 * K;
    int tid = threadIdx.x, lane = tid & 31, wid = tid >> 5;
    int m0 = blockIdx.x * BM, n0 = blockIdx.y * BN;
    int wm = (wid & 1) * 64, wn = (wid >> 1) * 32;
    int ntiles = K2 / BK;

    // cp.async mapping: thread -> (row = tid/4, 16B seg = tid%4), rows lr and lr+64
    int lr = tid >> 2;
    int lc = (tid & 3) * 8;
    const __half* gA0 = A + (size_t)(m0 + lr) * K2 + lc;
    const __half* gB0 = B + (size_t)(n0 + lr) * K + lc;
    uint32_t sOff = (uint32_t)(lr * ROWH + lc) * 2;

    // ldmatrix fragment addressing (no .trans; identical pattern for A and B)
    uint32_t foff = (uint32_t)(((lane & 15) * ROWH) + ((lane >> 4) * 8)) * 2;

    float acc[4][4][4];
#pragma unroll
    for (int a = 0; a < 4; a++)
#pragma unroll
        for (int b = 0; b < 4; b++)
#pragma unroll
            for (int c = 0; c < 4; c++) acc[a][b][c] = 0.f;

    auto LOAD = [&](int kt, int s) {
        int ak = kt * BK;
        int bk = (ak < K) ? ak : ak - K;      // B wraps: [Ah|Al] both hit same B
        uint32_t sA = sbase + s * STAGE_B;
        uint32_t sB = sA + STAGE_A;
#pragma unroll
        for (int h = 0; h < 2; h++) {
            CP_ASYNC16(sA + sOff + h * 64 * ROWH * 2, gA0 + (size_t)h * 64 * K2 + ak);
            CP_ASYNC16(sB + sOff + h * 64 * ROWH * 2, gB0 + (size_t)h * 64 * K + bk);
        }
    };

#pragma unroll
    for (int s = 0; s < STG - 1; s++) {
        if (s < ntiles) LOAD(s, s);
        CP_COMMIT();
    }

    for (int i = 0; i < ntiles; i++) {
        CP_WAIT(STG - 2);          // stage i resident
        __syncthreads();           // all warps done with stage written next

        int pf = i + STG - 1;
        if (pf < ntiles) LOAD(pf, pf % STG);   // writes stage (i-1)%STG — freed
        CP_COMMIT();

        int s = i % STG;
        uint32_t aB = sbase + s * STAGE_B;
        uint32_t bB = aB + STAGE_A;
        uint32_t aAddr = aB + (uint32_t)wm * ROWH * 2 + foff;
        uint32_t bAddr = bB + (uint32_t)wn * ROWH * 2 + foff;
#pragma unroll
        for (int ks = 0; ks < 2; ks++) {
            uint32_t af[4][4];
#pragma unroll
            for (int fm = 0; fm < 4; fm++)
                ldx4(af[fm][0], af[fm][1], af[fm][2], af[fm][3],
                     aAddr + (uint32_t)fm * 16 * ROWH * 2 + ks * 32);
            uint32_t t0, t1, t2, t3, t4, t5, t6, t7;
            ldx4(t0, t1, t2, t3, bAddr + ks * 32);
            ldx4(t4, t5, t6, t7, bAddr + 16 * ROWH * 2 + ks * 32);
            uint32_t b0[4] = {t0, t1, t4, t5};
            uint32_t b1[4] = {t2, t3, t6, t7};
#pragma unroll
            for (int fm = 0; fm < 4; fm++)
#pragma unroll
                for (int fn = 0; fn < 4; fn++)
                    hmma(acc[fm][fn], af[fm][0], af[fm][1], af[fm][2], af[fm][3],
                         b0[fn], b1[fn]);
        }
    }

#pragma unroll
    for (int fm = 0; fm < 4; fm++) {
        int r = m0 + wm + fm * 16 + (lane >> 2);
#pragma unroll
        for (int fn = 0; fn < 4; fn++) {
            int c = n0 + wn + fn * 8 + (lane & 3) * 2;
            *(float2*)&C[(size_t)r * N + c]       = make_float2(acc[fm][fn][0], acc[fm][fn][1]);
            *(float2*)&C[(size_t)(r + 8) * N + c] = make_float2(acc[fm][fn][2], acc[fm][fn][3]);
        }
    }
}

// ================= fp32 -> fp16 split conversions =================
// A' = [Ah | Al], row length 2K
__global__ void convert_act(const float* __restrict__ src, __half* __restrict__ dst, int K) {
    int K4 = K >> 2;
    int idx = blockIdx.x * 256 + threadIdx.x;
    int m = idx / K4, k4 = (idx - m * K4) * 4;
    float4 a = *(const float4*)(src + (size_t)m * K + k4);
    __half h0 = __float2half(a.x), h1 = __float2half(a.y);
    __half h2 = __float2half(a.z), h3 = __float2half(a.w);
    __half l0 = __float2half(a.x - __half2float(h0));
    __half l1 = __float2half(a.y - __half2float(h1));
    __half l2 = __float2half(a.z - __half2float(h2));
    __half l3 = __float2half(a.w - __half2float(h3));
    size_t base = (size_t)m * 2 * K + k4;
    *(__half2*)(dst + base)         = __halves2half2(h0, h1);
    *(__half2*)(dst + base + 2)     = __halves2half2(h2, h3);
    *(__half2*)(dst + base + K)     = __halves2half2(l0, l1);
    *(__half2*)(dst + base + K + 2) = __halves2half2(l2, l3);
}

// W[K,N] fp32 -> out[n_off+n][k] fp16 K-major (transpose)
__global__ void convert_wt(const float* __restrict__ W, __half* __restrict__ out,
                           int K, int N, int n_off) {
    __shared__ float tile[32][33];
    int n0 = blockIdx.x * 32, k0 = blockIdx.y * 32;
    int tx = threadIdx.x, ty = threadIdx.y;   // 32 x 8
#pragma unroll
    for (int r = 0; r < 4; r++)
        tile[ty + r * 8][tx] = W[(size_t)(k0 + ty + r * 8) * N + n0 + tx];
    __syncthreads();
#pragma unroll
    for (int r = 0; r < 4; r++) {
        int n = ty + r * 8;
        out[(size_t)(n_off + n0 + n) * K + k0 + tx] = __float2half(tile[tx][n]);
    }
}

// ================= RMSNorm (optional fused residual) =================
__global__ void rmsnorm_kernel(const float* __restrict__ in, const float* __restrict__ w,
                               const float* __restrict__ resid, float* __restrict__ out) {
    int row = blockIdx.x;
    const float* x = in + (size_t)row * HDIM;
    float ss = 0.f;
    for (int c = threadIdx.x; c < HDIM; c += 256) { float v = x[c]; ss += v * v; }
    __shared__ float red[256];
    red[threadIdx.x] = ss;
    __syncthreads();
    for (int s = 128; s > 0; s >>= 1) {
        if (threadIdx.x < s) red[threadIdx.x] += red[threadIdx.x + s];
        __syncthreads();
    }
    float scale = rsqrtf(red[0] / (float)HDIM + 1e-6f);
    for (int c = threadIdx.x; c < HDIM; c += 256) {
        float v = x[c] * scale * w[c];
        if (resid) v += resid[(size_t)row * HDIM + c];
        out[(size_t)row * HDIM + c] = v;
    }
}

// ================= RoPE in-place on qkv [2048, 8192] (q heads + k heads) =================
__global__ void rope_kernel(float* __restrict__ x) {
    int idx = blockIdx.x * 256 + threadIdx.x;   // over 2048*24*128
    int d = idx & 127;
    int hh = (idx >> 7) % 24;
    int s = idx / (128 * 24);
    float invf = (float)exp(-((double)(2 * d) / (double)HD) * log(10000.0));
    float ang = (float)s * invf;
    float c = (float)cos((double)ang);
    float si = (float)sin((double)ang);
    int col = (hh < 16) ? hh * 256 : 4096 + (hh - 16) * 256;
    size_t base = (size_t)s * QKVD + col;
    float x1 = x[base + d], x2 = x[base + d + 128];
    x[base + d]       = x1 * c - x2 * si;
    x[base + d + 128] = x2 * c + x1 * si;
}

// ================= flash attention w/ softcap (p = exp(s-50)), causal =================
#define BQ 64
#define QS_STR 68
#define VS_STR 260

__global__ void attn_kernel(const float* __restrict__ qkv, float* __restrict__ o) {
    extern __shared__ float sm[];
    float* Qs = sm;
    float* Ks = Qs + 256 * QS_STR;
    float* Vs = Ks + 256 * QS_STR;
    float* Ss = Vs + 64 * VS_STR;

    int qb = blockIdx.x;
    int head = blockIdx.y;
    int kvh = head >> 1;
    int t = threadIdx.x;

    for (int idx = t; idx < 64 * 64; idx += 256) {
        int i = idx >> 6, c = (idx & 63) * 4;
        float4 val = *(const float4*)&qkv[(size_t)(qb * BQ + i) * QKVD + head * HD + c];
        Qs[(c + 0) * QS_STR + i] = val.x;
        Qs[(c + 1) * QS_STR + i] = val.y;
        Qs[(c + 2) * QS_STR + i] = val.z;
        Qs[(c + 3) * QS_STR + i] = val.w;
    }

    float acc[64];
#pragma unroll
    for (int c = 0; c < 64; c++) acc[c] = 0.f;
    float lsum = 0.f;
    int oi = t & 63;
    int od = (t >> 6) * 64;
    int ti = (t >> 4) * 4;
    int tj = (t & 15) * 4;

    for (int kb = 0; kb <= qb; kb++) {
        __syncthreads();
        for (int idx = t; idx < 64 * 64; idx += 256) {
            int j = idx >> 6, c = (idx & 63) * 4;
            size_t gk = (size_t)(kb * BQ + j) * QKVD + 4096 + kvh * HD + c;
            size_t gv = (size_t)(kb * BQ + j) * QKVD + 6144 + kvh * HD + c;
            float4 kv = *(const float4*)&qkv[gk];
            Ks[(c + 0) * QS_STR + j] = kv.x;
            Ks[(c + 1) * QS_STR + j] = kv.y;
            Ks[(c + 2) * QS_STR + j] = kv.z;
            Ks[(c + 3) * QS_STR + j] = kv.w;
            *(float4*)&Vs[j * VS_STR + c] = *(const float4*)&qkv[gv];
        }
        __syncthreads();

        float s4[4][4];
#pragma unroll
        for (int i = 0; i < 4; i++)
#pragma unroll
            for (int j = 0; j < 4; j++) s4[i][j] = 0.f;
#pragma unroll 4
        for (int d = 0; d < 256; d++) {
            float4 a = *(const float4*)&Qs[d * QS_STR + ti];
            float4 b = *(const float4*)&Ks[d * QS_STR + tj];
            float av[4] = {a.x, a.y, a.z, a.w};
            float bv[4] = {b.x, b.y, b.z, b.w};
#pragma unroll
            for (int i = 0; i < 4; i++)
#pragma unroll
                for (int j = 0; j < 4; j++) s4[i][j] += av[i] * bv[j];
        }
#pragma unroll
        for (int i = 0; i < 4; i++) {
            int ig = qb * BQ + ti + i;
#pragma unroll
            for (int j = 0; j < 4; j++) {
                int jg = kb * BQ + tj + j;
                float sc = s4[i][j] * 0.0625f;
                sc = tanhf(sc * 0.02f) * 50.f;
                float p = (jg <= ig) ? __expf(sc - 50.f) : 0.f;
                Ss[(ti + i) * QS_STR + tj + j] = p;
            }
        }
        __syncthreads();

        const float* srow = &Ss[oi * QS_STR];
        for (int j = 0; j < 64; j++) {
            float p = srow[j];
            lsum += p;
            const float4* vrow = (const float4*)&Vs[j * VS_STR + od];
#pragma unroll
            for (int c = 0; c < 16; c++) {
                float4 vv = vrow[c];
                acc[c * 4 + 0] += p * vv.x;
                acc[c * 4 + 1] += p * vv.y;
                acc[c * 4 + 2] += p * vv.z;
                acc[c * 4 + 3] += p * vv.w;
            }
        }
    }

    float inv = 1.f / lsum;
    float* orow = &o[(size_t)(qb * BQ + oi) * QD + head * HD + od];
#pragma unroll
    for (int c = 0; c < 16; c++) {
        *(float4*)&orow[c * 4] = make_float4(acc[c*4+0]*inv, acc[c*4+1]*inv,
                                             acc[c*4+2]*inv, acc[c*4+3]*inv);
    }
}

// ===== SwiGLU fused with fp16-split convert: act[m] = split(gelu_tanh(g)*u) =====
__global__ void swiglu_conv_kernel(const float* __restrict__ gu, __half* __restrict__ dst) {
    int idx = blockIdx.x * 256 + threadIdx.x;    // over 2048*14336/2
    int m = idx / (IDIM / 2), c = (idx - m * (IDIM / 2)) * 2;
    const float* row = gu + (size_t)m * 2 * IDIM;
    float2 g = *(const float2*)(row + c);
    float2 u = *(const float2*)(row + IDIM + c);
    float t0 = tanhf(0.7978845608028654f * (g.x + 0.044715f * g.x * g.x * g.x));
    float t1 = tanhf(0.7978845608028654f * (g.y + 0.044715f * g.y * g.y * g.y));
    float v0 = 0.5f * g.x * (1.f + t0) * u.x;
    float v1 = 0.5f * g.y * (1.f + t1) * u.y;
    __half h0 = __float2half(v0), h1 = __float2half(v1);
    __half l0 = __float2half(v0 - __half2float(h0));
    __half l1 = __float2half(v1 - __half2float(h1));
    size_t base = (size_t)m * 2 * IDIM + c;
    *(__half2*)(dst + base)        = __halves2half2(h0, h1);
    *(__half2*)(dst + base + IDIM) = __halves2half2(l0, l1);
}

extern "C" void kernel_launch(void* const* d_in, const int* in_sizes, int n_in,
                              void* d_out, int out_size) {
    const float* hidden      = (const float*)d_in[0];
    const float* w_in        = (const float*)d_in[3];
    const float* w_post_attn = (const float*)d_in[4];
    const float* w_pre_ff    = (const float*)d_in[5];
    const float* w_post_ff   = (const float*)d_in[6];
    const float* wq          = (const float*)d_in[7];
    const float* wk          = (const float*)d_in[8];
    const float* wv          = (const float*)d_in[9];
    const float* wo          = (const float*)d_in[10];
    const float* w_gate      = (const float*)d_in[11];
    const float* w_up        = (const float*)d_in[12];
    const float* w_down      = (const float*)d_in[13];
    float* out = (float*)d_out;

    float *h, *qkv, *attn, *proj, *x1, *gu, *down;
    __half *act, *wt;
    cudaGetSymbolAddress((void**)&h, g_h);
    cudaGetSymbolAddress((void**)&qkv, g_qkv);
    cudaGetSymbolAddress((void**)&attn, g_attn);
    cudaGetSymbolAddress((void**)&proj, g_proj);
    cudaGetSymbolAddress((void**)&x1, g_x1);
    cudaGetSymbolAddress((void**)&gu, g_gu);
    cudaGetSymbolAddress((void**)&down, g_down);
    cudaGetSymbolAddress((void**)&act, g_act);
    cudaGetSymbolAddress((void**)&wt, g_wt);

    cudaFuncSetAttribute(gemm_mma, cudaFuncAttributeMaxDynamicSharedMemorySize, SMEM_MMA);
    const int smem_attn = (256 * QS_STR * 2 + 64 * VS_STR + 64 * QS_STR) * 4;
    cudaFuncSetAttribute(attn_kernel, cudaFuncAttributeMaxDynamicSharedMemorySize, smem_attn);

    dim3 wtb(32, 8);

    // ---- attention block ----
    rmsnorm_kernel<<<SQ, 256>>>(hidden, w_in, nullptr, h);
    convert_act<<<SQ * (HDIM/4) / 256, 256>>>(h, act, HDIM);
    convert_wt<<<dim3(QD/32,   HDIM/32), wtb>>>(wq, wt, HDIM, QD,   0);
    convert_wt<<<dim3(2048/32, HDIM/32), wtb>>>(wk, wt, HDIM, 2048, 4096);
    convert_wt<<<dim3(2048/32, HDIM/32), wtb>>>(wv, wt, HDIM, 2048, 6144);
    gemm_mma<<<dim3(SQ/BM, QKVD/BN), 256, SMEM_MMA>>>(act, wt, qkv, QKVD, HDIM);
    rope_kernel<<<SQ * 24 * 128 / 256, 256>>>(qkv);
    attn_kernel<<<dim3(SQ/BQ, NH), 256, smem_attn>>>(qkv, attn);
    convert_act<<<SQ * (QD/4) / 256, 256>>>(attn, act, QD);
    convert_wt<<<dim3(HDIM/32, QD/32), wtb>>>(wo, wt, QD, HDIM, 0);
    gemm_mma<<<dim3(SQ/BM, HDIM/BN), 256, SMEM_MMA>>>(act, wt, proj, HDIM, QD);
    rmsnorm_kernel<<<SQ, 256>>>(proj, w_post_attn, hidden, x1);

    // ---- MLP block ----
    rmsnorm_kernel<<<SQ, 256>>>(x1, w_pre_ff, nullptr, h);
    convert_act<<<SQ * (HDIM/4) / 256, 256>>>(h, act, HDIM);
    convert_wt<<<dim3(IDIM/32, HDIM/32), wtb>>>(w_gate, wt, HDIM, IDIM, 0);
    convert_wt<<<dim3(IDIM/32, HDIM/32), wtb>>>(w_up,   wt, HDIM, IDIM, IDIM);
    gemm_mma<<<dim3(SQ/BM, 2*IDIM/BN), 256, SMEM_MMA>>>(act, wt, gu, 2*IDIM, HDIM);
    swiglu_conv_kernel<<<SQ * (IDIM/2) / 256, 256>>>(gu, act);
    convert_wt<<<dim3(HDIM/32, IDIM/32), wtb>>>(w_down, wt, IDIM, HDIM, 0);
    gemm_mma<<<dim3(SQ/BM, HDIM/BN), 256, SMEM_MMA>>>(act, wt, down, HDIM, IDIM);
    rmsnorm_kernel<<<SQ, 256>>>(down, w_post_ff, x1, out);
}

// round 6
// speedup vs baseline: 1.1912x; 1.0462x over previous
#include <cuda_runtime.h>
#include <cuda_fp16.h>
#include <math.h>
#include <stdint.h>

#define SQ 2048
#define HDIM 3584
#define NH 16
#define NKV 8
#define HD 256
#define QKVD 8192           // 4096 q + 2048 k + 2048 v
#define QD 4096
#define IDIM 14336

// ---------------- scratch (allocation-free: __device__ globals) ----------------
static __device__ float g_h[SQ*HDIM];
static __device__ float g_qkv[SQ*QKVD];
static __device__ float g_attn[SQ*QD];
static __device__ float g_proj[SQ*HDIM];
static __device__ float g_x1[SQ*HDIM];
static __device__ float g_gu[(size_t)SQ*2*IDIM];
static __device__ float g_down[SQ*HDIM];
static __device__ __half g_act[(size_t)SQ*2*IDIM];        // A' = [Ah|Al], up to [2048, 28672]
static __device__ __half g_wt[(size_t)(2*IDIM)*HDIM];     // B' K-major, up to [28672, 3584]

// ---------------- PTX helpers (arch-agnostic only: sm_80-level) ----------------
__device__ __forceinline__ uint32_t smem_u32(const void* p) {
    uint32_t a;
    asm("{ .reg .u64 t; cvta.to.shared.u64 t, %1; cvt.u32.u64 %0, t; }" : "=r"(a) : "l"(p));
    return a;
}
__device__ __forceinline__ void ldx4(uint32_t& r0, uint32_t& r1, uint32_t& r2, uint32_t& r3, uint32_t a) {
    asm volatile("ldmatrix.sync.aligned.m8n8.x4.shared.b16 {%0,%1,%2,%3}, [%4];"
                 : "=r"(r0), "=r"(r1), "=r"(r2), "=r"(r3) : "r"(a));
}
__device__ __forceinline__ void hmma(float* c, uint32_t a0, uint32_t a1, uint32_t a2, uint32_t a3,
                                     uint32_t b0, uint32_t b1) {
    asm volatile("mma.sync.aligned.m16n8k16.row.col.f32.f16.f16.f32 "
                 "{%0,%1,%2,%3},{%4,%5,%6,%7},{%8,%9},{%0,%1,%2,%3};"
                 : "+f"(c[0]), "+f"(c[1]), "+f"(c[2]), "+f"(c[3])
                 : "r"(a0), "r"(a1), "r"(a2), "r"(a3), "r"(b0), "r"(b1));
}
#define CP_ASYNC16(dst, src) \
    asm volatile("cp.async.cg.shared.global [%0], [%1], 16;" :: "r"(dst), "l"(src))
#define CP_COMMIT() asm volatile("cp.async.commit_group;" ::: "memory")
#define CP_WAIT(n)  asm volatile("cp.async.wait_group %0;" :: "n"(n) : "memory")

// ============ HMMA fp16 split GEMM: C[M,N] = (Ah+Al)[M,2K] @ B'[N,K]^T ============
// A' row-major [M, 2K] fp16 ([Ah | Al]); B' K-major [N, K] fp16. fp32 accumulate.
// CTA tile 128x128x64, 8 warps (warp tile 64x32), 3-stage cp.async, 2 CTA/SM,
// single __syncthreads per mainloop iteration.
#define BM 128
#define BN 128
#define BK 64
#define STG 3
#define ROWH 72                               // halves per smem row (64 + 8 pad); 144B rows
#define STAGE_A (BM*ROWH*2)                   // 18432
#define STAGE_B (STAGE_A + BN*ROWH*2)         // 36864 per stage
#define SMEM_MMA (STG*STAGE_B)                // 110592

__global__ void __launch_bounds__(256, 2)
gemm_mma(const __half* __restrict__ A, const __half* __restrict__ B,
         float* __restrict__ C, int N, int K) {
    extern __shared__ char smem[];
    uint32_t sbase = smem_u32(smem);
    const int K2 = 2 * K;
    int tid = threadIdx.x, lane = tid & 31, wid = tid >> 5;
    int m0 = blockIdx.x * BM, n0 = blockIdx.y * BN;
    int wm = (wid & 1) * 64, wn = (wid >> 1) * 32;
    int ntiles = K2 / BK;                     // K multiple of 64 for all shapes here

    // cp.async mapping: thread -> (row = tid/8, 16B seg = tid%8); 4 row-blocks of 32
    int lr = tid >> 3;
    int lc = (tid & 7) * 8;
    const __half* gA0 = A + (size_t)(m0 + lr) * K2 + lc;
    const __half* gB0 = B + (size_t)(n0 + lr) * K + lc;
    uint32_t sOff = (uint32_t)(lr * ROWH + lc) * 2;

    // ldmatrix fragment addressing (no .trans; identical pattern for A and B)
    uint32_t foff = (uint32_t)(((lane & 15) * ROWH) + ((lane >> 4) * 8)) * 2;

    float acc[4][4][4];
#pragma unroll
    for (int a = 0; a < 4; a++)
#pragma unroll
        for (int b = 0; b < 4; b++)
#pragma unroll
            for (int c = 0; c < 4; c++) acc[a][b][c] = 0.f;

    auto LOAD = [&](int kt, int s) {
        int ak = kt * BK;
        int bk = (ak < K) ? ak : ak - K;      // B wraps: [Ah|Al] both hit same B
        uint32_t sA = sbase + s * STAGE_B;
        uint32_t sB = sA + STAGE_A;
#pragma unroll
        for (int h = 0; h < 4; h++) {
            CP_ASYNC16(sA + sOff + h * 32 * ROWH * 2, gA0 + (size_t)h * 32 * K2 + ak);
            CP_ASYNC16(sB + sOff + h * 32 * ROWH * 2, gB0 + (size_t)h * 32 * K + bk);
        }
    };

#pragma unroll
    for (int s = 0; s < STG - 1; s++) {
        LOAD(s, s);
        CP_COMMIT();
    }

    for (int i = 0; i < ntiles; i++) {
        CP_WAIT(STG - 2);          // stage i resident
        __syncthreads();           // all warps done with the stage written next

        int pf = i + STG - 1;
        if (pf < ntiles) LOAD(pf, pf % STG);   // writes stage (i-1)%STG — freed
        CP_COMMIT();

        int s = i % STG;
        uint32_t aB = sbase + s * STAGE_B;
        uint32_t bB = aB + STAGE_A;
        uint32_t aAddr = aB + (uint32_t)wm * ROWH * 2 + foff;
        uint32_t bAddr = bB + (uint32_t)wn * ROWH * 2 + foff;
#pragma unroll
        for (int ks = 0; ks < 4; ks++) {
            uint32_t af[4][4];
#pragma unroll
            for (int fm = 0; fm < 4; fm++)
                ldx4(af[fm][0], af[fm][1], af[fm][2], af[fm][3],
                     aAddr + (uint32_t)fm * 16 * ROWH * 2 + ks * 32);
            uint32_t t0, t1, t2, t3, t4, t5, t6, t7;
            ldx4(t0, t1, t2, t3, bAddr + ks * 32);
            ldx4(t4, t5, t6, t7, bAddr + 16 * ROWH * 2 + ks * 32);
            uint32_t b0[4] = {t0, t1, t4, t5};
            uint32_t b1[4] = {t2, t3, t6, t7};
#pragma unroll
            for (int fm = 0; fm < 4; fm++)
#pragma unroll
                for (int fn = 0; fn < 4; fn++)
                    hmma(acc[fm][fn], af[fm][0], af[fm][1], af[fm][2], af[fm][3],
                         b0[fn], b1[fn]);
        }
    }

#pragma unroll
    for (int fm = 0; fm < 4; fm++) {
        int r = m0 + wm + fm * 16 + (lane >> 2);
#pragma unroll
        for (int fn = 0; fn < 4; fn++) {
            int c = n0 + wn + fn * 8 + (lane & 3) * 2;
            *(float2*)&C[(size_t)r * N + c]       = make_float2(acc[fm][fn][0], acc[fm][fn][1]);
            *(float2*)&C[(size_t)(r + 8) * N + c] = make_float2(acc[fm][fn][2], acc[fm][fn][3]);
        }
    }
}

// ================= fp32 -> fp16 split conversions =================
// A' = [Ah | Al], row length 2K
__global__ void convert_act(const float* __restrict__ src, __half* __restrict__ dst, int K) {
    int K4 = K >> 2;
    int idx = blockIdx.x * 256 + threadIdx.x;
    int m = idx / K4, k4 = (idx - m * K4) * 4;
    float4 a = *(const float4*)(src + (size_t)m * K + k4);
    __half h0 = __float2half(a.x), h1 = __float2half(a.y);
    __half h2 = __float2half(a.z), h3 = __float2half(a.w);
    __half l0 = __float2half(a.x - __half2float(h0));
    __half l1 = __float2half(a.y - __half2float(h1));
    __half l2 = __float2half(a.z - __half2float(h2));
    __half l3 = __float2half(a.w - __half2float(h3));
    size_t base = (size_t)m * 2 * K + k4;
    *(__half2*)(dst + base)         = __halves2half2(h0, h1);
    *(__half2*)(dst + base + 2)     = __halves2half2(h2, h3);
    *(__half2*)(dst + base + K)     = __halves2half2(l0, l1);
    *(__half2*)(dst + base + K + 2) = __halves2half2(l2, l3);
}

// W[K,N] fp32 -> out[n_off+n][k] fp16 K-major (transpose)
__global__ void convert_wt(const float* __restrict__ W, __half* __restrict__ out,
                           int K, int N, int n_off) {
    __shared__ float tile[32][33];
    int n0 = blockIdx.x * 32, k0 = blockIdx.y * 32;
    int tx = threadIdx.x, ty = threadIdx.y;   // 32 x 8
#pragma unroll
    for (int r = 0; r < 4; r++)
        tile[ty + r * 8][tx] = W[(size_t)(k0 + ty + r * 8) * N + n0 + tx];
    __syncthreads();
#pragma unroll
    for (int r = 0; r < 4; r++) {
        int n = ty + r * 8;
        out[(size_t)(n_off + n0 + n) * K + k0 + tx] = __float2half(tile[tx][n]);
    }
}

// ================= RMSNorm (optional fused residual) =================
__global__ void rmsnorm_kernel(const float* __restrict__ in, const float* __restrict__ w,
                               const float* __restrict__ resid, float* __restrict__ out) {
    int row = blockIdx.x;
    const float* x = in + (size_t)row * HDIM;
    float ss = 0.f;
    for (int c = threadIdx.x; c < HDIM; c += 256) { float v = x[c]; ss += v * v; }
    __shared__ float red[256];
    red[threadIdx.x] = ss;
    __syncthreads();
    for (int s = 128; s > 0; s >>= 1) {
        if (threadIdx.x < s) red[threadIdx.x] += red[threadIdx.x + s];
        __syncthreads();
    }
    float scale = rsqrtf(red[0] / (float)HDIM + 1e-6f);
    for (int c = threadIdx.x; c < HDIM; c += 256) {
        float v = x[c] * scale * w[c];
        if (resid) v += resid[(size_t)row * HDIM + c];
        out[(size_t)row * HDIM + c] = v;
    }
}

// ================= RoPE in-place on qkv [2048, 8192] (q heads + k heads) =================
__global__ void rope_kernel(float* __restrict__ x) {
    int idx = blockIdx.x * 256 + threadIdx.x;   // over 2048*24*128
    int d = idx & 127;
    int hh = (idx >> 7) % 24;
    int s = idx / (128 * 24);
    float invf = (float)exp(-((double)(2 * d) / (double)HD) * log(10000.0));
    float ang = (float)s * invf;
    float c = (float)cos((double)ang);
    float si = (float)sin((double)ang);
    int col = (hh < 16) ? hh * 256 : 4096 + (hh - 16) * 256;
    size_t base = (size_t)s * QKVD + col;
    float x1 = x[base + d], x2 = x[base + d + 128];
    x[base + d]       = x1 * c - x2 * si;
    x[base + d + 128] = x2 * c + x1 * si;
}

// ================= flash attention w/ softcap (p = exp(s-50)), causal =================
#define BQ 64
#define QS_STR 68
#define VS_STR 260

__global__ void attn_kernel(const float* __restrict__ qkv, float* __restrict__ o) {
    extern __shared__ float sm[];
    float* Qs = sm;
    float* Ks = Qs + 256 * QS_STR;
    float* Vs = Ks + 256 * QS_STR;
    float* Ss = Vs + 64 * VS_STR;

    int qb = blockIdx.x;
    int head = blockIdx.y;
    int kvh = head >> 1;
    int t = threadIdx.x;

    for (int idx = t; idx < 64 * 64; idx += 256) {
        int i = idx >> 6, c = (idx & 63) * 4;
        float4 val = *(const float4*)&qkv[(size_t)(qb * BQ + i) * QKVD + head * HD + c];
        Qs[(c + 0) * QS_STR + i] = val.x;
        Qs[(c + 1) * QS_STR + i] = val.y;
        Qs[(c + 2) * QS_STR + i] = val.z;
        Qs[(c + 3) * QS_STR + i] = val.w;
    }

    float acc[64];
#pragma unroll
    for (int c = 0; c < 64; c++) acc[c] = 0.f;
    float lsum = 0.f;
    int oi = t & 63;
    int od = (t >> 6) * 64;
    int ti = (t >> 4) * 4;
    int tj = (t & 15) * 4;

    for (int kb = 0; kb <= qb; kb++) {
        __syncthreads();
        for (int idx = t; idx < 64 * 64; idx += 256) {
            int j = idx >> 6, c = (idx & 63) * 4;
            size_t gk = (size_t)(kb * BQ + j) * QKVD + 4096 + kvh * HD + c;
            size_t gv = (size_t)(kb * BQ + j) * QKVD + 6144 + kvh * HD + c;
            float4 kv = *(const float4*)&qkv[gk];
            Ks[(c + 0) * QS_STR + j] = kv.x;
            Ks[(c + 1) * QS_STR + j] = kv.y;
            Ks[(c + 2) * QS_STR + j] = kv.z;
            Ks[(c + 3) * QS_STR + j] = kv.w;
            *(float4*)&Vs[j * VS_STR + c] = *(const float4*)&qkv[gv];
        }
        __syncthreads();

        float s4[4][4];
#pragma unroll
        for (int i = 0; i < 4; i++)
#pragma unroll
            for (int j = 0; j < 4; j++) s4[i][j] = 0.f;
#pragma unroll 4
        for (int d = 0; d < 256; d++) {
            float4 a = *(const float4*)&Qs[d * QS_STR + ti];
            float4 b = *(const float4*)&Ks[d * QS_STR + tj];
            float av[4] = {a.x, a.y, a.z, a.w};
            float bv[4] = {b.x, b.y, b.z, b.w};
#pragma unroll
            for (int i = 0; i < 4; i++)
#pragma unroll
                for (int j = 0; j < 4; j++) s4[i][j] += av[i] * bv[j];
        }
#pragma unroll
        for (int i = 0; i < 4; i++) {
            int ig = qb * BQ + ti + i;
#pragma unroll
            for (int j = 0; j < 4; j++) {
                int jg = kb * BQ + tj + j;
                float sc = s4[i][j] * 0.0625f;
                sc = tanhf(sc * 0.02f) * 50.f;
                float p = (jg <= ig) ? __expf(sc - 50.f) : 0.f;
                Ss[(ti + i) * QS_STR + tj + j] = p;
            }
        }
        __syncthreads();

        const float* srow = &Ss[oi * QS_STR];
        for (int j = 0; j < 64; j++) {
            float p = srow[j];
            lsum += p;
            const float4* vrow = (const float4*)&Vs[j * VS_STR + od];
#pragma unroll
            for (int c = 0; c < 16; c++) {
                float4 vv = vrow[c];
                acc[c * 4 + 0] += p * vv.x;
                acc[c * 4 + 1] += p * vv.y;
                acc[c * 4 + 2] += p * vv.z;
                acc[c * 4 + 3] += p * vv.w;
            }
        }
    }

    float inv = 1.f / lsum;
    float* orow = &o[(size_t)(qb * BQ + oi) * QD + head * HD + od];
#pragma unroll
    for (int c = 0; c < 16; c++) {
        *(float4*)&orow[c * 4] = make_float4(acc[c*4+0]*inv, acc[c*4+1]*inv,
                                             acc[c*4+2]*inv, acc[c*4+3]*inv);
    }
}

// ===== SwiGLU fused with fp16-split convert: act[m] = split(gelu_tanh(g)*u) =====
__global__ void swiglu_conv_kernel(const float* __restrict__ gu, __half* __restrict__ dst) {
    int idx = blockIdx.x * 256 + threadIdx.x;    // over 2048*14336/2
    int m = idx / (IDIM / 2), c = (idx - m * (IDIM / 2)) * 2;
    const float* row = gu + (size_t)m * 2 * IDIM;
    float2 g = *(const float2*)(row + c);
    float2 u = *(const float2*)(row + IDIM + c);
    float t0 = tanhf(0.7978845608028654f * (g.x + 0.044715f * g.x * g.x * g.x));
    float t1 = tanhf(0.7978845608028654f * (g.y + 0.044715f * g.y * g.y * g.y));
    float v0 = 0.5f * g.x * (1.f + t0) * u.x;
    float v1 = 0.5f * g.y * (1.f + t1) * u.y;
    __half h0 = __float2half(v0), h1 = __float2half(v1);
    __half l0 = __float2half(v0 - __half2float(h0));
    __half l1 = __float2half(v1 - __half2float(h1));
    size_t base = (size_t)m * 2 * IDIM + c;
    *(__half2*)(dst + base)        = __halves2half2(h0, h1);
    *(__half2*)(dst + base + IDIM) = __halves2half2(l0, l1);
}

extern "C" void kernel_launch(void* const* d_in, const int* in_sizes, int n_in,
                              void* d_out, int out_size) {
    const float* hidden      = (const float*)d_in[0];
    const float* w_in        = (const float*)d_in[3];
    const float* w_post_attn = (const float*)d_in[4];
    const float* w_pre_ff    = (const float*)d_in[5];
    const float* w_post_ff   = (const float*)d_in[6];
    const float* wq          = (const float*)d_in[7];
    const float* wk          = (const float*)d_in[8];
    const float* wv          = (const float*)d_in[9];
    const float* wo          = (const float*)d_in[10];
    const float* w_gate      = (const float*)d_in[11];
    const float* w_up        = (const float*)d_in[12];
    const float* w_down      = (const float*)d_in[13];
    float* out = (float*)d_out;

    float *h, *qkv, *attn, *proj, *x1, *gu, *down;
    __half *act, *wt;
    cudaGetSymbolAddress((void**)&h, g_h);
    cudaGetSymbolAddress((void**)&qkv, g_qkv);
    cudaGetSymbolAddress((void**)&attn, g_attn);
    cudaGetSymbolAddress((void**)&proj, g_proj);
    cudaGetSymbolAddress((void**)&x1, g_x1);
    cudaGetSymbolAddress((void**)&gu, g_gu);
    cudaGetSymbolAddress((void**)&down, g_down);
    cudaGetSymbolAddress((void**)&act, g_act);
    cudaGetSymbolAddress((void**)&wt, g_wt);

    cudaFuncSetAttribute(gemm_mma, cudaFuncAttributeMaxDynamicSharedMemorySize, SMEM_MMA);
    const int smem_attn = (256 * QS_STR * 2 + 64 * VS_STR + 64 * QS_STR) * 4;
    cudaFuncSetAttribute(attn_kernel, cudaFuncAttributeMaxDynamicSharedMemorySize, smem_attn);

    dim3 wtb(32, 8);

    // ---- attention block ----
    rmsnorm_kernel<<<SQ, 256>>>(hidden, w_in, nullptr, h);
    convert_act<<<SQ * (HDIM/4) / 256, 256>>>(h, act, HDIM);
    convert_wt<<<dim3(QD/32,   HDIM/32), wtb>>>(wq, wt, HDIM, QD,   0);
    convert_wt<<<dim3(2048/32, HDIM/32), wtb>>>(wk, wt, HDIM, 2048, 4096);
    convert_wt<<<dim3(2048/32, HDIM/32), wtb>>>(wv, wt, HDIM, 2048, 6144);
    gemm_mma<<<dim3(SQ/BM, QKVD/BN), 256, SMEM_MMA>>>(act, wt, qkv, QKVD, HDIM);
    rope_kernel<<<SQ * 24 * 128 / 256, 256>>>(qkv);
    attn_kernel<<<dim3(SQ/BQ, NH), 256, smem_attn>>>(qkv, attn);
    convert_act<<<SQ * (QD/4) / 256, 256>>>(attn, act, QD);
    convert_wt<<<dim3(HDIM/32, QD/32), wtb>>>(wo, wt, QD, HDIM, 0);
    gemm_mma<<<dim3(SQ/BM, HDIM/BN), 256, SMEM_MMA>>>(act, wt, proj, HDIM, QD);
    rmsnorm_kernel<<<SQ, 256>>>(proj, w_post_attn, hidden, x1);

    // ---- MLP block ----
    rmsnorm_kernel<<<SQ, 256>>>(x1, w_pre_ff, nullptr, h);
    convert_act<<<SQ * (HDIM/4) / 256, 256>>>(h, act, HDIM);
    convert_wt<<<dim3(IDIM/32, HDIM/32), wtb>>>(w_gate, wt, HDIM, IDIM, 0);
    convert_wt<<<dim3(IDIM/32, HDIM/32), wtb>>>(w_up,   wt, HDIM, IDIM, IDIM);
    gemm_mma<<<dim3(SQ/BM, 2*IDIM/BN), 256, SMEM_MMA>>>(act, wt, gu, 2*IDIM, HDIM);
    swiglu_conv_kernel<<<SQ * (IDIM/2) / 256, 256>>>(gu, act);
    convert_wt<<<dim3(HDIM/32, IDIM/32), wtb>>>(w_down, wt, IDIM, HDIM, 0);
    gemm_mma<<<dim3(SQ/BM, HDIM/BN), 256, SMEM_MMA>>>(act, wt, down, HDIM, IDIM);
    rmsnorm_kernel<<<SQ, 256>>>(down, w_post_ff, x1, out);
}

// round 8
// speedup vs baseline: 1.2276x; 1.0305x over previous
#include <cuda_runtime.h>
#include <cuda_fp16.h>
#include <math.h>
#include <stdint.h>

#define SQ 2048
#define HDIM 3584
#define NH 16
#define NKV 8
#define HD 256
#define QKVD 8192           // 4096 q + 2048 k + 2048 v
#define QD 4096
#define IDIM 14336

// ---------------- scratch (allocation-free: __device__ globals) ----------------
static __device__ float g_qkv[SQ*QKVD];
static __device__ float g_proj[SQ*HDIM];
static __device__ float g_x1[SQ*HDIM];
static __device__ float g_gu[(size_t)SQ*2*IDIM];
static __device__ float g_down[SQ*HDIM];
static __device__ __half g_act[(size_t)SQ*2*IDIM];        // A' = [Ah|Al], up to [2048, 28672]
static __device__ __half g_wt[(size_t)(2*IDIM)*HDIM];     // B' K-major, up to [28672, 3584]

// ---------------- PTX helpers (arch-agnostic only: sm_80-level) ----------------
__device__ __forceinline__ uint32_t smem_u32(const void* p) {
    uint32_t a;
    asm("{ .reg .u64 t; cvta.to.shared.u64 t, %1; cvt.u32.u64 %0, t; }" : "=r"(a) : "l"(p));
    return a;
}
__device__ __forceinline__ void ldx4(uint32_t& r0, uint32_t& r1, uint32_t& r2, uint32_t& r3, uint32_t a) {
    asm volatile("ldmatrix.sync.aligned.m8n8.x4.shared.b16 {%0,%1,%2,%3}, [%4];"
                 : "=r"(r0), "=r"(r1), "=r"(r2), "=r"(r3) : "r"(a));
}
__device__ __forceinline__ void hmma(float* c, uint32_t a0, uint32_t a1, uint32_t a2, uint32_t a3,
                                     uint32_t b0, uint32_t b1) {
    asm volatile("mma.sync.aligned.m16n8k16.row.col.f32.f16.f16.f32 "
                 "{%0,%1,%2,%3},{%4,%5,%6,%7},{%8,%9},{%0,%1,%2,%3};"
                 : "+f"(c[0]), "+f"(c[1]), "+f"(c[2]), "+f"(c[3])
                 : "r"(a0), "r"(a1), "r"(a2), "r"(a3), "r"(b0), "r"(b1));
}
#define CP_ASYNC16(dst, src) \
    asm volatile("cp.async.cg.shared.global [%0], [%1], 16;" :: "r"(dst), "l"(src))
#define CP_COMMIT() asm volatile("cp.async.commit_group;" ::: "memory")
#define CP_WAIT(n)  asm volatile("cp.async.wait_group %0;" :: "n"(n) : "memory")

// ============ HMMA fp16 split GEMM: C[M,N] = (Ah+Al)[M,2K] @ B'[N,K]^T ============
#define BM 128
#define BN 128
#define BK 64
#define STG 3
#define ROWH 72                               // halves per smem row (64 + 8 pad); 144B rows
#define STAGE_A (BM*ROWH*2)                   // 18432
#define STAGE_B (STAGE_A + BN*ROWH*2)         // 36864 per stage
#define SMEM_MMA (STG*STAGE_B)                // 110592

__global__ void __launch_bounds__(256, 2)
gemm_mma(const __half* __restrict__ A, const __half* __restrict__ B,
         float* __restrict__ C, int N, int K) {
    extern __shared__ char smem[];
    uint32_t sbase = smem_u32(smem);
    const int K2 = 2 * K;
    int tid = threadIdx.x, lane = tid & 31, wid = tid >> 5;
    int m0 = blockIdx.x * BM, n0 = blockIdx.y * BN;
    int wm = (wid & 1) * 64, wn = (wid >> 1) * 32;
    int ntiles = K2 / BK;

    int lr = tid >> 3;
    int lc = (tid & 7) * 8;
    const __half* gA0 = A + (size_t)(m0 + lr) * K2 + lc;
    const __half* gB0 = B + (size_t)(n0 + lr) * K + lc;
    uint32_t sOff = (uint32_t)(lr * ROWH + lc) * 2;

    uint32_t foff = (uint32_t)(((lane & 15) * ROWH) + ((lane >> 4) * 8)) * 2;

    float acc[4][4][4];
#pragma unroll
    for (int a = 0; a < 4; a++)
#pragma unroll
        for (int b = 0; b < 4; b++)
#pragma unroll
            for (int c = 0; c < 4; c++) acc[a][b][c] = 0.f;

    auto LOAD = [&](int kt, int s) {
        int ak = kt * BK;
        int bk = (ak < K) ? ak : ak - K;      // B wraps: [Ah|Al] both hit same B
        uint32_t sA = sbase + s * STAGE_B;
        uint32_t sB = sA + STAGE_A;
#pragma unroll
        for (int h = 0; h < 4; h++) {
            CP_ASYNC16(sA + sOff + h * 32 * ROWH * 2, gA0 + (size_t)h * 32 * K2 + ak);
            CP_ASYNC16(sB + sOff + h * 32 * ROWH * 2, gB0 + (size_t)h * 32 * K + bk);
        }
    };

#pragma unroll
    for (int s = 0; s < STG - 1; s++) {
        LOAD(s, s);
        CP_COMMIT();
    }

    for (int i = 0; i < ntiles; i++) {
        CP_WAIT(STG - 2);
        __syncthreads();

        int pf = i + STG - 1;
        if (pf < ntiles) LOAD(pf, pf % STG);
        CP_COMMIT();

        int s = i % STG;
        uint32_t aB = sbase + s * STAGE_B;
        uint32_t bB = aB + STAGE_A;
        uint32_t aAddr = aB + (uint32_t)wm * ROWH * 2 + foff;
        uint32_t bAddr = bB + (uint32_t)wn * ROWH * 2 + foff;
#pragma unroll
        for (int ks = 0; ks < 4; ks++) {
            uint32_t af[4][4];
#pragma unroll
            for (int fm = 0; fm < 4; fm++)
                ldx4(af[fm][0], af[fm][1], af[fm][2], af[fm][3],
                     aAddr + (uint32_t)fm * 16 * ROWH * 2 + ks * 32);
            uint32_t t0, t1, t2, t3, t4, t5, t6, t7;
            ldx4(t0, t1, t2, t3, bAddr + ks * 32);
            ldx4(t4, t5, t6, t7, bAddr + 16 * ROWH * 2 + ks * 32);
            uint32_t b0[4] = {t0, t1, t4, t5};
            uint32_t b1[4] = {t2, t3, t6, t7};
#pragma unroll
            for (int fm = 0; fm < 4; fm++)
#pragma unroll
                for (int fn = 0; fn < 4; fn++)
                    hmma(acc[fm][fn], af[fm][0], af[fm][1], af[fm][2], af[fm][3],
                         b0[fn], b1[fn]);
        }
    }

#pragma unroll
    for (int fm = 0; fm < 4; fm++) {
        int r = m0 + wm + fm * 16 + (lane >> 2);
#pragma unroll
        for (int fn = 0; fn < 4; fn++) {
            int c = n0 + wn + fn * 8 + (lane & 3) * 2;
            *(float2*)&C[(size_t)r * N + c]       = make_float2(acc[fm][fn][0], acc[fm][fn][1]);
            *(float2*)&C[(size_t)(r + 8) * N + c] = make_float2(acc[fm][fn][2], acc[fm][fn][3]);
        }
    }
}

// ================= fp32 -> fp16 split helpers =================
__device__ __forceinline__ void split_store2(__half* dst, size_t base, int K, float x, float y) {
    __half hx = __float2half(x), hy = __float2half(y);
    __half lx = __float2half(x - __half2float(hx));
    __half ly = __float2half(y - __half2float(hy));
    *(__half2*)(dst + base)     = __halves2half2(hx, hy);
    *(__half2*)(dst + base + K) = __halves2half2(lx, ly);
}

// W[K,N] fp32 -> out[n_off+n][k] fp16 K-major (transpose)
__global__ void convert_wt(const float* __restrict__ W, __half* __restrict__ out,
                           int K, int N, int n_off) {
    __shared__ float tile[32][33];
    int n0 = blockIdx.x * 32, k0 = blockIdx.y * 32;
    int tx = threadIdx.x, ty = threadIdx.y;   // 32 x 8
#pragma unroll
    for (int r = 0; r < 4; r++)
        tile[ty + r * 8][tx] = W[(size_t)(k0 + ty + r * 8) * N + n0 + tx];
    __syncthreads();
#pragma unroll
    for (int r = 0; r < 4; r++) {
        int n = ty + r * 8;
        out[(size_t)(n_off + n0 + n) * K + k0 + tx] = __float2half(tile[tx][n]);
    }
}

// ===== RMSNorm writing fp16 split [Ah|Al] directly (row length 2*HDIM) =====
__global__ void rmsnorm_split_kernel(const float* __restrict__ in, const float* __restrict__ w,
                                     __half* __restrict__ act) {
    int row = blockIdx.x;
    const float* x = in + (size_t)row * HDIM;
    float ss = 0.f;
    for (int c = threadIdx.x; c < HDIM; c += 256) { float v = x[c]; ss += v * v; }
    __shared__ float red[256];
    red[threadIdx.x] = ss;
    __syncthreads();
    for (int s = 128; s > 0; s >>= 1) {
        if (threadIdx.x < s) red[threadIdx.x] += red[threadIdx.x + s];
        __syncthreads();
    }
    float scale = rsqrtf(red[0] / (float)HDIM + 1e-6f);
    for (int c = threadIdx.x * 2; c < HDIM; c += 512) {
        float v0 = x[c] * scale * w[c];
        float v1 = x[c + 1] * scale * w[c + 1];
        split_store2(act, (size_t)row * 2 * HDIM + c, HDIM, v0, v1);
    }
}

// ================= RMSNorm fp32 out (+ residual) =================
__global__ void rmsnorm_kernel(const float* __restrict__ in, const float* __restrict__ w,
                               const float* __restrict__ resid, float* __restrict__ out) {
    int row = blockIdx.x;
    const float* x = in + (size_t)row * HDIM;
    float ss = 0.f;
    for (int c = threadIdx.x; c < HDIM; c += 256) { float v = x[c]; ss += v * v; }
    __shared__ float red[256];
    red[threadIdx.x] = ss;
    __syncthreads();
    for (int s = 128; s > 0; s >>= 1) {
        if (threadIdx.x < s) red[threadIdx.x] += red[threadIdx.x + s];
        __syncthreads();
    }
    float scale = rsqrtf(red[0] / (float)HDIM + 1e-6f);
    for (int c = threadIdx.x; c < HDIM; c += 256) {
        float v = x[c] * scale * w[c];
        if (resid) v += resid[(size_t)row * HDIM + c];
        out[(size_t)row * HDIM + c] = v;
    }
}

// ================= RoPE in-place on qkv [2048, 8192] =================
__global__ void rope_kernel(float* __restrict__ x) {
    int idx = blockIdx.x * 256 + threadIdx.x;   // over 2048*24*128
    int d = idx & 127;
    int hh = (idx >> 7) % 24;
    int s = idx / (128 * 24);
    float invf = (float)exp(-((double)(2 * d) / (double)HD) * log(10000.0));
    float ang = (float)s * invf;
    float c = (float)cos((double)ang);
    float si = (float)sin((double)ang);
    int col = (hh < 16) ? hh * 256 : 4096 + (hh - 16) * 256;
    size_t base = (size_t)s * QKVD + col;
    float x1 = x[base + d], x2 = x[base + d + 128];
    x[base + d]       = x1 * c - x2 * si;
    x[base + d + 128] = x2 * c + x1 * si;
}

// ====== flash attention w/ softcap (p = exp(s-50)), causal; split-fp16 epilogue ======
// Qs/Ks stride 68 (float4-aligned); Ss stride 65 (scalar-only, bank-friendly)
#define BQ 64
#define QS_STR 68
#define SS_STR 65
#define VS_STR 260

__global__ void attn_kernel(const float* __restrict__ qkv, __half* __restrict__ act) {
    extern __shared__ float sm[];
    float* Qs = sm;                       // [256][QS_STR] transposed: Qs[d][i]
    float* Ks = Qs + 256 * QS_STR;        // [256][QS_STR] transposed: Ks[d][j]
    float* Vs = Ks + 256 * QS_STR;        // [64][VS_STR]
    float* Ss = Vs + 64 * VS_STR;         // [64][SS_STR]  p values

    int qb = blockIdx.x;
    int head = blockIdx.y;
    int kvh = head >> 1;
    int t = threadIdx.x;

    for (int idx = t; idx < 64 * 64; idx += 256) {
        int i = idx >> 6, c = (idx & 63) * 4;
        float4 val = *(const float4*)&qkv[(size_t)(qb * BQ + i) * QKVD + head * HD + c];
        Qs[(c + 0) * QS_STR + i] = val.x;
        Qs[(c + 1) * QS_STR + i] = val.y;
        Qs[(c + 2) * QS_STR + i] = val.z;
        Qs[(c + 3) * QS_STR + i] = val.w;
    }

    // PV mapping: thread owns rows orow..orow+3 and 16-col chunk og*16
    int orow = (t & 15) * 4;
    int og = t >> 4;                    // 0..15
    float acc[4][16];
#pragma unroll
    for (int r = 0; r < 4; r++)
#pragma unroll
        for (int c = 0; c < 16; c++) acc[r][c] = 0.f;
    float lsum[4] = {0.f, 0.f, 0.f, 0.f};

    int ti = (t >> 4) * 4;              // score-phase rows
    int tj = (t & 15) * 4;              // score-phase cols

    for (int kb = 0; kb <= qb; kb++) {
        __syncthreads();
        for (int idx = t; idx < 64 * 64; idx += 256) {
            int j = idx >> 6, c = (idx & 63) * 4;
            size_t gk = (size_t)(kb * BQ + j) * QKVD + 4096 + kvh * HD + c;
            size_t gv = (size_t)(kb * BQ + j) * QKVD + 6144 + kvh * HD + c;
            float4 kv = *(const float4*)&qkv[gk];
            Ks[(c + 0) * QS_STR + j] = kv.x;
            Ks[(c + 1) * QS_STR + j] = kv.y;
            Ks[(c + 2) * QS_STR + j] = kv.z;
            Ks[(c + 3) * QS_STR + j] = kv.w;
            *(float4*)&Vs[j * VS_STR + c] = *(const float4*)&qkv[gv];
        }
        __syncthreads();

        float s4[4][4];
#pragma unroll
        for (int i = 0; i < 4; i++)
#pragma unroll
            for (int j = 0; j < 4; j++) s4[i][j] = 0.f;
#pragma unroll 4
        for (int d = 0; d < 256; d++) {
            float4 a = *(const float4*)&Qs[d * QS_STR + ti];
            float4 b = *(const float4*)&Ks[d * QS_STR + tj];
            float av[4] = {a.x, a.y, a.z, a.w};
            float bv[4] = {b.x, b.y, b.z, b.w};
#pragma unroll
            for (int i = 0; i < 4; i++)
#pragma unroll
                for (int j = 0; j < 4; j++) s4[i][j] += av[i] * bv[j];
        }
#pragma unroll
        for (int i = 0; i < 4; i++) {
            int ig = qb * BQ + ti + i;
#pragma unroll
            for (int j = 0; j < 4; j++) {
                int jg = kb * BQ + tj + j;
                float sc = s4[i][j] * 0.0625f;
                sc = tanhf(sc * 0.02f) * 50.f;
                float p = (jg <= ig) ? __expf(sc - 50.f) : 0.f;
                Ss[(ti + i) * SS_STR + tj + j] = p;
            }
        }
        __syncthreads();

        // PV: 4 rows x 16 cols per thread; V float4 loads are warp-broadcast
        for (int j = 0; j < 64; j++) {
            float p0 = Ss[(orow + 0) * SS_STR + j];
            float p1 = Ss[(orow + 1) * SS_STR + j];
            float p2 = Ss[(orow + 2) * SS_STR + j];
            float p3 = Ss[(orow + 3) * SS_STR + j];
            lsum[0] += p0; lsum[1] += p1; lsum[2] += p2; lsum[3] += p3;
            const float4* vrow = (const float4*)&Vs[j * VS_STR + og * 16];
#pragma unroll
            for (int c4 = 0; c4 < 4; c4++) {
                float4 vv = vrow[c4];
                acc[0][c4*4+0] += p0 * vv.x; acc[0][c4*4+1] += p0 * vv.y;
                acc[0][c4*4+2] += p0 * vv.z; acc[0][c4*4+3] += p0 * vv.w;
                acc[1][c4*4+0] += p1 * vv.x; acc[1][c4*4+1] += p1 * vv.y;
                acc[1][c4*4+2] += p1 * vv.z; acc[1][c4*4+3] += p1 * vv.w;
                acc[2][c4*4+0] += p2 * vv.x; acc[2][c4*4+1] += p2 * vv.y;
                acc[2][c4*4+2] += p2 * vv.z; acc[2][c4*4+3] += p2 * vv.w;
                acc[3][c4*4+0] += p3 * vv.x; acc[3][c4*4+1] += p3 * vv.y;
                acc[3][c4*4+2] += p3 * vv.z; acc[3][c4*4+3] += p3 * vv.w;
            }
        }
    }

    // epilogue: write fp16 split directly into act (row length 2*QD)
#pragma unroll
    for (int r = 0; r < 4; r++) {
        float inv = 1.f / lsum[r];
        size_t base = (size_t)(qb * BQ + orow + r) * 2 * QD + head * HD + og * 16;
#pragma unroll
        for (int c = 0; c < 16; c += 2)
            split_store2(act, base + c, QD, acc[r][c] * inv, acc[r][c + 1] * inv);
    }
}

// ===== SwiGLU fused with fp16-split convert: act[m] = split(gelu_tanh(g)*u) =====
__global__ void swiglu_conv_kernel(const float* __restrict__ gu, __half* __restrict__ dst) {
    int idx = blockIdx.x * 256 + threadIdx.x;    // over 2048*14336/2
    int m = idx / (IDIM / 2), c = (idx - m * (IDIM / 2)) * 2;
    const float* row = gu + (size_t)m * 2 * IDIM;
    float2 g = *(const float2*)(row + c);
    float2 u = *(const float2*)(row + IDIM + c);
    float t0 = tanhf(0.7978845608028654f * (g.x + 0.044715f * g.x * g.x * g.x));
    float t1 = tanhf(0.7978845608028654f * (g.y + 0.044715f * g.y * g.y * g.y));
    float v0 = 0.5f * g.x * (1.f + t0) * u.x;
    float v1 = 0.5f * g.y * (1.f + t1) * u.y;
    split_store2(dst, (size_t)m * 2 * IDIM + c, IDIM, v0, v1);
}

extern "C" void kernel_launch(void* const* d_in, const int* in_sizes, int n_in,
                              void* d_out, int out_size) {
    const float* hidden      = (const float*)d_in[0];
    const float* w_in        = (const float*)d_in[3];
    const float* w_post_attn = (const float*)d_in[4];
    const float* w_pre_ff    = (const float*)d_in[5];
    const float* w_post_ff   = (const float*)d_in[6];
    const float* wq          = (const float*)d_in[7];
    const float* wk          = (const float*)d_in[8];
    const float* wv          = (const float*)d_in[9];
    const float* wo          = (const float*)d_in[10];
    const float* w_gate      = (const float*)d_in[11];
    const float* w_up        = (const float*)d_in[12];
    const float* w_down      = (const float*)d_in[13];
    float* out = (float*)d_out;

    float *qkv, *proj, *x1, *gu, *down;
    __half *act, *wt;
    cudaGetSymbolAddress((void**)&qkv, g_qkv);
    cudaGetSymbolAddress((void**)&proj, g_proj);
    cudaGetSymbolAddress((void**)&x1, g_x1);
    cudaGetSymbolAddress((void**)&gu, g_gu);
    cudaGetSymbolAddress((void**)&down, g_down);
    cudaGetSymbolAddress((void**)&act, g_act);
    cudaGetSymbolAddress((void**)&wt, g_wt);

    cudaFuncSetAttribute(gemm_mma, cudaFuncAttributeMaxDynamicSharedMemorySize, SMEM_MMA);
    const int smem_attn = (256 * QS_STR * 2 + 64 * VS_STR + 64 * SS_STR) * 4;
    cudaFuncSetAttribute(attn_kernel, cudaFuncAttributeMaxDynamicSharedMemorySize, smem_attn);

    dim3 wtb(32, 8);

    // ---- attention block ----
    rmsnorm_split_kernel<<<SQ, 256>>>(hidden, w_in, act);
    convert_wt<<<dim3(QD/32,   HDIM/32), wtb>>>(wq, wt, HDIM, QD,   0);
    convert_wt<<<dim3(2048/32, HDIM/32), wtb>>>(wk, wt, HDIM, 2048, 4096);
    convert_wt<<<dim3(2048/32, HDIM/32), wtb>>>(wv, wt, HDIM, 2048, 6144);
    gemm_mma<<<dim3(SQ/BM, QKVD/BN), 256, SMEM_MMA>>>(act, wt, qkv, QKVD, HDIM);
    rope_kernel<<<SQ * 24 * 128 / 256, 256>>>(qkv);
    attn_kernel<<<dim3(SQ/BQ, NH), 256, smem_attn>>>(qkv, act);
    convert_wt<<<dim3(HDIM/32, QD/32), wtb>>>(wo, wt, QD, HDIM, 0);
    gemm_mma<<<dim3(SQ/BM, HDIM/BN), 256, SMEM_MMA>>>(act, wt, proj, HDIM, QD);
    rmsnorm_kernel<<<SQ, 256>>>(proj, w_post_attn, hidden, x1);

    // ---- MLP block ----
    rmsnorm_split_kernel<<<SQ, 256>>>(x1, w_pre_ff, act);
    convert_wt<<<dim3(IDIM/32, HDIM/32), wtb>>>(w_gate, wt, HDIM, IDIM, 0);
    convert_wt<<<dim3(IDIM/32, HDIM/32), wtb>>>(w_up,   wt, HDIM, IDIM, IDIM);
    gemm_mma<<<dim3(SQ/BM, 2*IDIM/BN), 256, SMEM_MMA>>>(act, wt, gu, 2*IDIM, HDIM);
    swiglu_conv_kernel<<<SQ * (IDIM/2) / 256, 256>>>(gu, act);
    convert_wt<<<dim3(HDIM/32, IDIM/32), wtb>>>(w_down, wt, IDIM, HDIM, 0);
    gemm_mma<<<dim3(SQ/BM, HDIM/BN), 256, SMEM_MMA>>>(act, wt, down, HDIM, IDIM);
    rmsnorm_kernel<<<SQ, 256>>>(down, w_post_ff, x1, out);
}

// round 9
// speedup vs baseline: 1.7743x; 1.4453x over previous
#include <cuda_runtime.h>
#include <cuda_fp16.h>
#include <math.h>
#include <stdint.h>

#define SQ 2048
#define HDIM 3584
#define NH 16
#define NKV 8
#define HD 256
#define QKVD 8192           // 4096 q + 2048 k + 2048 v
#define QD 4096
#define IDIM 14336

// ---------------- scratch (allocation-free: __device__ globals) ----------------
static __device__ float g_qkv[SQ*QKVD];
static __device__ float g_proj[SQ*HDIM];
static __device__ float g_x1[SQ*HDIM];
static __device__ float g_gu[(size_t)SQ*2*IDIM];
static __device__ float g_down[SQ*HDIM];
static __device__ __half g_act[(size_t)SQ*IDIM];          // A fp16, up to [2048, 14336]
static __device__ __half g_wt[(size_t)(2*IDIM)*HDIM];     // B fp16 K-major, up to [28672, 3584]

// ---------------- PTX helpers (arch-agnostic only: sm_80-level) ----------------
__device__ __forceinline__ uint32_t smem_u32(const void* p) {
    uint32_t a;
    asm("{ .reg .u64 t; cvta.to.shared.u64 t, %1; cvt.u32.u64 %0, t; }" : "=r"(a) : "l"(p));
    return a;
}
__device__ __forceinline__ void ldx4(uint32_t& r0, uint32_t& r1, uint32_t& r2, uint32_t& r3, uint32_t a) {
    asm volatile("ldmatrix.sync.aligned.m8n8.x4.shared.b16 {%0,%1,%2,%3}, [%4];"
                 : "=r"(r0), "=r"(r1), "=r"(r2), "=r"(r3) : "r"(a));
}
__device__ __forceinline__ void hmma(float* c, uint32_t a0, uint32_t a1, uint32_t a2, uint32_t a3,
                                     uint32_t b0, uint32_t b1) {
    asm volatile("mma.sync.aligned.m16n8k16.row.col.f32.f16.f16.f32 "
                 "{%0,%1,%2,%3},{%4,%5,%6,%7},{%8,%9},{%0,%1,%2,%3};"
                 : "+f"(c[0]), "+f"(c[1]), "+f"(c[2]), "+f"(c[3])
                 : "r"(a0), "r"(a1), "r"(a2), "r"(a3), "r"(b0), "r"(b1));
}
#define CP_ASYNC16(dst, src) \
    asm volatile("cp.async.cg.shared.global [%0], [%1], 16;" :: "r"(dst), "l"(src))
#define CP_COMMIT() asm volatile("cp.async.commit_group;" ::: "memory")
#define CP_WAIT(n)  asm volatile("cp.async.wait_group %0;" :: "n"(n) : "memory")

// ============ HMMA fp16 GEMM: C[M,N] = A[M,K] @ B[N,K]^T, fp32 accumulate ============
#define BM 128
#define BN 128
#define BK 64
#define STG 3
#define ROWH 72                               // halves per smem row (64 + 8 pad); 144B rows
#define STAGE_A (BM*ROWH*2)                   // 18432
#define STAGE_B (STAGE_A + BN*ROWH*2)         // 36864 per stage
#define SMEM_MMA (STG*STAGE_B)                // 110592

__global__ void __launch_bounds__(256, 2)
gemm_mma(const __half* __restrict__ A, const __half* __restrict__ B,
         float* __restrict__ C, int N, int K) {
    extern __shared__ char smem[];
    uint32_t sbase = smem_u32(smem);
    int tid = threadIdx.x, lane = tid & 31, wid = tid >> 5;
    int m0 = blockIdx.x * BM, n0 = blockIdx.y * BN;
    int wm = (wid & 1) * 64, wn = (wid >> 1) * 32;
    int ntiles = K / BK;

    int lr = tid >> 3;
    int lc = (tid & 7) * 8;
    const __half* gA0 = A + (size_t)(m0 + lr) * K + lc;
    const __half* gB0 = B + (size_t)(n0 + lr) * K + lc;
    uint32_t sOff = (uint32_t)(lr * ROWH + lc) * 2;

    uint32_t foff = (uint32_t)(((lane & 15) * ROWH) + ((lane >> 4) * 8)) * 2;

    float acc[4][4][4];
#pragma unroll
    for (int a = 0; a < 4; a++)
#pragma unroll
        for (int b = 0; b < 4; b++)
#pragma unroll
            for (int c = 0; c < 4; c++) acc[a][b][c] = 0.f;

    auto LOAD = [&](int kt, int s) {
        int ak = kt * BK;
        uint32_t sA = sbase + s * STAGE_B;
        uint32_t sB = sA + STAGE_A;
#pragma unroll
        for (int h = 0; h < 4; h++) {
            CP_ASYNC16(sA + sOff + h * 32 * ROWH * 2, gA0 + (size_t)h * 32 * K + ak);
            CP_ASYNC16(sB + sOff + h * 32 * ROWH * 2, gB0 + (size_t)h * 32 * K + ak);
        }
    };

#pragma unroll
    for (int s = 0; s < STG - 1; s++) {
        LOAD(s, s);
        CP_COMMIT();
    }

    for (int i = 0; i < ntiles; i++) {
        CP_WAIT(STG - 2);
        __syncthreads();

        int pf = i + STG - 1;
        if (pf < ntiles) LOAD(pf, pf % STG);
        CP_COMMIT();

        int s = i % STG;
        uint32_t aB = sbase + s * STAGE_B;
        uint32_t bB = aB + STAGE_A;
        uint32_t aAddr = aB + (uint32_t)wm * ROWH * 2 + foff;
        uint32_t bAddr = bB + (uint32_t)wn * ROWH * 2 + foff;
#pragma unroll
        for (int ks = 0; ks < 4; ks++) {
            uint32_t af[4][4];
#pragma unroll
            for (int fm = 0; fm < 4; fm++)
                ldx4(af[fm][0], af[fm][1], af[fm][2], af[fm][3],
                     aAddr + (uint32_t)fm * 16 * ROWH * 2 + ks * 32);
            uint32_t t0, t1, t2, t3, t4, t5, t6, t7;
            ldx4(t0, t1, t2, t3, bAddr + ks * 32);
            ldx4(t4, t5, t6, t7, bAddr + 16 * ROWH * 2 + ks * 32);
            uint32_t b0[4] = {t0, t1, t4, t5};
            uint32_t b1[4] = {t2, t3, t6, t7};
#pragma unroll
            for (int fm = 0; fm < 4; fm++)
#pragma unroll
                for (int fn = 0; fn < 4; fn++)
                    hmma(acc[fm][fn], af[fm][0], af[fm][1], af[fm][2], af[fm][3],
                         b0[fn], b1[fn]);
        }
    }

#pragma unroll
    for (int fm = 0; fm < 4; fm++) {
        int r = m0 + wm + fm * 16 + (lane >> 2);
#pragma unroll
        for (int fn = 0; fn < 4; fn++) {
            int c = n0 + wn + fn * 8 + (lane & 3) * 2;
            *(float2*)&C[(size_t)r * N + c]       = make_float2(acc[fm][fn][0], acc[fm][fn][1]);
            *(float2*)&C[(size_t)(r + 8) * N + c] = make_float2(acc[fm][fn][2], acc[fm][fn][3]);
        }
    }
}

// W[K,N] fp32 -> out[n_off+n][k] fp16 K-major (transpose)
__global__ void convert_wt(const float* __restrict__ W, __half* __restrict__ out,
                           int K, int N, int n_off) {
    __shared__ float tile[32][33];
    int n0 = blockIdx.x * 32, k0 = blockIdx.y * 32;
    int tx = threadIdx.x, ty = threadIdx.y;   // 32 x 8
#pragma unroll
    for (int r = 0; r < 4; r++)
        tile[ty + r * 8][tx] = W[(size_t)(k0 + ty + r * 8) * N + n0 + tx];
    __syncthreads();
#pragma unroll
    for (int r = 0; r < 4; r++) {
        int n = ty + r * 8;
        out[(size_t)(n_off + n0 + n) * K + k0 + tx] = __float2half(tile[tx][n]);
    }
}

// ===== RMSNorm writing fp16 directly (row length HDIM) =====
__global__ void rmsnorm_h_kernel(const float* __restrict__ in, const float* __restrict__ w,
                                 __half* __restrict__ act) {
    int row = blockIdx.x;
    const float* x = in + (size_t)row * HDIM;
    float ss = 0.f;
    for (int c = threadIdx.x; c < HDIM; c += 256) { float v = x[c]; ss += v * v; }
    __shared__ float red[256];
    red[threadIdx.x] = ss;
    __syncthreads();
    for (int s = 128; s > 0; s >>= 1) {
        if (threadIdx.x < s) red[threadIdx.x] += red[threadIdx.x + s];
        __syncthreads();
    }
    float scale = rsqrtf(red[0] / (float)HDIM + 1e-6f);
    for (int c = threadIdx.x * 2; c < HDIM; c += 512) {
        float v0 = x[c] * scale * w[c];
        float v1 = x[c + 1] * scale * w[c + 1];
        *(__half2*)(act + (size_t)row * HDIM + c) =
            __halves2half2(__float2half(v0), __float2half(v1));
    }
}

// ================= RMSNorm fp32 out (+ residual) =================
__global__ void rmsnorm_kernel(const float* __restrict__ in, const float* __restrict__ w,
                               const float* __restrict__ resid, float* __restrict__ out) {
    int row = blockIdx.x;
    const float* x = in + (size_t)row * HDIM;
    float ss = 0.f;
    for (int c = threadIdx.x; c < HDIM; c += 256) { float v = x[c]; ss += v * v; }
    __shared__ float red[256];
    red[threadIdx.x] = ss;
    __syncthreads();
    for (int s = 128; s > 0; s >>= 1) {
        if (threadIdx.x < s) red[threadIdx.x] += red[threadIdx.x + s];
        __syncthreads();
    }
    float scale = rsqrtf(red[0] / (float)HDIM + 1e-6f);
    for (int c = threadIdx.x; c < HDIM; c += 256) {
        float v = x[c] * scale * w[c];
        if (resid) v += resid[(size_t)row * HDIM + c];
        out[(size_t)row * HDIM + c] = v;
    }
}

// ================= RoPE in-place on qkv [2048, 8192] =================
__global__ void rope_kernel(float* __restrict__ x) {
    int idx = blockIdx.x * 256 + threadIdx.x;   // over 2048*24*128
    int d = idx & 127;
    int hh = (idx >> 7) % 24;
    int s = idx / (128 * 24);
    float invf = (float)exp(-((double)(2 * d) / (double)HD) * log(10000.0));
    float ang = (float)s * invf;
    float c = (float)cos((double)ang);
    float si = (float)sin((double)ang);
    int col = (hh < 16) ? hh * 256 : 4096 + (hh - 16) * 256;
    size_t base = (size_t)s * QKVD + col;
    float x1 = x[base + d], x2 = x[base + d + 128];
    x[base + d]       = x1 * c - x2 * si;
    x[base + d + 128] = x2 * c + x1 * si;
}

// ====== flash attention w/ softcap (p = exp(s-50)), causal; fp16 epilogue ======
#define BQ 64
#define QS_STR 68
#define SS_STR 65
#define VS_STR 260

__global__ void attn_kernel(const float* __restrict__ qkv, __half* __restrict__ act) {
    extern __shared__ float sm[];
    float* Qs = sm;                       // [256][QS_STR] transposed: Qs[d][i]
    float* Ks = Qs + 256 * QS_STR;        // [256][QS_STR] transposed: Ks[d][j]
    float* Vs = Ks + 256 * QS_STR;        // [64][VS_STR]
    float* Ss = Vs + 64 * VS_STR;         // [64][SS_STR]  p values

    int qb = blockIdx.x;
    int head = blockIdx.y;
    int kvh = head >> 1;
    int t = threadIdx.x;

    for (int idx = t; idx < 64 * 64; idx += 256) {
        int i = idx >> 6, c = (idx & 63) * 4;
        float4 val = *(const float4*)&qkv[(size_t)(qb * BQ + i) * QKVD + head * HD + c];
        Qs[(c + 0) * QS_STR + i] = val.x;
        Qs[(c + 1) * QS_STR + i] = val.y;
        Qs[(c + 2) * QS_STR + i] = val.z;
        Qs[(c + 3) * QS_STR + i] = val.w;
    }

    int orow = (t & 15) * 4;
    int og = t >> 4;                    // 0..15
    float acc[4][16];
#pragma unroll
    for (int r = 0; r < 4; r++)
#pragma unroll
        for (int c = 0; c < 16; c++) acc[r][c] = 0.f;
    float lsum[4] = {0.f, 0.f, 0.f, 0.f};

    int ti = (t >> 4) * 4;
    int tj = (t & 15) * 4;

    for (int kb = 0; kb <= qb; kb++) {
        __syncthreads();
        for (int idx = t; idx < 64 * 64; idx += 256) {
            int j = idx >> 6, c = (idx & 63) * 4;
            size_t gk = (size_t)(kb * BQ + j) * QKVD + 4096 + kvh * HD + c;
            size_t gv = (size_t)(kb * BQ + j) * QKVD + 6144 + kvh * HD + c;
            float4 kv = *(const float4*)&qkv[gk];
            Ks[(c + 0) * QS_STR + j] = kv.x;
            Ks[(c + 1) * QS_STR + j] = kv.y;
            Ks[(c + 2) * QS_STR + j] = kv.z;
            Ks[(c + 3) * QS_STR + j] = kv.w;
            *(float4*)&Vs[j * VS_STR + c] = *(const float4*)&qkv[gv];
        }
        __syncthreads();

        float s4[4][4];
#pragma unroll
        for (int i = 0; i < 4; i++)
#pragma unroll
            for (int j = 0; j < 4; j++) s4[i][j] = 0.f;
#pragma unroll 4
        for (int d = 0; d < 256; d++) {
            float4 a = *(const float4*)&Qs[d * QS_STR + ti];
            float4 b = *(const float4*)&Ks[d * QS_STR + tj];
            float av[4] = {a.x, a.y, a.z, a.w};
            float bv[4] = {b.x, b.y, b.z, b.w};
#pragma unroll
            for (int i = 0; i < 4; i++)
#pragma unroll
                for (int j = 0; j < 4; j++) s4[i][j] += av[i] * bv[j];
        }
#pragma unroll
        for (int i = 0; i < 4; i++) {
            int ig = qb * BQ + ti + i;
#pragma unroll
            for (int j = 0; j < 4; j++) {
                int jg = kb * BQ + tj + j;
                float sc = s4[i][j] * 0.0625f;
                sc = tanhf(sc * 0.02f) * 50.f;
                float p = (jg <= ig) ? __expf(sc - 50.f) : 0.f;
                Ss[(ti + i) * SS_STR + tj + j] = p;
            }
        }
        __syncthreads();

        for (int j = 0; j < 64; j++) {
            float p0 = Ss[(orow + 0) * SS_STR + j];
            float p1 = Ss[(orow + 1) * SS_STR + j];
            float p2 = Ss[(orow + 2) * SS_STR + j];
            float p3 = Ss[(orow + 3) * SS_STR + j];
            lsum[0] += p0; lsum[1] += p1; lsum[2] += p2; lsum[3] += p3;
            const float4* vrow = (const float4*)&Vs[j * VS_STR + og * 16];
#pragma unroll
            for (int c4 = 0; c4 < 4; c4++) {
                float4 vv = vrow[c4];
                acc[0][c4*4+0] += p0 * vv.x; acc[0][c4*4+1] += p0 * vv.y;
                acc[0][c4*4+2] += p0 * vv.z; acc[0][c4*4+3] += p0 * vv.w;
                acc[1][c4*4+0] += p1 * vv.x; acc[1][c4*4+1] += p1 * vv.y;
                acc[1][c4*4+2] += p1 * vv.z; acc[1][c4*4+3] += p1 * vv.w;
                acc[2][c4*4+0] += p2 * vv.x; acc[2][c4*4+1] += p2 * vv.y;
                acc[2][c4*4+2] += p2 * vv.z; acc[2][c4*4+3] += p2 * vv.w;
                acc[3][c4*4+0] += p3 * vv.x; acc[3][c4*4+1] += p3 * vv.y;
                acc[3][c4*4+2] += p3 * vv.z; acc[3][c4*4+3] += p3 * vv.w;
            }
        }
    }

    // epilogue: write fp16 directly into act (row length QD)
#pragma unroll
    for (int r = 0; r < 4; r++) {
        float inv = 1.f / lsum[r];
        size_t base = (size_t)(qb * BQ + orow + r) * QD + head * HD + og * 16;
#pragma unroll
        for (int c = 0; c < 16; c += 2)
            *(__half2*)(act + base + c) =
                __halves2half2(__float2half(acc[r][c] * inv), __float2half(acc[r][c + 1] * inv));
    }
}

// ===== SwiGLU fused with fp16 convert: act[m] = fp16(gelu_tanh(g)*u) =====
__global__ void swiglu_conv_kernel(const float* __restrict__ gu, __half* __restrict__ dst) {
    int idx = blockIdx.x * 256 + threadIdx.x;    // over 2048*14336/2
    int m = idx / (IDIM / 2), c = (idx - m * (IDIM / 2)) * 2;
    const float* row = gu + (size_t)m * 2 * IDIM;
    float2 g = *(const float2*)(row + c);
    float2 u = *(const float2*)(row + IDIM + c);
    float t0 = tanhf(0.7978845608028654f * (g.x + 0.044715f * g.x * g.x * g.x));
    float t1 = tanhf(0.7978845608028654f * (g.y + 0.044715f * g.y * g.y * g.y));
    float v0 = 0.5f * g.x * (1.f + t0) * u.x;
    float v1 = 0.5f * g.y * (1.f + t1) * u.y;
    *(__half2*)(dst + (size_t)m * IDIM + c) =
        __halves2half2(__float2half(v0), __float2half(v1));
}

extern "C" void kernel_launch(void* const* d_in, const int* in_sizes, int n_in,
                              void* d_out, int out_size) {
    const float* hidden      = (const float*)d_in[0];
    const float* w_in        = (const float*)d_in[3];
    const float* w_post_attn = (const float*)d_in[4];
    const float* w_pre_ff    = (const float*)d_in[5];
    const float* w_post_ff   = (const float*)d_in[6];
    const float* wq          = (const float*)d_in[7];
    const float* wk          = (const float*)d_in[8];
    const float* wv          = (const float*)d_in[9];
    const float* wo          = (const float*)d_in[10];
    const float* w_gate      = (const float*)d_in[11];
    const float* w_up        = (const float*)d_in[12];
    const float* w_down      = (const float*)d_in[13];
    float* out = (float*)d_out;

    float *qkv, *proj, *x1, *gu, *down;
    __half *act, *wt;
    cudaGetSymbolAddress((void**)&qkv, g_qkv);
    cudaGetSymbolAddress((void**)&proj, g_proj);
    cudaGetSymbolAddress((void**)&x1, g_x1);
    cudaGetSymbolAddress((void**)&gu, g_gu);
    cudaGetSymbolAddress((void**)&down, g_down);
    cudaGetSymbolAddress((void**)&act, g_act);
    cudaGetSymbolAddress((void**)&wt, g_wt);

    cudaFuncSetAttribute(gemm_mma, cudaFuncAttributeMaxDynamicSharedMemorySize, SMEM_MMA);
    const int smem_attn = (256 * QS_STR * 2 + 64 * VS_STR + 64 * SS_STR) * 4;
    cudaFuncSetAttribute(attn_kernel, cudaFuncAttributeMaxDynamicSharedMemorySize, smem_attn);

    dim3 wtb(32, 8);

    // ---- attention block ----
    rmsnorm_h_kernel<<<SQ, 256>>>(hidden, w_in, act);
    convert_wt<<<dim3(QD/32,   HDIM/32), wtb>>>(wq, wt, HDIM, QD,   0);
    convert_wt<<<dim3(2048/32, HDIM/32), wtb>>>(wk, wt, HDIM, 2048, 4096);
    convert_wt<<<dim3(2048/32, HDIM/32), wtb>>>(wv, wt, HDIM, 2048, 6144);
    gemm_mma<<<dim3(SQ/BM, QKVD/BN), 256, SMEM_MMA>>>(act, wt, qkv, QKVD, HDIM);
    rope_kernel<<<SQ * 24 * 128 / 256, 256>>>(qkv);
    attn_kernel<<<dim3(SQ/BQ, NH), 256, smem_attn>>>(qkv, act);
    convert_wt<<<dim3(HDIM/32, QD/32), wtb>>>(wo, wt, QD, HDIM, 0);
    gemm_mma<<<dim3(SQ/BM, HDIM/BN), 256, SMEM_MMA>>>(act, wt, proj, HDIM, QD);
    rmsnorm_kernel<<<SQ, 256>>>(proj, w_post_attn, hidden, x1);

    // ---- MLP block ----
    rmsnorm_h_kernel<<<SQ, 256>>>(x1, w_pre_ff, act);
    convert_wt<<<dim3(IDIM/32, HDIM/32), wtb>>>(w_gate, wt, HDIM, IDIM, 0);
    convert_wt<<<dim3(IDIM/32, HDIM/32), wtb>>>(w_up,   wt, HDIM, IDIM, IDIM);
    gemm_mma<<<dim3(SQ/BM, 2*IDIM/BN), 256, SMEM_MMA>>>(act, wt, gu, 2*IDIM, HDIM);
    swiglu_conv_kernel<<<SQ * (IDIM/2) / 256, 256>>>(gu, act);
    convert_wt<<<dim3(HDIM/32, IDIM/32), wtb>>>(w_down, wt, IDIM, HDIM, 0);
    gemm_mma<<<dim3(SQ/BM, HDIM/BN), 256, SMEM_MMA>>>(act, wt, down, HDIM, IDIM);
    rmsnorm_kernel<<<SQ, 256>>>(down, w_post_ff, x1, out);
}

// round 11
// speedup vs baseline: 2.1778x; 1.2275x over previous
#include <cuda_runtime.h>
#include <cuda_fp16.h>
#include <math.h>
#include <stdint.h>

#define SQ 2048
#define HDIM 3584
#define NH 16
#define NKV 8
#define HD 256
#define QKVD 8192           // 4096 q + 2048 k + 2048 v
#define QD 4096
#define IDIM 14336

// ---------------- scratch (allocation-free: __device__ globals) ----------------
static __device__ float g_qkv[SQ*QKVD];
static __device__ float g_proj[SQ*HDIM];
static __device__ float g_x1[SQ*HDIM];
static __device__ float g_gu[(size_t)SQ*2*IDIM];
static __device__ float g_down[SQ*HDIM];
static __device__ __half g_act[(size_t)SQ*IDIM];          // A fp16, up to [2048, 14336]
static __device__ __half g_wt[(size_t)(2*IDIM)*HDIM];     // B fp16 K-major, up to [28672, 3584]

// ---------------- PTX helpers (arch-agnostic only: sm_80-level) ----------------
__device__ __forceinline__ uint32_t smem_u32(const void* p) {
    uint32_t a;
    asm("{ .reg .u64 t; cvta.to.shared.u64 t, %1; cvt.u32.u64 %0, t; }" : "=r"(a) : "l"(p));
    return a;
}
__device__ __forceinline__ void ldx4(uint32_t& r0, uint32_t& r1, uint32_t& r2, uint32_t& r3, uint32_t a) {
    asm volatile("ldmatrix.sync.aligned.m8n8.x4.shared.b16 {%0,%1,%2,%3}, [%4];"
                 : "=r"(r0), "=r"(r1), "=r"(r2), "=r"(r3) : "r"(a));
}
__device__ __forceinline__ void hmma(float* c, uint32_t a0, uint32_t a1, uint32_t a2, uint32_t a3,
                                     uint32_t b0, uint32_t b1) {
    asm volatile("mma.sync.aligned.m16n8k16.row.col.f32.f16.f16.f32 "
                 "{%0,%1,%2,%3},{%4,%5,%6,%7},{%8,%9},{%0,%1,%2,%3};"
                 : "+f"(c[0]), "+f"(c[1]), "+f"(c[2]), "+f"(c[3])
                 : "r"(a0), "r"(a1), "r"(a2), "r"(a3), "r"(b0), "r"(b1));
}
#define CP_ASYNC16(dst, src) \
    asm volatile("cp.async.cg.shared.global [%0], [%1], 16;" :: "r"(dst), "l"(src))
#define CP_COMMIT() asm volatile("cp.async.commit_group;" ::: "memory")
#define CP_WAIT(n)  asm volatile("cp.async.wait_group %0;" :: "n"(n) : "memory")

// ============ HMMA fp16 GEMM: C[M,N] = A[M,K] @ B[N,K]^T, fp32 accumulate ============
#define BM 128
#define BN 128
#define BK 64
#define STG 3
#define ROWH 72
#define STAGE_A (BM*ROWH*2)
#define STAGE_B (STAGE_A + BN*ROWH*2)
#define SMEM_MMA (STG*STAGE_B)

__global__ void __launch_bounds__(256, 2)
gemm_mma(const __half* __restrict__ A, const __half* __restrict__ B,
         float* __restrict__ C, int N, int K) {
    extern __shared__ char smem[];
    uint32_t sbase = smem_u32(smem);
    int tid = threadIdx.x, lane = tid & 31, wid = tid >> 5;
    int m0 = blockIdx.x * BM, n0 = blockIdx.y * BN;
    int wm = (wid & 1) * 64, wn = (wid >> 1) * 32;
    int ntiles = K / BK;

    int lr = tid >> 3;
    int lc = (tid & 7) * 8;
    const __half* gA0 = A + (size_t)(m0 + lr) * K + lc;
    const __half* gB0 = B + (size_t)(n0 + lr) * K + lc;
    uint32_t sOff = (uint32_t)(lr * ROWH + lc) * 2;

    uint32_t foff = (uint32_t)(((lane & 15) * ROWH) + ((lane >> 4) * 8)) * 2;

    float acc[4][4][4];
#pragma unroll
    for (int a = 0; a < 4; a++)
#pragma unroll
        for (int b = 0; b < 4; b++)
#pragma unroll
            for (int c = 0; c < 4; c++) acc[a][b][c] = 0.f;

    auto LOAD = [&](int kt, int s) {
        int ak = kt * BK;
        uint32_t sA = sbase + s * STAGE_B;
        uint32_t sB = sA + STAGE_A;
#pragma unroll
        for (int h = 0; h < 4; h++) {
            CP_ASYNC16(sA + sOff + h * 32 * ROWH * 2, gA0 + (size_t)h * 32 * K + ak);
            CP_ASYNC16(sB + sOff + h * 32 * ROWH * 2, gB0 + (size_t)h * 32 * K + ak);
        }
    };

#pragma unroll
    for (int s = 0; s < STG - 1; s++) {
        LOAD(s, s);
        CP_COMMIT();
    }

    for (int i = 0; i < ntiles; i++) {
        CP_WAIT(STG - 2);
        __syncthreads();

        int pf = i + STG - 1;
        if (pf < ntiles) LOAD(pf, pf % STG);
        CP_COMMIT();

        int s = i % STG;
        uint32_t aB = sbase + s * STAGE_B;
        uint32_t bB = aB + STAGE_A;
        uint32_t aAddr = aB + (uint32_t)wm * ROWH * 2 + foff;
        uint32_t bAddr = bB + (uint32_t)wn * ROWH * 2 + foff;
#pragma unroll
        for (int ks = 0; ks < 4; ks++) {
            uint32_t af[4][4];
#pragma unroll
            for (int fm = 0; fm < 4; fm++)
                ldx4(af[fm][0], af[fm][1], af[fm][2], af[fm][3],
                     aAddr + (uint32_t)fm * 16 * ROWH * 2 + ks * 32);
            uint32_t t0, t1, t2, t3, t4, t5, t6, t7;
            ldx4(t0, t1, t2, t3, bAddr + ks * 32);
            ldx4(t4, t5, t6, t7, bAddr + 16 * ROWH * 2 + ks * 32);
            uint32_t b0[4] = {t0, t1, t4, t5};
            uint32_t b1[4] = {t2, t3, t6, t7};
#pragma unroll
            for (int fm = 0; fm < 4; fm++)
#pragma unroll
                for (int fn = 0; fn < 4; fn++)
                    hmma(acc[fm][fn], af[fm][0], af[fm][1], af[fm][2], af[fm][3],
                         b0[fn], b1[fn]);
        }
    }

#pragma unroll
    for (int fm = 0; fm < 4; fm++) {
        int r = m0 + wm + fm * 16 + (lane >> 2);
#pragma unroll
        for (int fn = 0; fn < 4; fn++) {
            int c = n0 + wn + fn * 8 + (lane & 3) * 2;
            *(float2*)&C[(size_t)r * N + c]       = make_float2(acc[fm][fn][0], acc[fm][fn][1]);
            *(float2*)&C[(size_t)(r + 8) * N + c] = make_float2(acc[fm][fn][2], acc[fm][fn][3]);
        }
    }
}

// W[K,N] fp32 -> out[n_off+n][k] fp16 K-major (transpose)
__global__ void convert_wt(const float* __restrict__ W, __half* __restrict__ out,
                           int K, int N, int n_off) {
    __shared__ float tile[32][33];
    int n0 = blockIdx.x * 32, k0 = blockIdx.y * 32;
    int tx = threadIdx.x, ty = threadIdx.y;   // 32 x 8
#pragma unroll
    for (int r = 0; r < 4; r++)
        tile[ty + r * 8][tx] = W[(size_t)(k0 + ty + r * 8) * N + n0 + tx];
    __syncthreads();
#pragma unroll
    for (int r = 0; r < 4; r++) {
        int n = ty + r * 8;
        out[(size_t)(n_off + n0 + n) * K + k0 + tx] = __float2half(tile[tx][n]);
    }
}

// ===== RMSNorm writing fp16 directly =====
__global__ void rmsnorm_h_kernel(const float* __restrict__ in, const float* __restrict__ w,
                                 __half* __restrict__ act) {
    int row = blockIdx.x;
    const float* x = in + (size_t)row * HDIM;
    float ss = 0.f;
    for (int c = threadIdx.x; c < HDIM; c += 256) { float v = x[c]; ss += v * v; }
    __shared__ float red[256];
    red[threadIdx.x] = ss;
    __syncthreads();
    for (int s = 128; s > 0; s >>= 1) {
        if (threadIdx.x < s) red[threadIdx.x] += red[threadIdx.x + s];
        __syncthreads();
    }
    float scale = rsqrtf(red[0] / (float)HDIM + 1e-6f);
    for (int c = threadIdx.x * 2; c < HDIM; c += 512) {
        float v0 = x[c] * scale * w[c];
        float v1 = x[c + 1] * scale * w[c + 1];
        *(__half2*)(act + (size_t)row * HDIM + c) =
            __halves2half2(__float2half(v0), __float2half(v1));
    }
}

// ================= RMSNorm fp32 out (+ residual) =================
__global__ void rmsnorm_kernel(const float* __restrict__ in, const float* __restrict__ w,
                               const float* __restrict__ resid, float* __restrict__ out) {
    int row = blockIdx.x;
    const float* x = in + (size_t)row * HDIM;
    float ss = 0.f;
    for (int c = threadIdx.x; c < HDIM; c += 256) { float v = x[c]; ss += v * v; }
    __shared__ float red[256];
    red[threadIdx.x] = ss;
    __syncthreads();
    for (int s = 128; s > 0; s >>= 1) {
        if (threadIdx.x < s) red[threadIdx.x] += red[threadIdx.x + s];
        __syncthreads();
    }
    float scale = rsqrtf(red[0] / (float)HDIM + 1e-6f);
    for (int c = threadIdx.x; c < HDIM; c += 256) {
        float v = x[c] * scale * w[c];
        if (resid) v += resid[(size_t)row * HDIM + c];
        out[(size_t)row * HDIM + c] = v;
    }
}

// ================= RoPE in-place on qkv [2048, 8192] =================
__global__ void rope_kernel(float* __restrict__ x) {
    int idx = blockIdx.x * 256 + threadIdx.x;   // over 2048*24*128
    int d = idx & 127;
    int hh = (idx >> 7) % 24;
    int s = idx / (128 * 24);
    float invf = (float)exp(-((double)(2 * d) / (double)HD) * log(10000.0));
    float ang = (float)s * invf;
    float c = (float)cos((double)ang);
    float si = (float)sin((double)ang);
    int col = (hh < 16) ? hh * 256 : 4096 + (hh - 16) * 256;
    size_t base = (size_t)s * QKVD + col;
    float x1 = x[base + d], x2 = x[base + d + 128];
    x[base + d]       = x1 * c - x2 * si;
    x[base + d + 128] = x2 * c + x1 * si;
}

// ====== HMMA flash attention: softcap + online softmax (FA2), causal; fp16 epilogue ======
// 8 warps: warp = (rg = wid&3: 16 q-rows) x (dh = wid>>2: 128 out-dims).
// Both d-halves compute scores redundantly -> P stays in registers.
#define AQROW 264          // 256 + 8 pad halves, 528B rows
#define AVROW 72           // 64 + 8 pad halves
#define SMEM_ATT ((64*AQROW*2 + 256*AVROW) * 2)   // 104448 bytes

__global__ void __launch_bounds__(256, 1)
attn_mma_kernel(const float* __restrict__ qkv, __half* __restrict__ act) {
    extern __shared__ __half hsm[];
    __half* Qs = hsm;                    // [64][AQROW] q rows, K-major
    __half* Ks = hsm + 64 * AQROW;       // [64][AQROW] kv rows, K-major
    __half* Vs = hsm + 128 * AQROW;      // [256][AVROW] d rows, kv cols (transposed)

    int qb = blockIdx.x, head = blockIdx.y, kvh = head >> 1;
    int t = threadIdx.x, lane = t & 31, wid = t >> 5;
    int rg = wid & 3, dh = wid >> 2;

    // Q tile load fp32 -> fp16
    for (int idx = t; idx < 64 * 64; idx += 256) {
        int i = idx >> 6, c = (idx & 63) * 4;
        float4 v = *(const float4*)&qkv[(size_t)(qb * 64 + i) * QKVD + head * HD + c];
        *(__half2*)&Qs[i * AQROW + c]     = __floats2half2_rn(v.x, v.y);
        *(__half2*)&Qs[i * AQROW + c + 2] = __floats2half2_rn(v.z, v.w);
    }

    float oacc[16][4];
#pragma unroll
    for (int i = 0; i < 16; i++)
#pragma unroll
        for (int e = 0; e < 4; e++) oacc[i][e] = 0.f;
    float sl0 = 0.f, sl1 = 0.f;
    float M0 = -1e30f, M1 = -1e30f;     // running row maxes

    uint32_t qAddr = smem_u32(Qs) + (uint32_t)((rg * 16 + (lane & 15)) * AQROW + (lane >> 4) * 8) * 2;
    uint32_t kBase = smem_u32(Ks) + (uint32_t)((lane & 15) * AQROW + (lane >> 4) * 8) * 2;
    uint32_t vBase = smem_u32(Vs) + (uint32_t)((dh * 128 + (lane & 15)) * AVROW + (lane >> 4) * 8) * 2;

    int lrow = rg * 16 + (lane >> 2);    // local q row of c0/c1 (c2/c3: +8)

    for (int kb = 0; kb <= qb; kb++) {
        __syncthreads();
        // K tile (K-major) + V tile (transposed) fp32 -> fp16
        for (int idx = t; idx < 64 * 64; idx += 256) {
            int j = idx >> 6, c = (idx & 63) * 4;
            size_t gb = (size_t)(kb * 64 + j) * QKVD + kvh * HD + c;
            float4 kv = *(const float4*)&qkv[gb + 4096];
            *(__half2*)&Ks[j * AQROW + c]     = __floats2half2_rn(kv.x, kv.y);
            *(__half2*)&Ks[j * AQROW + c + 2] = __floats2half2_rn(kv.z, kv.w);
            float4 vv = *(const float4*)&qkv[gb + 6144];
            Vs[(c + 0) * AVROW + j] = __float2half(vv.x);
            Vs[(c + 1) * AVROW + j] = __float2half(vv.y);
            Vs[(c + 2) * AVROW + j] = __float2half(vv.z);
            Vs[(c + 3) * AVROW + j] = __float2half(vv.w);
        }
        __syncthreads();

        // QK^T: S[16, 64]
        float sacc[8][4];
#pragma unroll
        for (int i = 0; i < 8; i++)
#pragma unroll
            for (int e = 0; e < 4; e++) sacc[i][e] = 0.f;
#pragma unroll
        for (int ks = 0; ks < 16; ks++) {
            uint32_t a0, a1, a2, a3;
            ldx4(a0, a1, a2, a3, qAddr + ks * 32);
#pragma unroll
            for (int jt = 0; jt < 4; jt++) {
                uint32_t t0, t1, t2, t3;
                ldx4(t0, t1, t2, t3, kBase + (uint32_t)jt * 16 * AQROW * 2 + ks * 32);
                hmma(sacc[jt * 2],     a0, a1, a2, a3, t0, t2);
                hmma(sacc[jt * 2 + 1], a0, a1, a2, a3, t1, t3);
            }
        }

        // softcap + causal mask -> masked capped scores
        bool diag = (kb == qb);
#pragma unroll
        for (int tt = 0; tt < 8; tt++) {
            int colb = tt * 8 + (lane & 3) * 2;
#pragma unroll
            for (int e = 0; e < 4; e++) {
                float sc = sacc[tt][e] * 0.0625f;
                sc = tanhf(sc * 0.02f) * 50.f;
                bool valid = !diag || (colb + (e & 1) <= lrow + (e >> 1) * 8);
                sacc[tt][e] = valid ? sc : -1e30f;
            }
        }

        // online max update (per row-half), rescale state
        float m0 = -1e30f, m1 = -1e30f;
#pragma unroll
        for (int tt = 0; tt < 8; tt++) {
            m0 = fmaxf(m0, fmaxf(sacc[tt][0], sacc[tt][1]));
            m1 = fmaxf(m1, fmaxf(sacc[tt][2], sacc[tt][3]));
        }
        m0 = fmaxf(m0, __shfl_xor_sync(0xFFFFFFFF, m0, 1));
        m0 = fmaxf(m0, __shfl_xor_sync(0xFFFFFFFF, m0, 2));
        m1 = fmaxf(m1, __shfl_xor_sync(0xFFFFFFFF, m1, 1));
        m1 = fmaxf(m1, __shfl_xor_sync(0xFFFFFFFF, m1, 2));
        float nM0 = fmaxf(M0, m0), nM1 = fmaxf(M1, m1);
        float f0 = __expf(M0 - nM0), f1 = __expf(M1 - nM1);
        M0 = nM0; M1 = nM1;
        sl0 *= f0; sl1 *= f1;
#pragma unroll
        for (int i = 0; i < 16; i++) {
            oacc[i][0] *= f0; oacc[i][1] *= f0;
            oacc[i][2] *= f1; oacc[i][3] *= f1;
        }

        // p = exp(sc - M) in [0,1] -> fp16 fragments; lsum from rounded p
        uint32_t pf[4][4];
#pragma unroll
        for (int tt = 0; tt < 8; tt++) {
            __half2 h01 = __floats2half2_rn(__expf(sacc[tt][0] - M0), __expf(sacc[tt][1] - M0));
            __half2 h23 = __floats2half2_rn(__expf(sacc[tt][2] - M1), __expf(sacc[tt][3] - M1));
            pf[tt >> 1][(tt & 1) * 2]     = *(uint32_t*)&h01;
            pf[tt >> 1][(tt & 1) * 2 + 1] = *(uint32_t*)&h23;
            float2 f01 = __half22float2(h01), f23 = __half22float2(h23);
            sl0 += f01.x + f01.y;
            sl1 += f23.x + f23.y;
        }

        // PV: O[16, 128] += P[16, 64] @ V[64, 128(dh)]
#pragma unroll
        for (int s = 0; s < 4; s++) {
#pragma unroll
            for (int i = 0; i < 8; i++) {
                uint32_t t0, t1, t2, t3;
                ldx4(t0, t1, t2, t3, vBase + (uint32_t)i * 16 * AVROW * 2 + s * 32);
                hmma(oacc[i * 2],     pf[s][0], pf[s][1], pf[s][2], pf[s][3], t0, t2);
                hmma(oacc[i * 2 + 1], pf[s][0], pf[s][1], pf[s][2], pf[s][3], t1, t3);
            }
        }
    }

    // row sums: reduce over the 4 lanes sharing a row
    sl0 += __shfl_xor_sync(0xFFFFFFFF, sl0, 1);
    sl0 += __shfl_xor_sync(0xFFFFFFFF, sl0, 2);
    sl1 += __shfl_xor_sync(0xFFFFFFFF, sl1, 1);
    sl1 += __shfl_xor_sync(0xFFFFFFFF, sl1, 2);
    float inv0 = 1.f / sl0, inv1 = 1.f / sl1;

    int grow = qb * 64 + lrow;
#pragma unroll
    for (int i = 0; i < 16; i++) {
        int gcol = head * HD + dh * 128 + i * 8 + (lane & 3) * 2;
        *(__half2*)&act[(size_t)grow * QD + gcol] =
            __floats2half2_rn(oacc[i][0] * inv0, oacc[i][1] * inv0);
        *(__half2*)&act[(size_t)(grow + 8) * QD + gcol] =
            __floats2half2_rn(oacc[i][2] * inv1, oacc[i][3] * inv1);
    }
}

// ===== SwiGLU fused with fp16 convert =====
__global__ void swiglu_conv_kernel(const float* __restrict__ gu, __half* __restrict__ dst) {
    int idx = blockIdx.x * 256 + threadIdx.x;
    int m = idx / (IDIM / 2), c = (idx - m * (IDIM / 2)) * 2;
    const float* row = gu + (size_t)m * 2 * IDIM;
    float2 g = *(const float2*)(row + c);
    float2 u = *(const float2*)(row + IDIM + c);
    float t0 = tanhf(0.7978845608028654f * (g.x + 0.044715f * g.x * g.x * g.x));
    float t1 = tanhf(0.7978845608028654f * (g.y + 0.044715f * g.y * g.y * g.y));
    float v0 = 0.5f * g.x * (1.f + t0) * u.x;
    float v1 = 0.5f * g.y * (1.f + t1) * u.y;
    *(__half2*)(dst + (size_t)m * IDIM + c) =
        __halves2half2(__float2half(v0), __float2half(v1));
}

extern "C" void kernel_launch(void* const* d_in, const int* in_sizes, int n_in,
                              void* d_out, int out_size) {
    const float* hidden      = (const float*)d_in[0];
    const float* w_in        = (const float*)d_in[3];
    const float* w_post_attn = (const float*)d_in[4];
    const float* w_pre_ff    = (const float*)d_in[5];
    const float* w_post_ff   = (const float*)d_in[6];
    const float* wq          = (const float*)d_in[7];
    const float* wk          = (const float*)d_in[8];
    const float* wv          = (const float*)d_in[9];
    const float* wo          = (const float*)d_in[10];
    const float* w_gate      = (const float*)d_in[11];
    const float* w_up        = (const float*)d_in[12];
    const float* w_down      = (const float*)d_in[13];
    float* out = (float*)d_out;

    float *qkv, *proj, *x1, *gu, *down;
    __half *act, *wt;
    cudaGetSymbolAddress((void**)&qkv, g_qkv);
    cudaGetSymbolAddress((void**)&proj, g_proj);
    cudaGetSymbolAddress((void**)&x1, g_x1);
    cudaGetSymbolAddress((void**)&gu, g_gu);
    cudaGetSymbolAddress((void**)&down, g_down);
    cudaGetSymbolAddress((void**)&act, g_act);
    cudaGetSymbolAddress((void**)&wt, g_wt);

    cudaFuncSetAttribute(gemm_mma, cudaFuncAttributeMaxDynamicSharedMemorySize, SMEM_MMA);
    cudaFuncSetAttribute(attn_mma_kernel, cudaFuncAttributeMaxDynamicSharedMemorySize, SMEM_ATT);

    dim3 wtb(32, 8);

    // ---- attention block ----
    rmsnorm_h_kernel<<<SQ, 256>>>(hidden, w_in, act);
    convert_wt<<<dim3(QD/32,   HDIM/32), wtb>>>(wq, wt, HDIM, QD,   0);
    convert_wt<<<dim3(2048/32, HDIM/32), wtb>>>(wk, wt, HDIM, 2048, 4096);
    convert_wt<<<dim3(2048/32, HDIM/32), wtb>>>(wv, wt, HDIM, 2048, 6144);
    gemm_mma<<<dim3(SQ/BM, QKVD/BN), 256, SMEM_MMA>>>(act, wt, qkv, QKVD, HDIM);
    rope_kernel<<<SQ * 24 * 128 / 256, 256>>>(qkv);
    attn_mma_kernel<<<dim3(SQ/64, NH), 256, SMEM_ATT>>>(qkv, act);
    convert_wt<<<dim3(HDIM/32, QD/32), wtb>>>(wo, wt, QD, HDIM, 0);
    gemm_mma<<<dim3(SQ/BM, HDIM/BN), 256, SMEM_MMA>>>(act, wt, proj, HDIM, QD);
    rmsnorm_kernel<<<SQ, 256>>>(proj, w_post_attn, hidden, x1);

    // ---- MLP block ----
    rmsnorm_h_kernel<<<SQ, 256>>>(x1, w_pre_ff, act);
    convert_wt<<<dim3(IDIM/32, HDIM/32), wtb>>>(w_gate, wt, HDIM, IDIM, 0);
    convert_wt<<<dim3(IDIM/32, HDIM/32), wtb>>>(w_up,   wt, HDIM, IDIM, IDIM);
    gemm_mma<<<dim3(SQ/BM, 2*IDIM/BN), 256, SMEM_MMA>>>(act, wt, gu, 2*IDIM, HDIM);
    swiglu_conv_kernel<<<SQ * (IDIM/2) / 256, 256>>>(gu, act);
    convert_wt<<<dim3(HDIM/32, IDIM/32), wtb>>>(w_down, wt, IDIM, HDIM, 0);
    gemm_mma<<<dim3(SQ/BM, HDIM/BN), 256, SMEM_MMA>>>(act, wt, down, HDIM, IDIM);
    rmsnorm_kernel<<<SQ, 256>>>(down, w_post_ff, x1, out);
}

// round 12
// speedup vs baseline: 2.1996x; 1.0100x over previous
#include <cuda_runtime.h>
#include <cuda_fp16.h>
#include <math.h>
#include <stdint.h>

#define SQ 2048
#define HDIM 3584
#define NH 16
#define NKV 8
#define HD 256
#define QKVD 8192           // 4096 q + 2048 k + 2048 v
#define QD 4096
#define IDIM 14336

// ---------------- scratch (allocation-free: __device__ globals) ----------------
static __device__ float g_qkv[SQ*QKVD];
static __device__ float g_proj[SQ*HDIM];
static __device__ float g_x1[SQ*HDIM];
static __device__ float g_down[SQ*HDIM];
static __device__ __half g_act[(size_t)SQ*IDIM];          // GEMM A operand
static __device__ __half g_act2[(size_t)SQ*IDIM];         // swiglu output (down-GEMM A)
static __device__ __half g_wt[(size_t)(2*IDIM)*HDIM];     // B fp16 K-major

// ---------------- PTX helpers (arch-agnostic only: sm_80-level) ----------------
__device__ __forceinline__ uint32_t smem_u32(const void* p) {
    uint32_t a;
    asm("{ .reg .u64 t; cvta.to.shared.u64 t, %1; cvt.u32.u64 %0, t; }" : "=r"(a) : "l"(p));
    return a;
}
__device__ __forceinline__ void ldx4(uint32_t& r0, uint32_t& r1, uint32_t& r2, uint32_t& r3, uint32_t a) {
    asm volatile("ldmatrix.sync.aligned.m8n8.x4.shared.b16 {%0,%1,%2,%3}, [%4];"
                 : "=r"(r0), "=r"(r1), "=r"(r2), "=r"(r3) : "r"(a));
}
__device__ __forceinline__ void hmma(float* c, uint32_t a0, uint32_t a1, uint32_t a2, uint32_t a3,
                                     uint32_t b0, uint32_t b1) {
    asm volatile("mma.sync.aligned.m16n8k16.row.col.f32.f16.f16.f32 "
                 "{%0,%1,%2,%3},{%4,%5,%6,%7},{%8,%9},{%0,%1,%2,%3};"
                 : "+f"(c[0]), "+f"(c[1]), "+f"(c[2]), "+f"(c[3])
                 : "r"(a0), "r"(a1), "r"(a2), "r"(a3), "r"(b0), "r"(b1));
}
#define CP_ASYNC16(dst, src) \
    asm volatile("cp.async.cg.shared.global [%0], [%1], 16;" :: "r"(dst), "l"(src))
#define CP_COMMIT() asm volatile("cp.async.commit_group;" ::: "memory")
#define CP_WAIT(n)  asm volatile("cp.async.wait_group %0;" :: "n"(n) : "memory")

// ============ HMMA fp16 GEMM: C[M,N] = A[M,K] @ B[N,K]^T, fp32 accumulate ============
#define BM 128
#define BN 128
#define BK 64
#define STG 3
#define ROWH 72
#define STAGE_A (BM*ROWH*2)
#define STAGE_B (STAGE_A + BN*ROWH*2)
#define SMEM_MMA (STG*STAGE_B)

// Shared mainloop body via macro-free duplication: plain GEMM writes fp32 C;
// swiglu variant stages tile in smem and writes gelu(gate)*up as fp16.

__global__ void __launch_bounds__(256, 2)
gemm_mma(const __half* __restrict__ A, const __half* __restrict__ B,
         float* __restrict__ C, int N, int K) {
    extern __shared__ char smem[];
    uint32_t sbase = smem_u32(smem);
    int tid = threadIdx.x, lane = tid & 31, wid = tid >> 5;
    int m0 = blockIdx.x * BM, n0 = blockIdx.y * BN;
    int wm = (wid & 1) * 64, wn = (wid >> 1) * 32;
    int ntiles = K / BK;

    int lr = tid >> 3;
    int lc = (tid & 7) * 8;
    const __half* gA0 = A + (size_t)(m0 + lr) * K + lc;
    const __half* gB0 = B + (size_t)(n0 + lr) * K + lc;
    uint32_t sOff = (uint32_t)(lr * ROWH + lc) * 2;

    uint32_t foff = (uint32_t)(((lane & 15) * ROWH) + ((lane >> 4) * 8)) * 2;

    float acc[4][4][4];
#pragma unroll
    for (int a = 0; a < 4; a++)
#pragma unroll
        for (int b = 0; b < 4; b++)
#pragma unroll
            for (int c = 0; c < 4; c++) acc[a][b][c] = 0.f;

    auto LOAD = [&](int kt, int s) {
        int ak = kt * BK;
        uint32_t sA = sbase + s * STAGE_B;
        uint32_t sB = sA + STAGE_A;
#pragma unroll
        for (int h = 0; h < 4; h++) {
            CP_ASYNC16(sA + sOff + h * 32 * ROWH * 2, gA0 + (size_t)h * 32 * K + ak);
            CP_ASYNC16(sB + sOff + h * 32 * ROWH * 2, gB0 + (size_t)h * 32 * K + ak);
        }
    };

#pragma unroll
    for (int s = 0; s < STG - 1; s++) {
        LOAD(s, s);
        CP_COMMIT();
    }

    for (int i = 0; i < ntiles; i++) {
        CP_WAIT(STG - 2);
        __syncthreads();

        int pf = i + STG - 1;
        if (pf < ntiles) LOAD(pf, pf % STG);
        CP_COMMIT();

        int s = i % STG;
        uint32_t aB = sbase + s * STAGE_B;
        uint32_t bB = aB + STAGE_A;
        uint32_t aAddr = aB + (uint32_t)wm * ROWH * 2 + foff;
        uint32_t bAddr = bB + (uint32_t)wn * ROWH * 2 + foff;
#pragma unroll
        for (int ks = 0; ks < 4; ks++) {
            uint32_t af[4][4];
#pragma unroll
            for (int fm = 0; fm < 4; fm++)
                ldx4(af[fm][0], af[fm][1], af[fm][2], af[fm][3],
                     aAddr + (uint32_t)fm * 16 * ROWH * 2 + ks * 32);
            uint32_t t0, t1, t2, t3, t4, t5, t6, t7;
            ldx4(t0, t1, t2, t3, bAddr + ks * 32);
            ldx4(t4, t5, t6, t7, bAddr + 16 * ROWH * 2 + ks * 32);
            uint32_t b0[4] = {t0, t1, t4, t5};
            uint32_t b1[4] = {t2, t3, t6, t7};
#pragma unroll
            for (int fm = 0; fm < 4; fm++)
#pragma unroll
                for (int fn = 0; fn < 4; fn++)
                    hmma(acc[fm][fn], af[fm][0], af[fm][1], af[fm][2], af[fm][3],
                         b0[fn], b1[fn]);
        }
    }

#pragma unroll
    for (int fm = 0; fm < 4; fm++) {
        int r = m0 + wm + fm * 16 + (lane >> 2);
#pragma unroll
        for (int fn = 0; fn < 4; fn++) {
            int c = n0 + wn + fn * 8 + (lane & 3) * 2;
            *(float2*)&C[(size_t)r * N + c]       = make_float2(acc[fm][fn][0], acc[fm][fn][1]);
            *(float2*)&C[(size_t)(r + 8) * N + c] = make_float2(acc[fm][fn][2], acc[fm][fn][3]);
        }
    }
}

// ==== gate/up GEMM with fused SwiGLU epilogue. B rows interleaved per 128-block:
// [gate 64g..64g+63 | up 64g..64g+63]. Writes fp16 act2[2048, IDIM]. ====
__global__ void __launch_bounds__(256, 2)
gemm_swiglu(const __half* __restrict__ A, const __half* __restrict__ B,
            __half* __restrict__ O, int K) {
    extern __shared__ char smem[];
    uint32_t sbase = smem_u32(smem);
    int tid = threadIdx.x, lane = tid & 31, wid = tid >> 5;
    int m0 = blockIdx.x * BM, n0 = blockIdx.y * BN;
    int wm = (wid & 1) * 64, wn = (wid >> 1) * 32;
    int ntiles = K / BK;

    int lr = tid >> 3;
    int lc = (tid & 7) * 8;
    const __half* gA0 = A + (size_t)(m0 + lr) * K + lc;
    const __half* gB0 = B + (size_t)(n0 + lr) * K + lc;
    uint32_t sOff = (uint32_t)(lr * ROWH + lc) * 2;
    uint32_t foff = (uint32_t)(((lane & 15) * ROWH) + ((lane >> 4) * 8)) * 2;

    float acc[4][4][4];
#pragma unroll
    for (int a = 0; a < 4; a++)
#pragma unroll
        for (int b = 0; b < 4; b++)
#pragma unroll
            for (int c = 0; c < 4; c++) acc[a][b][c] = 0.f;

    auto LOAD = [&](int kt, int s) {
        int ak = kt * BK;
        uint32_t sA = sbase + s * STAGE_B;
        uint32_t sB = sA + STAGE_A;
#pragma unroll
        for (int h = 0; h < 4; h++) {
            CP_ASYNC16(sA + sOff + h * 32 * ROWH * 2, gA0 + (size_t)h * 32 * K + ak);
            CP_ASYNC16(sB + sOff + h * 32 * ROWH * 2, gB0 + (size_t)h * 32 * K + ak);
        }
    };

#pragma unroll
    for (int s = 0; s < STG - 1; s++) {
        LOAD(s, s);
        CP_COMMIT();
    }

    for (int i = 0; i < ntiles; i++) {
        CP_WAIT(STG - 2);
        __syncthreads();
        int pf = i + STG - 1;
        if (pf < ntiles) LOAD(pf, pf % STG);
        CP_COMMIT();
        int s = i % STG;
        uint32_t aB = sbase + s * STAGE_B;
        uint32_t bB = aB + STAGE_A;
        uint32_t aAddr = aB + (uint32_t)wm * ROWH * 2 + foff;
        uint32_t bAddr = bB + (uint32_t)wn * ROWH * 2 + foff;
#pragma unroll
        for (int ks = 0; ks < 4; ks++) {
            uint32_t af[4][4];
#pragma unroll
            for (int fm = 0; fm < 4; fm++)
                ldx4(af[fm][0], af[fm][1], af[fm][2], af[fm][3],
                     aAddr + (uint32_t)fm * 16 * ROWH * 2 + ks * 32);
            uint32_t t0, t1, t2, t3, t4, t5, t6, t7;
            ldx4(t0, t1, t2, t3, bAddr + ks * 32);
            ldx4(t4, t5, t6, t7, bAddr + 16 * ROWH * 2 + ks * 32);
            uint32_t b0[4] = {t0, t1, t4, t5};
            uint32_t b1[4] = {t2, t3, t6, t7};
#pragma unroll
            for (int fm = 0; fm < 4; fm++)
#pragma unroll
                for (int fn = 0; fn < 4; fn++)
                    hmma(acc[fm][fn], af[fm][0], af[fm][1], af[fm][2], af[fm][3],
                         b0[fn], b1[fn]);
        }
    }

    // --- fused SwiGLU epilogue: stage C tile (fp32) into freed pipeline smem ---
    __syncthreads();                       // all warps done reading stages
    float* Cs = (float*)smem;              // [128][132]
#pragma unroll
    for (int fm = 0; fm < 4; fm++) {
        int r = wm + fm * 16 + (lane >> 2);
#pragma unroll
        for (int fn = 0; fn < 4; fn++) {
            int c = wn + fn * 8 + (lane & 3) * 2;
            *(float2*)&Cs[r * 132 + c]       = make_float2(acc[fm][fn][0], acc[fm][fn][1]);
            *(float2*)&Cs[(r + 8) * 132 + c] = make_float2(acc[fm][fn][2], acc[fm][fn][3]);
        }
    }
    __syncthreads();
    int colb = blockIdx.y * 64;            // gate-column block in act2
    for (int idx = tid; idx < 128 * 32; idx += 256) {
        int r = idx >> 5, c = (idx & 31) * 2;
        float2 g = *(float2*)&Cs[r * 132 + c];
        float2 u = *(float2*)&Cs[r * 132 + 64 + c];
        float t0 = tanhf(0.7978845608028654f * (g.x + 0.044715f * g.x * g.x * g.x));
        float t1 = tanhf(0.7978845608028654f * (g.y + 0.044715f * g.y * g.y * g.y));
        float v0 = 0.5f * g.x * (1.f + t0) * u.x;
        float v1 = 0.5f * g.y * (1.f + t1) * u.y;
        *(__half2*)&O[(size_t)(m0 + r) * IDIM + colb + c] =
            __halves2half2(__float2half(v0), __float2half(v1));
    }
}

// W[K,N] fp32 -> out[n_off+n][k] fp16 K-major (transpose)
__global__ void convert_wt(const float* __restrict__ W, __half* __restrict__ out,
                           int K, int N, int n_off) {
    __shared__ float tile[32][33];
    int n0 = blockIdx.x * 32, k0 = blockIdx.y * 32;
    int tx = threadIdx.x, ty = threadIdx.y;   // 32 x 8
#pragma unroll
    for (int r = 0; r < 4; r++)
        tile[ty + r * 8][tx] = W[(size_t)(k0 + ty + r * 8) * N + n0 + tx];
    __syncthreads();
#pragma unroll
    for (int r = 0; r < 4; r++) {
        int n = ty + r * 8;
        out[(size_t)(n_off + n0 + n) * K + k0 + tx] = __float2half(tile[tx][n]);
    }
}

// gate/up interleaved convert: row -> (n/64)*128 + which*64 + (n%64)
__global__ void convert_wt_swi(const float* __restrict__ W, __half* __restrict__ out,
                               int K, int N, int which) {
    __shared__ float tile[32][33];
    int n0 = blockIdx.x * 32, k0 = blockIdx.y * 32;
    int tx = threadIdx.x, ty = threadIdx.y;   // 32 x 8
#pragma unroll
    for (int r = 0; r < 4; r++)
        tile[ty + r * 8][tx] = W[(size_t)(k0 + ty + r * 8) * N + n0 + tx];
    __syncthreads();
#pragma unroll
    for (int r = 0; r < 4; r++) {
        int n = ty + r * 8;
        int ng = n0 + n;
        size_t rowg = (size_t)((ng >> 6) * 128 + which * 64 + (ng & 63));
        out[rowg * K + k0 + tx] = __float2half(tile[tx][n]);
    }
}

// ===== RMSNorm writing fp16 directly =====
__global__ void rmsnorm_h_kernel(const float* __restrict__ in, const float* __restrict__ w,
                                 __half* __restrict__ act) {
    int row = blockIdx.x;
    const float* x = in + (size_t)row * HDIM;
    float ss = 0.f;
    for (int c = threadIdx.x; c < HDIM; c += 256) { float v = x[c]; ss += v * v; }
    __shared__ float red[256];
    red[threadIdx.x] = ss;
    __syncthreads();
    for (int s = 128; s > 0; s >>= 1) {
        if (threadIdx.x < s) red[threadIdx.x] += red[threadIdx.x + s];
        __syncthreads();
    }
    float scale = rsqrtf(red[0] / (float)HDIM + 1e-6f);
    for (int c = threadIdx.x * 2; c < HDIM; c += 512) {
        float v0 = x[c] * scale * w[c];
        float v1 = x[c + 1] * scale * w[c + 1];
        *(__half2*)(act + (size_t)row * HDIM + c) =
            __halves2half2(__float2half(v0), __float2half(v1));
    }
}

// ================= RMSNorm fp32 out (+ residual) =================
__global__ void rmsnorm_kernel(const float* __restrict__ in, const float* __restrict__ w,
                               const float* __restrict__ resid, float* __restrict__ out) {
    int row = blockIdx.x;
    const float* x = in + (size_t)row * HDIM;
    float ss = 0.f;
    for (int c = threadIdx.x; c < HDIM; c += 256) { float v = x[c]; ss += v * v; }
    __shared__ float red[256];
    red[threadIdx.x] = ss;
    __syncthreads();
    for (int s = 128; s > 0; s >>= 1) {
        if (threadIdx.x < s) red[threadIdx.x] += red[threadIdx.x + s];
        __syncthreads();
    }
    float scale = rsqrtf(red[0] / (float)HDIM + 1e-6f);
    for (int c = threadIdx.x; c < HDIM; c += 256) {
        float v = x[c] * scale * w[c];
        if (resid) v += resid[(size_t)row * HDIM + c];
        out[(size_t)row * HDIM + c] = v;
    }
}

// ================= RoPE in-place on qkv [2048, 8192] =================
__global__ void rope_kernel(float* __restrict__ x) {
    int idx = blockIdx.x * 256 + threadIdx.x;   // over 2048*24*128
    int d = idx & 127;
    int hh = (idx >> 7) % 24;
    int s = idx / (128 * 24);
    float invf = (float)exp(-((double)(2 * d) / (double)HD) * log(10000.0));
    float ang = (float)s * invf;
    float c = (float)cos((double)ang);
    float si = (float)sin((double)ang);
    int col = (hh < 16) ? hh * 256 : 4096 + (hh - 16) * 256;
    size_t base = (size_t)s * QKVD + col;
    float x1 = x[base + d], x2 = x[base + d + 128];
    x[base + d]       = x1 * c - x2 * si;
    x[base + d + 128] = x2 * c + x1 * si;
}

// ====== HMMA flash attention: softcap + online softmax (FA2), causal; fp16 epilogue ======
#define AQROW 264
#define AVROW 72
#define SMEM_ATT ((64*AQROW*2 + 256*AVROW) * 2)   // 104448 bytes

__global__ void __launch_bounds__(256, 1)
attn_mma_kernel(const float* __restrict__ qkv, __half* __restrict__ act) {
    extern __shared__ __half hsm[];
    __half* Qs = hsm;
    __half* Ks = hsm + 64 * AQROW;
    __half* Vs = hsm + 128 * AQROW;

    int qb = blockIdx.x, head = blockIdx.y, kvh = head >> 1;
    int t = threadIdx.x, lane = t & 31, wid = t >> 5;
    int rg = wid & 3, dh = wid >> 2;

    for (int idx = t; idx < 64 * 64; idx += 256) {
        int i = idx >> 6, c = (idx & 63) * 4;
        float4 v = *(const float4*)&qkv[(size_t)(qb * 64 + i) * QKVD + head * HD + c];
        *(__half2*)&Qs[i * AQROW + c]     = __floats2half2_rn(v.x, v.y);
        *(__half2*)&Qs[i * AQROW + c + 2] = __floats2half2_rn(v.z, v.w);
    }

    float oacc[16][4];
#pragma unroll
    for (int i = 0; i < 16; i++)
#pragma unroll
        for (int e = 0; e < 4; e++) oacc[i][e] = 0.f;
    float sl0 = 0.f, sl1 = 0.f;
    float M0 = -1e30f, M1 = -1e30f;

    uint32_t qAddr = smem_u32(Qs) + (uint32_t)((rg * 16 + (lane & 15)) * AQROW + (lane >> 4) * 8) * 2;
    uint32_t kBase = smem_u32(Ks) + (uint32_t)((lane & 15) * AQROW + (lane >> 4) * 8) * 2;
    uint32_t vBase = smem_u32(Vs) + (uint32_t)((dh * 128 + (lane & 15)) * AVROW + (lane >> 4) * 8) * 2;

    int lrow = rg * 16 + (lane >> 2);

    for (int kb = 0; kb <= qb; kb++) {
        __syncthreads();
        for (int idx = t; idx < 64 * 64; idx += 256) {
            int j = idx >> 6, c = (idx & 63) * 4;
            size_t gb = (size_t)(kb * 64 + j) * QKVD + kvh * HD + c;
            float4 kv = *(const float4*)&qkv[gb + 4096];
            *(__half2*)&Ks[j * AQROW + c]     = __floats2half2_rn(kv.x, kv.y);
            *(__half2*)&Ks[j * AQROW + c + 2] = __floats2half2_rn(kv.z, kv.w);
            float4 vv = *(const float4*)&qkv[gb + 6144];
            Vs[(c + 0) * AVROW + j] = __float2half(vv.x);
            Vs[(c + 1) * AVROW + j] = __float2half(vv.y);
            Vs[(c + 2) * AVROW + j] = __float2half(vv.z);
            Vs[(c + 3) * AVROW + j] = __float2half(vv.w);
        }
        __syncthreads();

        float sacc[8][4];
#pragma unroll
        for (int i = 0; i < 8; i++)
#pragma unroll
            for (int e = 0; e < 4; e++) sacc[i][e] = 0.f;
#pragma unroll
        for (int ks = 0; ks < 16; ks++) {
            uint32_t a0, a1, a2, a3;
            ldx4(a0, a1, a2, a3, qAddr + ks * 32);
#pragma unroll
            for (int jt = 0; jt < 4; jt++) {
                uint32_t t0, t1, t2, t3;
                ldx4(t0, t1, t2, t3, kBase + (uint32_t)jt * 16 * AQROW * 2 + ks * 32);
                hmma(sacc[jt * 2],     a0, a1, a2, a3, t0, t2);
                hmma(sacc[jt * 2 + 1], a0, a1, a2, a3, t1, t3);
            }
        }

        bool diag = (kb == qb);
#pragma unroll
        for (int tt = 0; tt < 8; tt++) {
            int colb = tt * 8 + (lane & 3) * 2;
#pragma unroll
            for (int e = 0; e < 4; e++) {
                float sc = sacc[tt][e] * 0.0625f;
                sc = tanhf(sc * 0.02f) * 50.f;
                bool valid = !diag || (colb + (e & 1) <= lrow + (e >> 1) * 8);
                sacc[tt][e] = valid ? sc : -1e30f;
            }
        }

        float m0 = -1e30f, m1 = -1e30f;
#pragma unroll
        for (int tt = 0; tt < 8; tt++) {
            m0 = fmaxf(m0, fmaxf(sacc[tt][0], sacc[tt][1]));
            m1 = fmaxf(m1, fmaxf(sacc[tt][2], sacc[tt][3]));
        }
        m0 = fmaxf(m0, __shfl_xor_sync(0xFFFFFFFF, m0, 1));
        m0 = fmaxf(m0, __shfl_xor_sync(0xFFFFFFFF, m0, 2));
        m1 = fmaxf(m1, __shfl_xor_sync(0xFFFFFFFF, m1, 1));
        m1 = fmaxf(m1, __shfl_xor_sync(0xFFFFFFFF, m1, 2));
        float nM0 = fmaxf(M0, m0), nM1 = fmaxf(M1, m1);
        float f0 = __expf(M0 - nM0), f1 = __expf(M1 - nM1);
        M0 = nM0; M1 = nM1;
        sl0 *= f0; sl1 *= f1;
#pragma unroll
        for (int i = 0; i < 16; i++) {
            oacc[i][0] *= f0; oacc[i][1] *= f0;
            oacc[i][2] *= f1; oacc[i][3] *= f1;
        }

        uint32_t pf[4][4];
#pragma unroll
        for (int tt = 0; tt < 8; tt++) {
            __half2 h01 = __floats2half2_rn(__expf(sacc[tt][0] - M0), __expf(sacc[tt][1] - M0));
            __half2 h23 = __floats2half2_rn(__expf(sacc[tt][2] - M1), __expf(sacc[tt][3] - M1));
            pf[tt >> 1][(tt & 1) * 2]     = *(uint32_t*)&h01;
            pf[tt >> 1][(tt & 1) * 2 + 1] = *(uint32_t*)&h23;
            float2 f01 = __half22float2(h01), f23 = __half22float2(h23);
            sl0 += f01.x + f01.y;
            sl1 += f23.x + f23.y;
        }

#pragma unroll
        for (int s = 0; s < 4; s++) {
#pragma unroll
            for (int i = 0; i < 8; i++) {
                uint32_t t0, t1, t2, t3;
                ldx4(t0, t1, t2, t3, vBase + (uint32_t)i * 16 * AVROW * 2 + s * 32);
                hmma(oacc[i * 2],     pf[s][0], pf[s][1], pf[s][2], pf[s][3], t0, t2);
                hmma(oacc[i * 2 + 1], pf[s][0], pf[s][1], pf[s][2], pf[s][3], t1, t3);
            }
        }
    }

    sl0 += __shfl_xor_sync(0xFFFFFFFF, sl0, 1);
    sl0 += __shfl_xor_sync(0xFFFFFFFF, sl0, 2);
    sl1 += __shfl_xor_sync(0xFFFFFFFF, sl1, 1);
    sl1 += __shfl_xor_sync(0xFFFFFFFF, sl1, 2);
    float inv0 = 1.f / sl0, inv1 = 1.f / sl1;

    int grow = qb * 64 + lrow;
#pragma unroll
    for (int i = 0; i < 16; i++) {
        int gcol = head * HD + dh * 128 + i * 8 + (lane & 3) * 2;
        *(__half2*)&act[(size_t)grow * QD + gcol] =
            __floats2half2_rn(oacc[i][0] * inv0, oacc[i][1] * inv0);
        *(__half2*)&act[(size_t)(grow + 8) * QD + gcol] =
            __floats2half2_rn(oacc[i][2] * inv1, oacc[i][3] * inv1);
    }
}

extern "C" void kernel_launch(void* const* d_in, const int* in_sizes, int n_in,
                              void* d_out, int out_size) {
    const float* hidden      = (const float*)d_in[0];
    const float* w_in        = (const float*)d_in[3];
    const float* w_post_attn = (const float*)d_in[4];
    const float* w_pre_ff    = (const float*)d_in[5];
    const float* w_post_ff   = (const float*)d_in[6];
    const float* wq          = (const float*)d_in[7];
    const float* wk          = (const float*)d_in[8];
    const float* wv          = (const float*)d_in[9];
    const float* wo          = (const float*)d_in[10];
    const float* w_gate      = (const float*)d_in[11];
    const float* w_up        = (const float*)d_in[12];
    const float* w_down      = (const float*)d_in[13];
    float* out = (float*)d_out;

    float *qkv, *proj, *x1, *down;
    __half *act, *act2, *wt;
    cudaGetSymbolAddress((void**)&qkv, g_qkv);
    cudaGetSymbolAddress((void**)&proj, g_proj);
    cudaGetSymbolAddress((void**)&x1, g_x1);
    cudaGetSymbolAddress((void**)&down, g_down);
    cudaGetSymbolAddress((void**)&act, g_act);
    cudaGetSymbolAddress((void**)&act2, g_act2);
    cudaGetSymbolAddress((void**)&wt, g_wt);

    cudaFuncSetAttribute(gemm_mma, cudaFuncAttributeMaxDynamicSharedMemorySize, SMEM_MMA);
    cudaFuncSetAttribute(gemm_swiglu, cudaFuncAttributeMaxDynamicSharedMemorySize, SMEM_MMA);
    cudaFuncSetAttribute(attn_mma_kernel, cudaFuncAttributeMaxDynamicSharedMemorySize, SMEM_ATT);

    dim3 wtb(32, 8);

    // ---- attention block ----
    rmsnorm_h_kernel<<<SQ, 256>>>(hidden, w_in, act);
    convert_wt<<<dim3(QD/32,   HDIM/32), wtb>>>(wq, wt, HDIM, QD,   0);
    convert_wt<<<dim3(2048/32, HDIM/32), wtb>>>(wk, wt, HDIM, 2048, 4096);
    convert_wt<<<dim3(2048/32, HDIM/32), wtb>>>(wv, wt, HDIM, 2048, 6144);
    gemm_mma<<<dim3(SQ/BM, QKVD/BN), 256, SMEM_MMA>>>(act, wt, qkv, QKVD, HDIM);
    rope_kernel<<<SQ * 24 * 128 / 256, 256>>>(qkv);
    attn_mma_kernel<<<dim3(SQ/64, NH), 256, SMEM_ATT>>>(qkv, act);
    convert_wt<<<dim3(HDIM/32, QD/32), wtb>>>(wo, wt, QD, HDIM, 0);
    gemm_mma<<<dim3(SQ/BM, HDIM/BN), 256, SMEM_MMA>>>(act, wt, proj, HDIM, QD);
    rmsnorm_kernel<<<SQ, 256>>>(proj, w_post_attn, hidden, x1);

    // ---- MLP block ----
    rmsnorm_h_kernel<<<SQ, 256>>>(x1, w_pre_ff, act);
    convert_wt_swi<<<dim3(IDIM/32, HDIM/32), wtb>>>(w_gate, wt, HDIM, IDIM, 0);
    convert_wt_swi<<<dim3(IDIM/32, HDIM/32), wtb>>>(w_up,   wt, HDIM, IDIM, 1);
    gemm_swiglu<<<dim3(SQ/BM, 2*IDIM/BN), 256, SMEM_MMA>>>(act, wt, act2, HDIM);
    convert_wt<<<dim3(HDIM/32, IDIM/32), wtb>>>(w_down, wt, IDIM, HDIM, 0);
    gemm_mma<<<dim3(SQ/BM, HDIM/BN), 256, SMEM_MMA>>>(act2, wt, down, HDIM, IDIM);
    rmsnorm_kernel<<<SQ, 256>>>(down, w_post_ff, x1, out);
}

// round 13
// speedup vs baseline: 2.2690x; 1.0316x over previous
#include <cuda_runtime.h>
#include <cuda_fp16.h>
#include <math.h>
#include <stdint.h>

#define SQ 2048
#define HDIM 3584
#define NH 16
#define NKV 8
#define HD 256
#define QKVD 8192           // 4096 q + 2048 k + 2048 v
#define QD 4096
#define IDIM 14336

// ---------------- scratch (allocation-free: __device__ globals) ----------------
static __device__ float g_proj[SQ*HDIM];
static __device__ float g_x1[SQ*HDIM];
static __device__ float g_down[SQ*HDIM];
static __device__ __half g_qkvh[SQ*QKVD];                 // fp16 qkv
static __device__ __half g_act[(size_t)SQ*IDIM];          // GEMM A operand
static __device__ __half g_act2[(size_t)SQ*IDIM];         // swiglu output (down-GEMM A)
static __device__ __half g_wt[(size_t)(2*IDIM)*HDIM];     // B fp16 K-major

// ---------------- PTX helpers (arch-agnostic only: sm_80-level) ----------------
__device__ __forceinline__ uint32_t smem_u32(const void* p) {
    uint32_t a;
    asm("{ .reg .u64 t; cvta.to.shared.u64 t, %1; cvt.u32.u64 %0, t; }" : "=r"(a) : "l"(p));
    return a;
}
__device__ __forceinline__ void ldx4(uint32_t& r0, uint32_t& r1, uint32_t& r2, uint32_t& r3, uint32_t a) {
    asm volatile("ldmatrix.sync.aligned.m8n8.x4.shared.b16 {%0,%1,%2,%3}, [%4];"
                 : "=r"(r0), "=r"(r1), "=r"(r2), "=r"(r3) : "r"(a));
}
__device__ __forceinline__ void hmma(float* c, uint32_t a0, uint32_t a1, uint32_t a2, uint32_t a3,
                                     uint32_t b0, uint32_t b1) {
    asm volatile("mma.sync.aligned.m16n8k16.row.col.f32.f16.f16.f32 "
                 "{%0,%1,%2,%3},{%4,%5,%6,%7},{%8,%9},{%0,%1,%2,%3};"
                 : "+f"(c[0]), "+f"(c[1]), "+f"(c[2]), "+f"(c[3])
                 : "r"(a0), "r"(a1), "r"(a2), "r"(a3), "r"(b0), "r"(b1));
}
#define CP_ASYNC16(dst, src) \
    asm volatile("cp.async.cg.shared.global [%0], [%1], 16;" :: "r"(dst), "l"(src))
#define CP_COMMIT() asm volatile("cp.async.commit_group;" ::: "memory")
#define CP_WAIT(n)  asm volatile("cp.async.wait_group %0;" :: "n"(n) : "memory")

// ============ HMMA fp16 GEMM core config ============
#define BM 128
#define BN 128
#define BK 64
#define STG 3
#define ROWH 72
#define STAGE_A (BM*ROWH*2)
#define STAGE_B (STAGE_A + BN*ROWH*2)
#define SMEM_MMA (STG*STAGE_B)

// Mainloop shared by all GEMM variants (expands inline; acc/addressing in scope)
#define GEMM_MAINLOOP(A_, B_, K_)                                                        \
    int lr = tid >> 3;                                                                   \
    int lc = (tid & 7) * 8;                                                              \
    const __half* gA0 = (A_) + (size_t)(m0 + lr) * (K_) + lc;                            \
    const __half* gB0 = (B_) + (size_t)(n0 + lr) * (K_) + lc;                            \
    uint32_t sOff = (uint32_t)(lr * ROWH + lc) * 2;                                      \
    uint32_t foff = (uint32_t)(((lane & 15) * ROWH) + ((lane >> 4) * 8)) * 2;            \
    float acc[4][4][4];                                                                  \
    _Pragma("unroll") for (int a = 0; a < 4; a++)                                        \
        _Pragma("unroll") for (int b = 0; b < 4; b++)                                    \
            _Pragma("unroll") for (int c = 0; c < 4; c++) acc[a][b][c] = 0.f;            \
    int ntiles = (K_) / BK;                                                              \
    auto LOAD = [&](int kt, int s) {                                                     \
        int ak = kt * BK;                                                                \
        uint32_t sA = sbase + s * STAGE_B;                                               \
        uint32_t sB = sA + STAGE_A;                                                      \
        _Pragma("unroll") for (int h = 0; h < 4; h++) {                                  \
            CP_ASYNC16(sA + sOff + h * 32 * ROWH * 2, gA0 + (size_t)h * 32 * (K_) + ak); \
            CP_ASYNC16(sB + sOff + h * 32 * ROWH * 2, gB0 + (size_t)h * 32 * (K_) + ak); \
        }                                                                                \
    };                                                                                   \
    _Pragma("unroll") for (int s = 0; s < STG - 1; s++) { LOAD(s, s); CP_COMMIT(); }     \
    for (int i = 0; i < ntiles; i++) {                                                   \
        CP_WAIT(STG - 2);                                                                \
        __syncthreads();                                                                 \
        int pf = i + STG - 1;                                                            \
        if (pf < ntiles) LOAD(pf, pf % STG);                                             \
        CP_COMMIT();                                                                     \
        int s = i % STG;                                                                 \
        uint32_t aB = sbase + s * STAGE_B;                                               \
        uint32_t bB = aB + STAGE_A;                                                      \
        uint32_t aAddr = aB + (uint32_t)wm * ROWH * 2 + foff;                            \
        uint32_t bAddr = bB + (uint32_t)wn * ROWH * 2 + foff;                            \
        _Pragma("unroll") for (int ks = 0; ks < 4; ks++) {                               \
            uint32_t af[4][4];                                                           \
            _Pragma("unroll") for (int fm = 0; fm < 4; fm++)                             \
                ldx4(af[fm][0], af[fm][1], af[fm][2], af[fm][3],                         \
                     aAddr + (uint32_t)fm * 16 * ROWH * 2 + ks * 32);                    \
            uint32_t t0, t1, t2, t3, t4, t5, t6, t7;                                     \
            ldx4(t0, t1, t2, t3, bAddr + ks * 32);                                       \
            ldx4(t4, t5, t6, t7, bAddr + 16 * ROWH * 2 + ks * 32);                       \
            uint32_t b0[4] = {t0, t1, t4, t5};                                           \
            uint32_t b1[4] = {t2, t3, t6, t7};                                           \
            _Pragma("unroll") for (int fm = 0; fm < 4; fm++)                             \
                _Pragma("unroll") for (int fn = 0; fn < 4; fn++)                         \
                    hmma(acc[fm][fn], af[fm][0], af[fm][1], af[fm][2], af[fm][3],        \
                         b0[fn], b1[fn]);                                                \
        }                                                                                \
    }

__global__ void __launch_bounds__(256, 2)
gemm_mma(const __half* __restrict__ A, const __half* __restrict__ B,
         float* __restrict__ C, int N, int K) {
    extern __shared__ char smem[];
    uint32_t sbase = smem_u32(smem);
    int tid = threadIdx.x, lane = tid & 31, wid = tid >> 5;
    int m0 = blockIdx.x * BM, n0 = blockIdx.y * BN;
    int wm = (wid & 1) * 64, wn = (wid >> 1) * 32;
    GEMM_MAINLOOP(A, B, K)
#pragma unroll
    for (int fm = 0; fm < 4; fm++) {
        int r = m0 + wm + fm * 16 + (lane >> 2);
#pragma unroll
        for (int fn = 0; fn < 4; fn++) {
            int c = n0 + wn + fn * 8 + (lane & 3) * 2;
            *(float2*)&C[(size_t)r * N + c]       = make_float2(acc[fm][fn][0], acc[fm][fn][1]);
            *(float2*)&C[(size_t)(r + 8) * N + c] = make_float2(acc[fm][fn][2], acc[fm][fn][3]);
        }
    }
}

// fp16-output GEMM (for qkv)
__global__ void __launch_bounds__(256, 2)
gemm_mma_h(const __half* __restrict__ A, const __half* __restrict__ B,
           __half* __restrict__ C, int N, int K) {
    extern __shared__ char smem[];
    uint32_t sbase = smem_u32(smem);
    int tid = threadIdx.x, lane = tid & 31, wid = tid >> 5;
    int m0 = blockIdx.x * BM, n0 = blockIdx.y * BN;
    int wm = (wid & 1) * 64, wn = (wid >> 1) * 32;
    GEMM_MAINLOOP(A, B, K)
#pragma unroll
    for (int fm = 0; fm < 4; fm++) {
        int r = m0 + wm + fm * 16 + (lane >> 2);
#pragma unroll
        for (int fn = 0; fn < 4; fn++) {
            int c = n0 + wn + fn * 8 + (lane & 3) * 2;
            *(__half2*)&C[(size_t)r * N + c]       = __floats2half2_rn(acc[fm][fn][0], acc[fm][fn][1]);
            *(__half2*)&C[(size_t)(r + 8) * N + c] = __floats2half2_rn(acc[fm][fn][2], acc[fm][fn][3]);
        }
    }
}

// gate/up GEMM with fused SwiGLU epilogue (interleaved B rows)
__global__ void __launch_bounds__(256, 2)
gemm_swiglu(const __half* __restrict__ A, const __half* __restrict__ B,
            __half* __restrict__ O, int K) {
    extern __shared__ char smem[];
    uint32_t sbase = smem_u32(smem);
    int tid = threadIdx.x, lane = tid & 31, wid = tid >> 5;
    int m0 = blockIdx.x * BM, n0 = blockIdx.y * BN;
    int wm = (wid & 1) * 64, wn = (wid >> 1) * 32;
    GEMM_MAINLOOP(A, B, K)
    __syncthreads();
    float* Cs = (float*)smem;              // [128][132]
#pragma unroll
    for (int fm = 0; fm < 4; fm++) {
        int r = wm + fm * 16 + (lane >> 2);
#pragma unroll
        for (int fn = 0; fn < 4; fn++) {
            int c = wn + fn * 8 + (lane & 3) * 2;
            *(float2*)&Cs[r * 132 + c]       = make_float2(acc[fm][fn][0], acc[fm][fn][1]);
            *(float2*)&Cs[(r + 8) * 132 + c] = make_float2(acc[fm][fn][2], acc[fm][fn][3]);
        }
    }
    __syncthreads();
    int colb = blockIdx.y * 64;
    for (int idx = tid; idx < 128 * 32; idx += 256) {
        int r = idx >> 5, c = (idx & 31) * 2;
        float2 g = *(float2*)&Cs[r * 132 + c];
        float2 u = *(float2*)&Cs[r * 132 + 64 + c];
        float t0 = tanhf(0.7978845608028654f * (g.x + 0.044715f * g.x * g.x * g.x));
        float t1 = tanhf(0.7978845608028654f * (g.y + 0.044715f * g.y * g.y * g.y));
        float v0 = 0.5f * g.x * (1.f + t0) * u.x;
        float v1 = 0.5f * g.y * (1.f + t1) * u.y;
        *(__half2*)&O[(size_t)(m0 + r) * IDIM + colb + c] =
            __halves2half2(__float2half(v0), __float2half(v1));
    }
}

// W[K,N] fp32 -> out[n_off+n][k] fp16 K-major (transpose)
__global__ void convert_wt(const float* __restrict__ W, __half* __restrict__ out,
                           int K, int N, int n_off) {
    __shared__ float tile[32][33];
    int n0 = blockIdx.x * 32, k0 = blockIdx.y * 32;
    int tx = threadIdx.x, ty = threadIdx.y;
#pragma unroll
    for (int r = 0; r < 4; r++)
        tile[ty + r * 8][tx] = W[(size_t)(k0 + ty + r * 8) * N + n0 + tx];
    __syncthreads();
#pragma unroll
    for (int r = 0; r < 4; r++) {
        int n = ty + r * 8;
        out[(size_t)(n_off + n0 + n) * K + k0 + tx] = __float2half(tile[tx][n]);
    }
}

// gate/up interleaved convert: row -> (n/64)*128 + which*64 + (n%64)
__global__ void convert_wt_swi(const float* __restrict__ W, __half* __restrict__ out,
                               int K, int N, int which) {
    __shared__ float tile[32][33];
    int n0 = blockIdx.x * 32, k0 = blockIdx.y * 32;
    int tx = threadIdx.x, ty = threadIdx.y;
#pragma unroll
    for (int r = 0; r < 4; r++)
        tile[ty + r * 8][tx] = W[(size_t)(k0 + ty + r * 8) * N + n0 + tx];
    __syncthreads();
#pragma unroll
    for (int r = 0; r < 4; r++) {
        int n = ty + r * 8;
        int ng = n0 + n;
        size_t rowg = (size_t)((ng >> 6) * 128 + which * 64 + (ng & 63));
        out[rowg * K + k0 + tx] = __float2half(tile[tx][n]);
    }
}

// ===== RMSNorm writing fp16 directly =====
__global__ void rmsnorm_h_kernel(const float* __restrict__ in, const float* __restrict__ w,
                                 __half* __restrict__ act) {
    int row = blockIdx.x;
    const float* x = in + (size_t)row * HDIM;
    float ss = 0.f;
    for (int c = threadIdx.x; c < HDIM; c += 256) { float v = x[c]; ss += v * v; }
    __shared__ float red[256];
    red[threadIdx.x] = ss;
    __syncthreads();
    for (int s = 128; s > 0; s >>= 1) {
        if (threadIdx.x < s) red[threadIdx.x] += red[threadIdx.x + s];
        __syncthreads();
    }
    float scale = rsqrtf(red[0] / (float)HDIM + 1e-6f);
    for (int c = threadIdx.x * 2; c < HDIM; c += 512) {
        float v0 = x[c] * scale * w[c];
        float v1 = x[c + 1] * scale * w[c + 1];
        *(__half2*)(act + (size_t)row * HDIM + c) =
            __halves2half2(__float2half(v0), __float2half(v1));
    }
}

// ================= RMSNorm fp32 out (+ residual) =================
__global__ void rmsnorm_kernel(const float* __restrict__ in, const float* __restrict__ w,
                               const float* __restrict__ resid, float* __restrict__ out) {
    int row = blockIdx.x;
    const float* x = in + (size_t)row * HDIM;
    float ss = 0.f;
    for (int c = threadIdx.x; c < HDIM; c += 256) { float v = x[c]; ss += v * v; }
    __shared__ float red[256];
    red[threadIdx.x] = ss;
    __syncthreads();
    for (int s = 128; s > 0; s >>= 1) {
        if (threadIdx.x < s) red[threadIdx.x] += red[threadIdx.x + s];
        __syncthreads();
    }
    float scale = rsqrtf(red[0] / (float)HDIM + 1e-6f);
    for (int c = threadIdx.x; c < HDIM; c += 256) {
        float v = x[c] * scale * w[c];
        if (resid) v += resid[(size_t)row * HDIM + c];
        out[(size_t)row * HDIM + c] = v;
    }
}

// ================= RoPE in-place on fp16 qkv [2048, 8192] =================
__global__ void rope_h_kernel(__half* __restrict__ x) {
    int idx = blockIdx.x * 256 + threadIdx.x;   // over 2048*24*64
    int d2 = (idx & 63) * 2;                    // even d
    int hh = (idx >> 6) % 24;
    int s = idx / (64 * 24);
    int col = (hh < 16) ? hh * 256 : 4096 + (hh - 16) * 256;
    size_t base = (size_t)s * QKVD + col;
    float2 a = __half22float2(*(__half2*)(x + base + d2));
    float2 b = __half22float2(*(__half2*)(x + base + d2 + 128));
    float c0, s0, c1, s1;
    {
        float invf = (float)exp(-((double)(2 * d2) / (double)HD) * log(10000.0));
        float ang = (float)s * invf;
        c0 = (float)cos((double)ang); s0 = (float)sin((double)ang);
    }
    {
        float invf = (float)exp(-((double)(2 * (d2 + 1)) / (double)HD) * log(10000.0));
        float ang = (float)s * invf;
        c1 = (float)cos((double)ang); s1 = (float)sin((double)ang);
    }
    *(__half2*)(x + base + d2)       = __floats2half2_rn(a.x * c0 - b.x * s0, a.y * c1 - b.y * s1);
    *(__half2*)(x + base + d2 + 128) = __floats2half2_rn(b.x * c0 + a.x * s0, b.y * c1 + a.y * s1);
}

// ====== HMMA flash attention: softcap + online softmax (FA2), causal; fp16 in/out ======
#define AQROW 264
#define AVROW 72
#define SMEM_ATT ((64*AQROW*2 + 256*AVROW) * 2)   // 104448 bytes

__global__ void __launch_bounds__(256, 1)
attn_mma_kernel(const __half* __restrict__ qkv, __half* __restrict__ act) {
    extern __shared__ __half hsm[];
    __half* Qs = hsm;
    __half* Ks = hsm + 64 * AQROW;
    __half* Vs = hsm + 128 * AQROW;

    int qb = blockIdx.x, head = blockIdx.y, kvh = head >> 1;
    int t = threadIdx.x, lane = t & 31, wid = t >> 5;
    int rg = wid & 3, dh = wid >> 2;

    // Q tile: straight fp16 16B copies
    for (int idx = t; idx < 64 * 32; idx += 256) {
        int i = idx >> 5, ch = (idx & 31) * 8;
        *(uint4*)&Qs[i * AQROW + ch] =
            *(const uint4*)&qkv[(size_t)(qb * 64 + i) * QKVD + head * HD + ch];
    }

    float oacc[16][4];
#pragma unroll
    for (int i = 0; i < 16; i++)
#pragma unroll
        for (int e = 0; e < 4; e++) oacc[i][e] = 0.f;
    float sl0 = 0.f, sl1 = 0.f;
    float M0 = -1e30f, M1 = -1e30f;

    uint32_t qAddr = smem_u32(Qs) + (uint32_t)((rg * 16 + (lane & 15)) * AQROW + (lane >> 4) * 8) * 2;
    uint32_t kBase = smem_u32(Ks) + (uint32_t)((lane & 15) * AQROW + (lane >> 4) * 8) * 2;
    uint32_t vBase = smem_u32(Vs) + (uint32_t)((dh * 128 + (lane & 15)) * AVROW + (lane >> 4) * 8) * 2;

    int lrow = rg * 16 + (lane >> 2);

    for (int kb = 0; kb <= qb; kb++) {
        __syncthreads();
        // K tile fp16 copies
        for (int idx = t; idx < 64 * 32; idx += 256) {
            int j = idx >> 5, ch = (idx & 31) * 8;
            *(uint4*)&Ks[j * AQROW + ch] =
                *(const uint4*)&qkv[(size_t)(kb * 64 + j) * QKVD + 4096 + kvh * HD + ch];
        }
        // V tile transposed (scalar half scatter)
        for (int idx = t; idx < 64 * 64; idx += 256) {
            int j = idx >> 6, c = (idx & 63) * 4;
            const __half* gv = &qkv[(size_t)(kb * 64 + j) * QKVD + 6144 + kvh * HD + c];
            __half2 v01 = *(const __half2*)gv;
            __half2 v23 = *(const __half2*)(gv + 2);
            Vs[(c + 0) * AVROW + j] = __low2half(v01);
            Vs[(c + 1) * AVROW + j] = __high2half(v01);
            Vs[(c + 2) * AVROW + j] = __low2half(v23);
            Vs[(c + 3) * AVROW + j] = __high2half(v23);
        }
        __syncthreads();

        float sacc[8][4];
#pragma unroll
        for (int i = 0; i < 8; i++)
#pragma unroll
            for (int e = 0; e < 4; e++) sacc[i][e] = 0.f;
#pragma unroll
        for (int ks = 0; ks < 16; ks++) {
            uint32_t a0, a1, a2, a3;
            ldx4(a0, a1, a2, a3, qAddr + ks * 32);
#pragma unroll
            for (int jt = 0; jt < 4; jt++) {
                uint32_t t0, t1, t2, t3;
                ldx4(t0, t1, t2, t3, kBase + (uint32_t)jt * 16 * AQROW * 2 + ks * 32);
                hmma(sacc[jt * 2],     a0, a1, a2, a3, t0, t2);
                hmma(sacc[jt * 2 + 1], a0, a1, a2, a3, t1, t3);
            }
        }

        bool diag = (kb == qb);
#pragma unroll
        for (int tt = 0; tt < 8; tt++) {
            int colb = tt * 8 + (lane & 3) * 2;
#pragma unroll
            for (int e = 0; e < 4; e++) {
                float sc = sacc[tt][e] * 0.0625f;
                sc = tanhf(sc * 0.02f) * 50.f;
                bool valid = !diag || (colb + (e & 1) <= lrow + (e >> 1) * 8);
                sacc[tt][e] = valid ? sc : -1e30f;
            }
        }

        float m0 = -1e30f, m1 = -1e30f;
#pragma unroll
        for (int tt = 0; tt < 8; tt++) {
            m0 = fmaxf(m0, fmaxf(sacc[tt][0], sacc[tt][1]));
            m1 = fmaxf(m1, fmaxf(sacc[tt][2], sacc[tt][3]));
        }
        m0 = fmaxf(m0, __shfl_xor_sync(0xFFFFFFFF, m0, 1));
        m0 = fmaxf(m0, __shfl_xor_sync(0xFFFFFFFF, m0, 2));
        m1 = fmaxf(m1, __shfl_xor_sync(0xFFFFFFFF, m1, 1));
        m1 = fmaxf(m1, __shfl_xor_sync(0xFFFFFFFF, m1, 2));
        float nM0 = fmaxf(M0, m0), nM1 = fmaxf(M1, m1);
        float f0 = __expf(M0 - nM0), f1 = __expf(M1 - nM1);
        M0 = nM0; M1 = nM1;
        sl0 *= f0; sl1 *= f1;
#pragma unroll
        for (int i = 0; i < 16; i++) {
            oacc[i][0] *= f0; oacc[i][1] *= f0;
            oacc[i][2] *= f1; oacc[i][3] *= f1;
        }

        uint32_t pf[4][4];
#pragma unroll
        for (int tt = 0; tt < 8; tt++) {
            __half2 h01 = __floats2half2_rn(__expf(sacc[tt][0] - M0), __expf(sacc[tt][1] - M0));
            __half2 h23 = __floats2half2_rn(__expf(sacc[tt][2] - M1), __expf(sacc[tt][3] - M1));
            pf[tt >> 1][(tt & 1) * 2]     = *(uint32_t*)&h01;
            pf[tt >> 1][(tt & 1) * 2 + 1] = *(uint32_t*)&h23;
            float2 f01 = __half22float2(h01), f23 = __half22float2(h23);
            sl0 += f01.x + f01.y;
            sl1 += f23.x + f23.y;
        }

#pragma unroll
        for (int s = 0; s < 4; s++) {
#pragma unroll
            for (int i = 0; i < 8; i++) {
                uint32_t t0, t1, t2, t3;
                ldx4(t0, t1, t2, t3, vBase + (uint32_t)i * 16 * AVROW * 2 + s * 32);
                hmma(oacc[i * 2],     pf[s][0], pf[s][1], pf[s][2], pf[s][3], t0, t2);
                hmma(oacc[i * 2 + 1], pf[s][0], pf[s][1], pf[s][2], pf[s][3], t1, t3);
            }
        }
    }

    sl0 += __shfl_xor_sync(0xFFFFFFFF, sl0, 1);
    sl0 += __shfl_xor_sync(0xFFFFFFFF, sl0, 2);
    sl1 += __shfl_xor_sync(0xFFFFFFFF, sl1, 1);
    sl1 += __shfl_xor_sync(0xFFFFFFFF, sl1, 2);
    float inv0 = 1.f / sl0, inv1 = 1.f / sl1;

    int grow = qb * 64 + lrow;
#pragma unroll
    for (int i = 0; i < 16; i++) {
        int gcol = head * HD + dh * 128 + i * 8 + (lane & 3) * 2;
        *(__half2*)&act[(size_t)grow * QD + gcol] =
            __floats2half2_rn(oacc[i][0] * inv0, oacc[i][1] * inv0);
        *(__half2*)&act[(size_t)(grow + 8) * QD + gcol] =
            __floats2half2_rn(oacc[i][2] * inv1, oacc[i][3] * inv1);
    }
}

extern "C" void kernel_launch(void* const* d_in, const int* in_sizes, int n_in,
                              void* d_out, int out_size) {
    const float* hidden      = (const float*)d_in[0];
    const float* w_in        = (const float*)d_in[3];
    const float* w_post_attn = (const float*)d_in[4];
    const float* w_pre_ff    = (const float*)d_in[5];
    const float* w_post_ff   = (const float*)d_in[6];
    const float* wq          = (const float*)d_in[7];
    const float* wk          = (const float*)d_in[8];
    const float* wv          = (const float*)d_in[9];
    const float* wo          = (const float*)d_in[10];
    const float* w_gate      = (const float*)d_in[11];
    const float* w_up        = (const float*)d_in[12];
    const float* w_down      = (const float*)d_in[13];
    float* out = (float*)d_out;

    float *proj, *x1, *down;
    __half *qkvh, *act, *act2, *wt;
    cudaGetSymbolAddress((void**)&proj, g_proj);
    cudaGetSymbolAddress((void**)&x1, g_x1);
    cudaGetSymbolAddress((void**)&down, g_down);
    cudaGetSymbolAddress((void**)&qkvh, g_qkvh);
    cudaGetSymbolAddress((void**)&act, g_act);
    cudaGetSymbolAddress((void**)&act2, g_act2);
    cudaGetSymbolAddress((void**)&wt, g_wt);

    cudaFuncSetAttribute(gemm_mma, cudaFuncAttributeMaxDynamicSharedMemorySize, SMEM_MMA);
    cudaFuncSetAttribute(gemm_mma_h, cudaFuncAttributeMaxDynamicSharedMemorySize, SMEM_MMA);
    cudaFuncSetAttribute(gemm_swiglu, cudaFuncAttributeMaxDynamicSharedMemorySize, SMEM_MMA);
    cudaFuncSetAttribute(attn_mma_kernel, cudaFuncAttributeMaxDynamicSharedMemorySize, SMEM_ATT);

    dim3 wtb(32, 8);

    // ---- attention block ----
    rmsnorm_h_kernel<<<SQ, 256>>>(hidden, w_in, act);
    convert_wt<<<dim3(QD/32,   HDIM/32), wtb>>>(wq, wt, HDIM, QD,   0);
    convert_wt<<<dim3(2048/32, HDIM/32), wtb>>>(wk, wt, HDIM, 2048, 4096);
    convert_wt<<<dim3(2048/32, HDIM/32), wtb>>>(wv, wt, HDIM, 2048, 6144);
    gemm_mma_h<<<dim3(SQ/BM, QKVD/BN), 256, SMEM_MMA>>>(act, wt, qkvh, QKVD, HDIM);
    rope_h_kernel<<<SQ * 24 * 64 / 256, 256>>>(qkvh);
    attn_mma_kernel<<<dim3(SQ/64, NH), 256, SMEM_ATT>>>(qkvh, act);
    convert_wt<<<dim3(HDIM/32, QD/32), wtb>>>(wo, wt, QD, HDIM, 0);
    gemm_mma<<<dim3(SQ/BM, HDIM/BN), 256, SMEM_MMA>>>(act, wt, proj, HDIM, QD);
    rmsnorm_kernel<<<SQ, 256>>>(proj, w_post_attn, hidden, x1);

    // ---- MLP block ----
    rmsnorm_h_kernel<<<SQ, 256>>>(x1, w_pre_ff, act);
    convert_wt_swi<<<dim3(IDIM/32, HDIM/32), wtb>>>(w_gate, wt, HDIM, IDIM, 0);
    convert_wt_swi<<<dim3(IDIM/32, HDIM/32), wtb>>>(w_up,   wt, HDIM, IDIM, 1);
    gemm_swiglu<<<dim3(SQ/BM, 2*IDIM/BN), 256, SMEM_MMA>>>(act, wt, act2, HDIM);
    convert_wt<<<dim3(HDIM/32, IDIM/32), wtb>>>(w_down, wt, IDIM, HDIM, 0);
    gemm_mma<<<dim3(SQ/BM, HDIM/BN), 256, SMEM_MMA>>>(act2, wt, down, HDIM, IDIM);
    rmsnorm_kernel<<<SQ, 256>>>(down, w_post_ff, x1, out);
}

// round 14
// speedup vs baseline: 2.3008x; 1.0140x over previous
#include <cuda_runtime.h>
#include <cuda_fp16.h>
#include <math.h>
#include <stdint.h>

#define SQ 2048
#define HDIM 3584
#define NH 16
#define NKV 8
#define HD 256
#define QKVD 8192           // 4096 q + 2048 k + 2048 v
#define QD 4096
#define IDIM 14336

// ---------------- scratch (allocation-free: __device__ globals) ----------------
static __device__ float g_proj[SQ*HDIM];
static __device__ float g_x1[SQ*HDIM];
static __device__ float g_down[SQ*HDIM];
static __device__ __half g_qkvh[SQ*QKVD];                 // fp16 qkv
static __device__ __half g_act[(size_t)SQ*IDIM];          // GEMM A operand
static __device__ __half g_act2[(size_t)SQ*IDIM];         // swiglu output (down-GEMM A)
static __device__ __half g_wt[(size_t)(2*IDIM)*HDIM];     // B fp16 K-major

// ---------------- PTX helpers (arch-agnostic only: sm_80-level) ----------------
__device__ __forceinline__ uint32_t smem_u32(const void* p) {
    uint32_t a;
    asm("{ .reg .u64 t; cvta.to.shared.u64 t, %1; cvt.u32.u64 %0, t; }" : "=r"(a) : "l"(p));
    return a;
}
__device__ __forceinline__ void ldx4(uint32_t& r0, uint32_t& r1, uint32_t& r2, uint32_t& r3, uint32_t a) {
    asm volatile("ldmatrix.sync.aligned.m8n8.x4.shared.b16 {%0,%1,%2,%3}, [%4];"
                 : "=r"(r0), "=r"(r1), "=r"(r2), "=r"(r3) : "r"(a));
}
__device__ __forceinline__ void hmma(float* c, uint32_t a0, uint32_t a1, uint32_t a2, uint32_t a3,
                                     uint32_t b0, uint32_t b1) {
    asm volatile("mma.sync.aligned.m16n8k16.row.col.f32.f16.f16.f32 "
                 "{%0,%1,%2,%3},{%4,%5,%6,%7},{%8,%9},{%0,%1,%2,%3};"
                 : "+f"(c[0]), "+f"(c[1]), "+f"(c[2]), "+f"(c[3])
                 : "r"(a0), "r"(a1), "r"(a2), "r"(a3), "r"(b0), "r"(b1));
}
#define CP_ASYNC16(dst, src) \
    asm volatile("cp.async.cg.shared.global [%0], [%1], 16;" :: "r"(dst), "l"(src))
#define CP_COMMIT() asm volatile("cp.async.commit_group;" ::: "memory")
#define CP_WAIT(n)  asm volatile("cp.async.wait_group %0;" :: "n"(n) : "memory")

// ============ HMMA fp16 GEMM core config ============
#define BM 128
#define BN 128
#define BK 64
#define STG 3
#define ROWH 72
#define STAGE_A (BM*ROWH*2)
#define STAGE_B (STAGE_A + BN*ROWH*2)
#define SMEM_MMA (STG*STAGE_B)

#define GEMM_MAINLOOP(A_, B_, K_)                                                        \
    int lr = tid >> 3;                                                                   \
    int lc = (tid & 7) * 8;                                                              \
    const __half* gA0 = (A_) + (size_t)(m0 + lr) * (K_) + lc;                            \
    const __half* gB0 = (B_) + (size_t)(n0 + lr) * (K_) + lc;                            \
    uint32_t sOff = (uint32_t)(lr * ROWH + lc) * 2;                                      \
    uint32_t foff = (uint32_t)(((lane & 15) * ROWH) + ((lane >> 4) * 8)) * 2;            \
    float acc[4][4][4];                                                                  \
    _Pragma("unroll") for (int a = 0; a < 4; a++)                                        \
        _Pragma("unroll") for (int b = 0; b < 4; b++)                                    \
            _Pragma("unroll") for (int c = 0; c < 4; c++) acc[a][b][c] = 0.f;            \
    int ntiles = (K_) / BK;                                                              \
    auto LOAD = [&](int kt, int s) {                                                     \
        int ak = kt * BK;                                                                \
        uint32_t sA = sbase + s * STAGE_B;                                               \
        uint32_t sB = sA + STAGE_A;                                                      \
        _Pragma("unroll") for (int h = 0; h < 4; h++) {                                  \
            CP_ASYNC16(sA + sOff + h * 32 * ROWH * 2, gA0 + (size_t)h * 32 * (K_) + ak); \
            CP_ASYNC16(sB + sOff + h * 32 * ROWH * 2, gB0 + (size_t)h * 32 * (K_) + ak); \
        }                                                                                \
    };                                                                                   \
    _Pragma("unroll") for (int s = 0; s < STG - 1; s++) { LOAD(s, s); CP_COMMIT(); }     \
    for (int i = 0; i < ntiles; i++) {                                                   \
        CP_WAIT(STG - 2);                                                                \
        __syncthreads();                                                                 \
        int pf = i + STG - 1;                                                            \
        if (pf < ntiles) LOAD(pf, pf % STG);                                             \
        CP_COMMIT();                                                                     \
        int s = i % STG;                                                                 \
        uint32_t aB = sbase + s * STAGE_B;                                               \
        uint32_t bB = aB + STAGE_A;                                                      \
        uint32_t aAddr = aB + (uint32_t)wm * ROWH * 2 + foff;                            \
        uint32_t bAddr = bB + (uint32_t)wn * ROWH * 2 + foff;                            \
        _Pragma("unroll") for (int ks = 0; ks < 4; ks++) {                               \
            uint32_t af[4][4];                                                           \
            _Pragma("unroll") for (int fm = 0; fm < 4; fm++)                             \
                ldx4(af[fm][0], af[fm][1], af[fm][2], af[fm][3],                         \
                     aAddr + (uint32_t)fm * 16 * ROWH * 2 + ks * 32);                    \
            uint32_t t0, t1, t2, t3, t4, t5, t6, t7;                                     \
            ldx4(t0, t1, t2, t3, bAddr + ks * 32);                                       \
            ldx4(t4, t5, t6, t7, bAddr + 16 * ROWH * 2 + ks * 32);                       \
            uint32_t b0[4] = {t0, t1, t4, t5};                                           \
            uint32_t b1[4] = {t2, t3, t6, t7};                                           \
            _Pragma("unroll") for (int fm = 0; fm < 4; fm++)                             \
                _Pragma("unroll") for (int fn = 0; fn < 4; fn++)                         \
                    hmma(acc[fm][fn], af[fm][0], af[fm][1], af[fm][2], af[fm][3],        \
                         b0[fn], b1[fn]);                                                \
        }                                                                                \
    }

__global__ void __launch_bounds__(256, 2)
gemm_mma(const __half* __restrict__ A, const __half* __restrict__ B,
         float* __restrict__ C, int N, int K) {
    extern __shared__ char smem[];
    uint32_t sbase = smem_u32(smem);
    int tid = threadIdx.x, lane = tid & 31, wid = tid >> 5;
    int m0 = blockIdx.x * BM, n0 = blockIdx.y * BN;
    int wm = (wid & 1) * 64, wn = (wid >> 1) * 32;
    GEMM_MAINLOOP(A, B, K)
#pragma unroll
    for (int fm = 0; fm < 4; fm++) {
        int r = m0 + wm + fm * 16 + (lane >> 2);
#pragma unroll
        for (int fn = 0; fn < 4; fn++) {
            int c = n0 + wn + fn * 8 + (lane & 3) * 2;
            *(float2*)&C[(size_t)r * N + c]       = make_float2(acc[fm][fn][0], acc[fm][fn][1]);
            *(float2*)&C[(size_t)(r + 8) * N + c] = make_float2(acc[fm][fn][2], acc[fm][fn][3]);
        }
    }
}

// fp16-output GEMM (for qkv)
__global__ void __launch_bounds__(256, 2)
gemm_mma_h(const __half* __restrict__ A, const __half* __restrict__ B,
           __half* __restrict__ C, int N, int K) {
    extern __shared__ char smem[];
    uint32_t sbase = smem_u32(smem);
    int tid = threadIdx.x, lane = tid & 31, wid = tid >> 5;
    int m0 = blockIdx.x * BM, n0 = blockIdx.y * BN;
    int wm = (wid & 1) * 64, wn = (wid >> 1) * 32;
    GEMM_MAINLOOP(A, B, K)
#pragma unroll
    for (int fm = 0; fm < 4; fm++) {
        int r = m0 + wm + fm * 16 + (lane >> 2);
#pragma unroll
        for (int fn = 0; fn < 4; fn++) {
            int c = n0 + wn + fn * 8 + (lane & 3) * 2;
            *(__half2*)&C[(size_t)r * N + c]       = __floats2half2_rn(acc[fm][fn][0], acc[fm][fn][1]);
            *(__half2*)&C[(size_t)(r + 8) * N + c] = __floats2half2_rn(acc[fm][fn][2], acc[fm][fn][3]);
        }
    }
}

// gate/up GEMM with fused SwiGLU epilogue (interleaved B rows)
__global__ void __launch_bounds__(256, 2)
gemm_swiglu(const __half* __restrict__ A, const __half* __restrict__ B,
            __half* __restrict__ O, int K) {
    extern __shared__ char smem[];
    uint32_t sbase = smem_u32(smem);
    int tid = threadIdx.x, lane = tid & 31, wid = tid >> 5;
    int m0 = blockIdx.x * BM, n0 = blockIdx.y * BN;
    int wm = (wid & 1) * 64, wn = (wid >> 1) * 32;
    GEMM_MAINLOOP(A, B, K)
    __syncthreads();
    float* Cs = (float*)smem;              // [128][132]
#pragma unroll
    for (int fm = 0; fm < 4; fm++) {
        int r = wm + fm * 16 + (lane >> 2);
#pragma unroll
        for (int fn = 0; fn < 4; fn++) {
            int c = wn + fn * 8 + (lane & 3) * 2;
            *(float2*)&Cs[r * 132 + c]       = make_float2(acc[fm][fn][0], acc[fm][fn][1]);
            *(float2*)&Cs[(r + 8) * 132 + c] = make_float2(acc[fm][fn][2], acc[fm][fn][3]);
        }
    }
    __syncthreads();
    int colb = blockIdx.y * 64;
    for (int idx = tid; idx < 128 * 32; idx += 256) {
        int r = idx >> 5, c = (idx & 31) * 2;
        float2 g = *(float2*)&Cs[r * 132 + c];
        float2 u = *(float2*)&Cs[r * 132 + 64 + c];
        float t0 = tanhf(0.7978845608028654f * (g.x + 0.044715f * g.x * g.x * g.x));
        float t1 = tanhf(0.7978845608028654f * (g.y + 0.044715f * g.y * g.y * g.y));
        float v0 = 0.5f * g.x * (1.f + t0) * u.x;
        float v1 = 0.5f * g.y * (1.f + t1) * u.y;
        *(__half2*)&O[(size_t)(m0 + r) * IDIM + colb + c] =
            __halves2half2(__float2half(v0), __float2half(v1));
    }
}

// ===== W[K,N] fp32 -> out[n_off+n][k] fp16 K-major, vectorized (32n x 64k tiles) =====
__global__ void convert_wt(const float* __restrict__ W, __half* __restrict__ out,
                           int K, int N, int n_off) {
    __shared__ float tile[32][67];     // [n][k], 67-pad: conflict-free writes
    int n0 = blockIdx.x * 32, k0 = blockIdx.y * 64;
    int tx = threadIdx.x, ty = threadIdx.y;   // 32 x 8
#pragma unroll
    for (int r = 0; r < 8; r++) {
        int k = ty + r * 8;
        tile[tx][k] = W[(size_t)(k0 + k) * N + n0 + tx];
    }
    __syncthreads();
#pragma unroll
    for (int r = 0; r < 4; r++) {
        int n = ty + r * 8;
        float a = tile[n][tx * 2], b = tile[n][tx * 2 + 1];
        *(__half2*)&out[(size_t)(n_off + n0 + n) * K + k0 + tx * 2] = __floats2half2_rn(a, b);
    }
}

// gate/up interleaved convert: row -> (n/64)*128 + which*64 + (n%64); vectorized
__global__ void convert_wt_swi(const float* __restrict__ W, __half* __restrict__ out,
                               int K, int N, int which) {
    __shared__ float tile[32][67];
    int n0 = blockIdx.x * 32, k0 = blockIdx.y * 64;
    int tx = threadIdx.x, ty = threadIdx.y;
#pragma unroll
    for (int r = 0; r < 8; r++) {
        int k = ty + r * 8;
        tile[tx][k] = W[(size_t)(k0 + k) * N + n0 + tx];
    }
    __syncthreads();
#pragma unroll
    for (int r = 0; r < 4; r++) {
        int n = ty + r * 8;
        int ng = n0 + n;
        size_t rowg = (size_t)((ng >> 6) * 128 + which * 64 + (ng & 63));
        float a = tile[n][tx * 2], b = tile[n][tx * 2 + 1];
        *(__half2*)&out[rowg * K + k0 + tx * 2] = __floats2half2_rn(a, b);
    }
}

// ===== RMSNorm writing fp16 directly =====
__global__ void rmsnorm_h_kernel(const float* __restrict__ in, const float* __restrict__ w,
                                 __half* __restrict__ act) {
    int row = blockIdx.x;
    const float* x = in + (size_t)row * HDIM;
    float ss = 0.f;
    for (int c = threadIdx.x; c < HDIM; c += 256) { float v = x[c]; ss += v * v; }
    __shared__ float red[256];
    red[threadIdx.x] = ss;
    __syncthreads();
    for (int s = 128; s > 0; s >>= 1) {
        if (threadIdx.x < s) red[threadIdx.x] += red[threadIdx.x + s];
        __syncthreads();
    }
    float scale = rsqrtf(red[0] / (float)HDIM + 1e-6f);
    for (int c = threadIdx.x * 2; c < HDIM; c += 512) {
        float v0 = x[c] * scale * w[c];
        float v1 = x[c + 1] * scale * w[c + 1];
        *(__half2*)(act + (size_t)row * HDIM + c) =
            __halves2half2(__float2half(v0), __float2half(v1));
    }
}

// ===== fused: x1 = resid + rmsnorm(in, w1);  act = fp16(rmsnorm(x1, w2)) =====
__global__ void rmsnorm_pair_kernel(const float* __restrict__ in, const float* __restrict__ w1,
                                    const float* __restrict__ resid, const float* __restrict__ w2,
                                    float* __restrict__ x1, __half* __restrict__ act) {
    extern __shared__ float buf[];   // HDIM floats
    __shared__ float red[256];
    int row = blockIdx.x, t = threadIdx.x;
    const float* x = in + (size_t)row * HDIM;
    float ss = 0.f;
    for (int c = t; c < HDIM; c += 256) { float v = x[c]; buf[c] = v; ss += v * v; }
    red[t] = ss;
    __syncthreads();
    for (int s = 128; s > 0; s >>= 1) {
        if (t < s) red[t] += red[t + s];
        __syncthreads();
    }
    float scale = rsqrtf(red[0] / (float)HDIM + 1e-6f);
    __syncthreads();
    float ss2 = 0.f;
    for (int c = t; c < HDIM; c += 256) {
        float v = buf[c] * scale * w1[c] + resid[(size_t)row * HDIM + c];
        buf[c] = v;
        x1[(size_t)row * HDIM + c] = v;
        ss2 += v * v;
    }
    red[t] = ss2;
    __syncthreads();
    for (int s = 128; s > 0; s >>= 1) {
        if (t < s) red[t] += red[t + s];
        __syncthreads();
    }
    float scale2 = rsqrtf(red[0] / (float)HDIM + 1e-6f);
    for (int c = t * 2; c < HDIM; c += 512) {
        float v0 = buf[c] * scale2 * w2[c];
        float v1 = buf[c + 1] * scale2 * w2[c + 1];
        *(__half2*)(act + (size_t)row * HDIM + c) =
            __halves2half2(__float2half(v0), __float2half(v1));
    }
}

// ================= RMSNorm fp32 out (+ residual) =================
__global__ void rmsnorm_kernel(const float* __restrict__ in, const float* __restrict__ w,
                               const float* __restrict__ resid, float* __restrict__ out) {
    int row = blockIdx.x;
    const float* x = in + (size_t)row * HDIM;
    float ss = 0.f;
    for (int c = threadIdx.x; c < HDIM; c += 256) { float v = x[c]; ss += v * v; }
    __shared__ float red[256];
    red[threadIdx.x] = ss;
    __syncthreads();
    for (int s = 128; s > 0; s >>= 1) {
        if (threadIdx.x < s) red[threadIdx.x] += red[threadIdx.x + s];
        __syncthreads();
    }
    float scale = rsqrtf(red[0] / (float)HDIM + 1e-6f);
    for (int c = threadIdx.x; c < HDIM; c += 256) {
        float v = x[c] * scale * w[c];
        if (resid) v += resid[(size_t)row * HDIM + c];
        out[(size_t)row * HDIM + c] = v;
    }
}

// ================= RoPE in-place on fp16 qkv [2048, 8192] =================
__global__ void rope_h_kernel(__half* __restrict__ x) {
    int idx = blockIdx.x * 256 + threadIdx.x;   // over 2048*24*64
    int d2 = (idx & 63) * 2;
    int hh = (idx >> 6) % 24;
    int s = idx / (64 * 24);
    int col = (hh < 16) ? hh * 256 : 4096 + (hh - 16) * 256;
    size_t base = (size_t)s * QKVD + col;
    float2 a = __half22float2(*(__half2*)(x + base + d2));
    float2 b = __half22float2(*(__half2*)(x + base + d2 + 128));
    float c0, s0, c1, s1;
    {
        float invf = (float)exp(-((double)(2 * d2) / (double)HD) * log(10000.0));
        float ang = (float)s * invf;
        c0 = (float)cos((double)ang); s0 = (float)sin((double)ang);
    }
    {
        float invf = (float)exp(-((double)(2 * (d2 + 1)) / (double)HD) * log(10000.0));
        float ang = (float)s * invf;
        c1 = (float)cos((double)ang); s1 = (float)sin((double)ang);
    }
    *(__half2*)(x + base + d2)       = __floats2half2_rn(a.x * c0 - b.x * s0, a.y * c1 - b.y * s1);
    *(__half2*)(x + base + d2 + 128) = __floats2half2_rn(b.x * c0 + a.x * s0, b.y * c1 + a.y * s1);
}

// ====== HMMA flash attention: softcap + online softmax (FA2), causal; fp16 in/out ======
#define AQROW 264
#define AVROW 72
#define SMEM_ATT ((64*AQROW*2 + 256*AVROW) * 2)   // 104448 bytes

__global__ void __launch_bounds__(256, 1)
attn_mma_kernel(const __half* __restrict__ qkv, __half* __restrict__ act) {
    extern __shared__ __half hsm[];
    __half* Qs = hsm;
    __half* Ks = hsm + 64 * AQROW;
    __half* Vs = hsm + 128 * AQROW;

    int qb = blockIdx.x, head = blockIdx.y, kvh = head >> 1;
    int t = threadIdx.x, lane = t & 31, wid = t >> 5;
    int rg = wid & 3, dh = wid >> 2;

    for (int idx = t; idx < 64 * 32; idx += 256) {
        int i = idx >> 5, ch = (idx & 31) * 8;
        *(uint4*)&Qs[i * AQROW + ch] =
            *(const uint4*)&qkv[(size_t)(qb * 64 + i) * QKVD + head * HD + ch];
    }

    float oacc[16][4];
#pragma unroll
    for (int i = 0; i < 16; i++)
#pragma unroll
        for (int e = 0; e < 4; e++) oacc[i][e] = 0.f;
    float sl0 = 0.f, sl1 = 0.f;
    float M0 = -1e30f, M1 = -1e30f;

    uint32_t qAddr = smem_u32(Qs) + (uint32_t)((rg * 16 + (lane & 15)) * AQROW + (lane >> 4) * 8) * 2;
    uint32_t kBase = smem_u32(Ks) + (uint32_t)((lane & 15) * AQROW + (lane >> 4) * 8) * 2;
    uint32_t vBase = smem_u32(Vs) + (uint32_t)((dh * 128 + (lane & 15)) * AVROW + (lane >> 4) * 8) * 2;

    int lrow = rg * 16 + (lane >> 2);

    for (int kb = 0; kb <= qb; kb++) {
        __syncthreads();
        for (int idx = t; idx < 64 * 32; idx += 256) {
            int j = idx >> 5, ch = (idx & 31) * 8;
            *(uint4*)&Ks[j * AQROW + ch] =
                *(const uint4*)&qkv[(size_t)(kb * 64 + j) * QKVD + 4096 + kvh * HD + ch];
        }
        for (int idx = t; idx < 64 * 64; idx += 256) {
            int j = idx >> 6, c = (idx & 63) * 4;
            const __half* gv = &qkv[(size_t)(kb * 64 + j) * QKVD + 6144 + kvh * HD + c];
            __half2 v01 = *(const __half2*)gv;
            __half2 v23 = *(const __half2*)(gv + 2);
            Vs[(c + 0) * AVROW + j] = __low2half(v01);
            Vs[(c + 1) * AVROW + j] = __high2half(v01);
            Vs[(c + 2) * AVROW + j] = __low2half(v23);
            Vs[(c + 3) * AVROW + j] = __high2half(v23);
        }
        __syncthreads();

        float sacc[8][4];
#pragma unroll
        for (int i = 0; i < 8; i++)
#pragma unroll
            for (int e = 0; e < 4; e++) sacc[i][e] = 0.f;
#pragma unroll
        for (int ks = 0; ks < 16; ks++) {
            uint32_t a0, a1, a2, a3;
            ldx4(a0, a1, a2, a3, qAddr + ks * 32);
#pragma unroll
            for (int jt = 0; jt < 4; jt++) {
                uint32_t t0, t1, t2, t3;
                ldx4(t0, t1, t2, t3, kBase + (uint32_t)jt * 16 * AQROW * 2 + ks * 32);
                hmma(sacc[jt * 2],     a0, a1, a2, a3, t0, t2);
                hmma(sacc[jt * 2 + 1], a0, a1, a2, a3, t1, t3);
            }
        }

        bool diag = (kb == qb);
#pragma unroll
        for (int tt = 0; tt < 8; tt++) {
            int colb = tt * 8 + (lane & 3) * 2;
#pragma unroll
            for (int e = 0; e < 4; e++) {
                float sc = sacc[tt][e] * 0.0625f;
                sc = tanhf(sc * 0.02f) * 50.f;
                bool valid = !diag || (colb + (e & 1) <= lrow + (e >> 1) * 8);
                sacc[tt][e] = valid ? sc : -1e30f;
            }
        }

        float m0 = -1e30f, m1 = -1e30f;
#pragma unroll
        for (int tt = 0; tt < 8; tt++) {
            m0 = fmaxf(m0, fmaxf(sacc[tt][0], sacc[tt][1]));
            m1 = fmaxf(m1, fmaxf(sacc[tt][2], sacc[tt][3]));
        }
        m0 = fmaxf(m0, __shfl_xor_sync(0xFFFFFFFF, m0, 1));
        m0 = fmaxf(m0, __shfl_xor_sync(0xFFFFFFFF, m0, 2));
        m1 = fmaxf(m1, __shfl_xor_sync(0xFFFFFFFF, m1, 1));
        m1 = fmaxf(m1, __shfl_xor_sync(0xFFFFFFFF, m1, 2));
        float nM0 = fmaxf(M0, m0), nM1 = fmaxf(M1, m1);
        float f0 = __expf(M0 - nM0), f1 = __expf(M1 - nM1);
        M0 = nM0; M1 = nM1;
        sl0 *= f0; sl1 *= f1;
#pragma unroll
        for (int i = 0; i < 16; i++) {
            oacc[i][0] *= f0; oacc[i][1] *= f0;
            oacc[i][2] *= f1; oacc[i][3] *= f1;
        }

        uint32_t pf[4][4];
#pragma unroll
        for (int tt = 0; tt < 8; tt++) {
            __half2 h01 = __floats2half2_rn(__expf(sacc[tt][0] - M0), __expf(sacc[tt][1] - M0));
            __half2 h23 = __floats2half2_rn(__expf(sacc[tt][2] - M1), __expf(sacc[tt][3] - M1));
            pf[tt >> 1][(tt & 1) * 2]     = *(uint32_t*)&h01;
            pf[tt >> 1][(tt & 1) * 2 + 1] = *(uint32_t*)&h23;
            float2 f01 = __half22float2(h01), f23 = __half22float2(h23);
            sl0 += f01.x + f01.y;
            sl1 += f23.x + f23.y;
        }

#pragma unroll
        for (int s = 0; s < 4; s++) {
#pragma unroll
            for (int i = 0; i < 8; i++) {
                uint32_t t0, t1, t2, t3;
                ldx4(t0, t1, t2, t3, vBase + (uint32_t)i * 16 * AVROW * 2 + s * 32);
                hmma(oacc[i * 2],     pf[s][0], pf[s][1], pf[s][2], pf[s][3], t0, t2);
                hmma(oacc[i * 2 + 1], pf[s][0], pf[s][1], pf[s][2], pf[s][3], t1, t3);
            }
        }
    }

    sl0 += __shfl_xor_sync(0xFFFFFFFF, sl0, 1);
    sl0 += __shfl_xor_sync(0xFFFFFFFF, sl0, 2);
    sl1 += __shfl_xor_sync(0xFFFFFFFF, sl1, 1);
    sl1 += __shfl_xor_sync(0xFFFFFFFF, sl1, 2);
    float inv0 = 1.f / sl0, inv1 = 1.f / sl1;

    int grow = qb * 64 + lrow;
#pragma unroll
    for (int i = 0; i < 16; i++) {
        int gcol = head * HD + dh * 128 + i * 8 + (lane & 3) * 2;
        *(__half2*)&act[(size_t)grow * QD + gcol] =
            __floats2half2_rn(oacc[i][0] * inv0, oacc[i][1] * inv0);
        *(__half2*)&act[(size_t)(grow + 8) * QD + gcol] =
            __floats2half2_rn(oacc[i][2] * inv1, oacc[i][3] * inv1);
    }
}

extern "C" void kernel_launch(void* const* d_in, const int* in_sizes, int n_in,
                              void* d_out, int out_size) {
    const float* hidden      = (const float*)d_in[0];
    const float* w_in        = (const float*)d_in[3];
    const float* w_post_attn = (const float*)d_in[4];
    const float* w_pre_ff    = (const float*)d_in[5];
    const float* w_post_ff   = (const float*)d_in[6];
    const float* wq          = (const float*)d_in[7];
    const float* wk          = (const float*)d_in[8];
    const float* wv          = (const float*)d_in[9];
    const float* wo          = (const float*)d_in[10];
    const float* w_gate      = (const float*)d_in[11];
    const float* w_up        = (const float*)d_in[12];
    const float* w_down      = (const float*)d_in[13];
    float* out = (float*)d_out;

    float *proj, *x1, *down;
    __half *qkvh, *act, *act2, *wt;
    cudaGetSymbolAddress((void**)&proj, g_proj);
    cudaGetSymbolAddress((void**)&x1, g_x1);
    cudaGetSymbolAddress((void**)&down, g_down);
    cudaGetSymbolAddress((void**)&qkvh, g_qkvh);
    cudaGetSymbolAddress((void**)&act, g_act);
    cudaGetSymbolAddress((void**)&act2, g_act2);
    cudaGetSymbolAddress((void**)&wt, g_wt);

    cudaFuncSetAttribute(gemm_mma, cudaFuncAttributeMaxDynamicSharedMemorySize, SMEM_MMA);
    cudaFuncSetAttribute(gemm_mma_h, cudaFuncAttributeMaxDynamicSharedMemorySize, SMEM_MMA);
    cudaFuncSetAttribute(gemm_swiglu, cudaFuncAttributeMaxDynamicSharedMemorySize, SMEM_MMA);
    cudaFuncSetAttribute(attn_mma_kernel, cudaFuncAttributeMaxDynamicSharedMemorySize, SMEM_ATT);
    cudaFuncSetAttribute(rmsnorm_pair_kernel, cudaFuncAttributeMaxDynamicSharedMemorySize, HDIM * 4);

    dim3 wtb(32, 8);

    // ---- attention block ----
    rmsnorm_h_kernel<<<SQ, 256>>>(hidden, w_in, act);
    convert_wt<<<dim3(QD/32,   HDIM/64), wtb>>>(wq, wt, HDIM, QD,   0);
    convert_wt<<<dim3(2048/32, HDIM/64), wtb>>>(wk, wt, HDIM, 2048, 4096);
    convert_wt<<<dim3(2048/32, HDIM/64), wtb>>>(wv, wt, HDIM, 2048, 6144);
    gemm_mma_h<<<dim3(SQ/BM, QKVD/BN), 256, SMEM_MMA>>>(act, wt, qkvh, QKVD, HDIM);
    rope_h_kernel<<<SQ * 24 * 64 / 256, 256>>>(qkvh);
    attn_mma_kernel<<<dim3(SQ/64, NH), 256, SMEM_ATT>>>(qkvh, act);
    convert_wt<<<dim3(HDIM/32, QD/64), wtb>>>(wo, wt, QD, HDIM, 0);
    gemm_mma<<<dim3(SQ/BM, HDIM/BN), 256, SMEM_MMA>>>(act, wt, proj, HDIM, QD);
    rmsnorm_pair_kernel<<<SQ, 256, HDIM * 4>>>(proj, w_post_attn, hidden, w_pre_ff, x1, act);

    // ---- MLP block ----
    convert_wt_swi<<<dim3(IDIM/32, HDIM/64), wtb>>>(w_gate, wt, HDIM, IDIM, 0);
    convert_wt_swi<<<dim3(IDIM/32, HDIM/64), wtb>>>(w_up,   wt, HDIM, IDIM, 1);
    gemm_swiglu<<<dim3(SQ/BM, 2*IDIM/BN), 256, SMEM_MMA>>>(act, wt, act2, HDIM);
    convert_wt<<<dim3(HDIM/32, IDIM/64), wtb>>>(w_down, wt, IDIM, HDIM, 0);
    gemm_mma<<<dim3(SQ/BM, HDIM/BN), 256, SMEM_MMA>>>(act2, wt, down, HDIM, IDIM);
    rmsnorm_kernel<<<SQ, 256>>>(down, w_post_ff, x1, out);
}

// round 15
// speedup vs baseline: 2.3153x; 1.0063x over previous
#include <cuda_runtime.h>
#include <cuda_fp16.h>
#include <math.h>
#include <stdint.h>

#define SQ 2048
#define HDIM 3584
#define NH 16
#define NKV 8
#define HD 256
#define QKVD 8192           // 4096 q + 2048 k + 2048 v
#define QD 4096
#define IDIM 14336

// ---------------- scratch (allocation-free: __device__ globals) ----------------
static __device__ float g_proj[SQ*HDIM];
static __device__ float g_x1[SQ*HDIM];
static __device__ float g_down[SQ*HDIM];
static __device__ __half g_qkvh[SQ*QKVD];                 // fp16 qkv
static __device__ __half g_act[(size_t)SQ*IDIM];          // GEMM A operand
static __device__ __half g_act2[(size_t)SQ*IDIM];         // swiglu output (down-GEMM A)
static __device__ __half g_wt[(size_t)(2*IDIM)*HDIM];     // B fp16 K-major

// ---------------- PTX helpers (arch-agnostic only: sm_80-level) ----------------
__device__ __forceinline__ uint32_t smem_u32(const void* p) {
    uint32_t a;
    asm("{ .reg .u64 t; cvta.to.shared.u64 t, %1; cvt.u32.u64 %0, t; }" : "=r"(a) : "l"(p));
    return a;
}
__device__ __forceinline__ void ldx4(uint32_t& r0, uint32_t& r1, uint32_t& r2, uint32_t& r3, uint32_t a) {
    asm volatile("ldmatrix.sync.aligned.m8n8.x4.shared.b16 {%0,%1,%2,%3}, [%4];"
                 : "=r"(r0), "=r"(r1), "=r"(r2), "=r"(r3) : "r"(a));
}
__device__ __forceinline__ void hmma(float* c, uint32_t a0, uint32_t a1, uint32_t a2, uint32_t a3,
                                     uint32_t b0, uint32_t b1) {
    asm volatile("mma.sync.aligned.m16n8k16.row.col.f32.f16.f16.f32 "
                 "{%0,%1,%2,%3},{%4,%5,%6,%7},{%8,%9},{%0,%1,%2,%3};"
                 : "+f"(c[0]), "+f"(c[1]), "+f"(c[2]), "+f"(c[3])
                 : "r"(a0), "r"(a1), "r"(a2), "r"(a3), "r"(b0), "r"(b1));
}
#define CP_ASYNC16(dst, src) \
    asm volatile("cp.async.cg.shared.global [%0], [%1], 16;" :: "r"(dst), "l"(src))
#define CP_COMMIT() asm volatile("cp.async.commit_group;" ::: "memory")
#define CP_WAIT(n)  asm volatile("cp.async.wait_group %0;" :: "n"(n) : "memory")

// ============ HMMA fp16 GEMM core config ============
#define BM 128
#define BN 128
#define BK 64
#define STG 3
#define ROWH 72
#define STAGE_A (BM*ROWH*2)
#define STAGE_B (STAGE_A + BN*ROWH*2)
#define SMEM_MMA (STG*STAGE_B)

#define GEMM_MAINLOOP(A_, B_, K_)                                                        \
    int lr = tid >> 3;                                                                   \
    int lc = (tid & 7) * 8;                                                              \
    const __half* gA0 = (A_) + (size_t)(m0 + lr) * (K_) + lc;                            \
    const __half* gB0 = (B_) + (size_t)(n0 + lr) * (K_) + lc;                            \
    uint32_t sOff = (uint32_t)(lr * ROWH + lc) * 2;                                      \
    uint32_t foff = (uint32_t)(((lane & 15) * ROWH) + ((lane >> 4) * 8)) * 2;            \
    float acc[4][4][4];                                                                  \
    _Pragma("unroll") for (int a = 0; a < 4; a++)                                        \
        _Pragma("unroll") for (int b = 0; b < 4; b++)                                    \
            _Pragma("unroll") for (int c = 0; c < 4; c++) acc[a][b][c] = 0.f;            \
    int ntiles = (K_) / BK;                                                              \
    auto LOAD = [&](int kt, int s) {                                                     \
        int ak = kt * BK;                                                                \
        uint32_t sA = sbase + s * STAGE_B;                                               \
        uint32_t sB = sA + STAGE_A;                                                      \
        _Pragma("unroll") for (int h = 0; h < 4; h++) {                                  \
            CP_ASYNC16(sA + sOff + h * 32 * ROWH * 2, gA0 + (size_t)h * 32 * (K_) + ak); \
            CP_ASYNC16(sB + sOff + h * 32 * ROWH * 2, gB0 + (size_t)h * 32 * (K_) + ak); \
        }                                                                                \
    };                                                                                   \
    _Pragma("unroll") for (int s = 0; s < STG - 1; s++) { LOAD(s, s); CP_COMMIT(); }     \
    for (int i = 0; i < ntiles; i++) {                                                   \
        CP_WAIT(STG - 2);                                                                \
        __syncthreads();                                                                 \
        int pf = i + STG - 1;                                                            \
        if (pf < ntiles) LOAD(pf, pf % STG);                                             \
        CP_COMMIT();                                                                     \
        int s = i % STG;                                                                 \
        uint32_t aB = sbase + s * STAGE_B;                                               \
        uint32_t bB = aB + STAGE_A;                                                      \
        uint32_t aAddr = aB + (uint32_t)wm * ROWH * 2 + foff;                            \
        uint32_t bAddr = bB + (uint32_t)wn * ROWH * 2 + foff;                            \
        _Pragma("unroll") for (int ks = 0; ks < 4; ks++) {                               \
            uint32_t af[4][4];                                                           \
            _Pragma("unroll") for (int fm = 0; fm < 4; fm++)                             \
                ldx4(af[fm][0], af[fm][1], af[fm][2], af[fm][3],                         \
                     aAddr + (uint32_t)fm * 16 * ROWH * 2 + ks * 32);                    \
            uint32_t t0, t1, t2, t3, t4, t5, t6, t7;                                     \
            ldx4(t0, t1, t2, t3, bAddr + ks * 32);                                       \
            ldx4(t4, t5, t6, t7, bAddr + 16 * ROWH * 2 + ks * 32);                       \
            uint32_t b0[4] = {t0, t1, t4, t5};                                           \
            uint32_t b1[4] = {t2, t3, t6, t7};                                           \
            _Pragma("unroll") for (int fm = 0; fm < 4; fm++)                             \
                _Pragma("unroll") for (int fn = 0; fn < 4; fn++)                         \
                    hmma(acc[fm][fn], af[fm][0], af[fm][1], af[fm][2], af[fm][3],        \
                         b0[fn], b1[fn]);                                                \
        }                                                                                \
    }

__global__ void __launch_bounds__(256, 2)
gemm_mma(const __half* __restrict__ A, const __half* __restrict__ B,
         float* __restrict__ C, int N, int K) {
    extern __shared__ char smem[];
    uint32_t sbase = smem_u32(smem);
    int tid = threadIdx.x, lane = tid & 31, wid = tid >> 5;
    int m0 = blockIdx.x * BM, n0 = blockIdx.y * BN;
    int wm = (wid & 1) * 64, wn = (wid >> 1) * 32;
    GEMM_MAINLOOP(A, B, K)
#pragma unroll
    for (int fm = 0; fm < 4; fm++) {
        int r = m0 + wm + fm * 16 + (lane >> 2);
#pragma unroll
        for (int fn = 0; fn < 4; fn++) {
            int c = n0 + wn + fn * 8 + (lane & 3) * 2;
            *(float2*)&C[(size_t)r * N + c]       = make_float2(acc[fm][fn][0], acc[fm][fn][1]);
            *(float2*)&C[(size_t)(r + 8) * N + c] = make_float2(acc[fm][fn][2], acc[fm][fn][3]);
        }
    }
}

// fp16-output GEMM (for qkv)
__global__ void __launch_bounds__(256, 2)
gemm_mma_h(const __half* __restrict__ A, const __half* __restrict__ B,
           __half* __restrict__ C, int N, int K) {
    extern __shared__ char smem[];
    uint32_t sbase = smem_u32(smem);
    int tid = threadIdx.x, lane = tid & 31, wid = tid >> 5;
    int m0 = blockIdx.x * BM, n0 = blockIdx.y * BN;
    int wm = (wid & 1) * 64, wn = (wid >> 1) * 32;
    GEMM_MAINLOOP(A, B, K)
#pragma unroll
    for (int fm = 0; fm < 4; fm++) {
        int r = m0 + wm + fm * 16 + (lane >> 2);
#pragma unroll
        for (int fn = 0; fn < 4; fn++) {
            int c = n0 + wn + fn * 8 + (lane & 3) * 2;
            *(__half2*)&C[(size_t)r * N + c]       = __floats2half2_rn(acc[fm][fn][0], acc[fm][fn][1]);
            *(__half2*)&C[(size_t)(r + 8) * N + c] = __floats2half2_rn(acc[fm][fn][2], acc[fm][fn][3]);
        }
    }
}

// gate/up GEMM with fused SwiGLU epilogue (interleaved B rows)
__global__ void __launch_bounds__(256, 2)
gemm_swiglu(const __half* __restrict__ A, const __half* __restrict__ B,
            __half* __restrict__ O, int K) {
    extern __shared__ char smem[];
    uint32_t sbase = smem_u32(smem);
    int tid = threadIdx.x, lane = tid & 31, wid = tid >> 5;
    int m0 = blockIdx.x * BM, n0 = blockIdx.y * BN;
    int wm = (wid & 1) * 64, wn = (wid >> 1) * 32;
    GEMM_MAINLOOP(A, B, K)
    __syncthreads();
    float* Cs = (float*)smem;              // [128][132]
#pragma unroll
    for (int fm = 0; fm < 4; fm++) {
        int r = wm + fm * 16 + (lane >> 2);
#pragma unroll
        for (int fn = 0; fn < 4; fn++) {
            int c = wn + fn * 8 + (lane & 3) * 2;
            *(float2*)&Cs[r * 132 + c]       = make_float2(acc[fm][fn][0], acc[fm][fn][1]);
            *(float2*)&Cs[(r + 8) * 132 + c] = make_float2(acc[fm][fn][2], acc[fm][fn][3]);
        }
    }
    __syncthreads();
    int colb = blockIdx.y * 64;
    for (int idx = tid; idx < 128 * 32; idx += 256) {
        int r = idx >> 5, c = (idx & 31) * 2;
        float2 g = *(float2*)&Cs[r * 132 + c];
        float2 u = *(float2*)&Cs[r * 132 + 64 + c];
        float t0 = tanhf(0.7978845608028654f * (g.x + 0.044715f * g.x * g.x * g.x));
        float t1 = tanhf(0.7978845608028654f * (g.y + 0.044715f * g.y * g.y * g.y));
        float v0 = 0.5f * g.x * (1.f + t0) * u.x;
        float v1 = 0.5f * g.y * (1.f + t1) * u.y;
        *(__half2*)&O[(size_t)(m0 + r) * IDIM + colb + c] =
            __halves2half2(__float2half(v0), __float2half(v1));
    }
}

// ===== W[K,N] fp32 -> out[n_off+n][k] fp16 K-major; 64n x 64k tiles, float4 reads =====
__global__ void convert_wt(const float* __restrict__ W, __half* __restrict__ out,
                           int K, int N, int n_off) {
    __shared__ float tile[64][65];     // [n][k]
    int n0 = blockIdx.x * 64, k0 = blockIdx.y * 64;
    int tid = threadIdx.x;             // 256
#pragma unroll
    for (int r = 0; r < 4; r++) {
        int idx = r * 256 + tid;
        int k = idx >> 4, n4 = (idx & 15) * 4;
        float4 v = *(const float4*)&W[(size_t)(k0 + k) * N + n0 + n4];
        tile[n4 + 0][k] = v.x;
        tile[n4 + 1][k] = v.y;
        tile[n4 + 2][k] = v.z;
        tile[n4 + 3][k] = v.w;
    }
    __syncthreads();
#pragma unroll
    for (int r = 0; r < 8; r++) {
        int idx = r * 256 + tid;
        int n = idx >> 5, kh = (idx & 31) * 2;
        *(__half2*)&out[(size_t)(n_off + n0 + n) * K + k0 + kh] =
            __floats2half2_rn(tile[n][kh], tile[n][kh + 1]);
    }
}

// gate/up interleaved convert: row -> (n/64)*128 + which*64 + (n%64); 64n x 64k tiles
__global__ void convert_wt_swi(const float* __restrict__ W, __half* __restrict__ out,
                               int K, int N, int which) {
    __shared__ float tile[64][65];
    int n0 = blockIdx.x * 64, k0 = blockIdx.y * 64;
    int tid = threadIdx.x;
#pragma unroll
    for (int r = 0; r < 4; r++) {
        int idx = r * 256 + tid;
        int k = idx >> 4, n4 = (idx & 15) * 4;
        float4 v = *(const float4*)&W[(size_t)(k0 + k) * N + n0 + n4];
        tile[n4 + 0][k] = v.x;
        tile[n4 + 1][k] = v.y;
        tile[n4 + 2][k] = v.z;
        tile[n4 + 3][k] = v.w;
    }
    __syncthreads();
    size_t rowb = (size_t)blockIdx.x * 128 + which * 64;   // ng>>6 == blockIdx.x
#pragma unroll
    for (int r = 0; r < 8; r++) {
        int idx = r * 256 + tid;
        int n = idx >> 5, kh = (idx & 31) * 2;
        *(__half2*)&out[(rowb + n) * K + k0 + kh] =
            __floats2half2_rn(tile[n][kh], tile[n][kh + 1]);
    }
}

// ===== RMSNorm writing fp16 directly =====
__global__ void rmsnorm_h_kernel(const float* __restrict__ in, const float* __restrict__ w,
                                 __half* __restrict__ act) {
    int row = blockIdx.x;
    const float* x = in + (size_t)row * HDIM;
    float ss = 0.f;
    for (int c = threadIdx.x; c < HDIM; c += 256) { float v = x[c]; ss += v * v; }
    __shared__ float red[256];
    red[threadIdx.x] = ss;
    __syncthreads();
    for (int s = 128; s > 0; s >>= 1) {
        if (threadIdx.x < s) red[threadIdx.x] += red[threadIdx.x + s];
        __syncthreads();
    }
    float scale = rsqrtf(red[0] / (float)HDIM + 1e-6f);
    for (int c = threadIdx.x * 2; c < HDIM; c += 512) {
        float v0 = x[c] * scale * w[c];
        float v1 = x[c + 1] * scale * w[c + 1];
        *(__half2*)(act + (size_t)row * HDIM + c) =
            __halves2half2(__float2half(v0), __float2half(v1));
    }
}

// ===== fused: x1 = resid + rmsnorm(in, w1);  act = fp16(rmsnorm(x1, w2)) =====
__global__ void rmsnorm_pair_kernel(const float* __restrict__ in, const float* __restrict__ w1,
                                    const float* __restrict__ resid, const float* __restrict__ w2,
                                    float* __restrict__ x1, __half* __restrict__ act) {
    extern __shared__ float buf[];   // HDIM floats
    __shared__ float red[256];
    int row = blockIdx.x, t = threadIdx.x;
    const float* x = in + (size_t)row * HDIM;
    float ss = 0.f;
    for (int c = t; c < HDIM; c += 256) { float v = x[c]; buf[c] = v; ss += v * v; }
    red[t] = ss;
    __syncthreads();
    for (int s = 128; s > 0; s >>= 1) {
        if (t < s) red[t] += red[t + s];
        __syncthreads();
    }
    float scale = rsqrtf(red[0] / (float)HDIM + 1e-6f);
    __syncthreads();
    float ss2 = 0.f;
    for (int c = t; c < HDIM; c += 256) {
        float v = buf[c] * scale * w1[c] + resid[(size_t)row * HDIM + c];
        buf[c] = v;
        x1[(size_t)row * HDIM + c] = v;
        ss2 += v * v;
    }
    red[t] = ss2;
    __syncthreads();
    for (int s = 128; s > 0; s >>= 1) {
        if (t < s) red[t] += red[t + s];
        __syncthreads();
    }
    float scale2 = rsqrtf(red[0] / (float)HDIM + 1e-6f);
    for (int c = t * 2; c < HDIM; c += 512) {
        float v0 = buf[c] * scale2 * w2[c];
        float v1 = buf[c + 1] * scale2 * w2[c + 1];
        *(__half2*)(act + (size_t)row * HDIM + c) =
            __halves2half2(__float2half(v0), __float2half(v1));
    }
}

// ================= RMSNorm fp32 out (+ residual) =================
__global__ void rmsnorm_kernel(const float* __restrict__ in, const float* __restrict__ w,
                               const float* __restrict__ resid, float* __restrict__ out) {
    int row = blockIdx.x;
    const float* x = in + (size_t)row * HDIM;
    float ss = 0.f;
    for (int c = threadIdx.x; c < HDIM; c += 256) { float v = x[c]; ss += v * v; }
    __shared__ float red[256];
    red[threadIdx.x] = ss;
    __syncthreads();
    for (int s = 128; s > 0; s >>= 1) {
        if (threadIdx.x < s) red[threadIdx.x] += red[threadIdx.x + s];
        __syncthreads();
    }
    float scale = rsqrtf(red[0] / (float)HDIM + 1e-6f);
    for (int c = threadIdx.x; c < HDIM; c += 256) {
        float v = x[c] * scale * w[c];
        if (resid) v += resid[(size_t)row * HDIM + c];
        out[(size_t)row * HDIM + c] = v;
    }
}

// ================= RoPE in-place on fp16 qkv [2048, 8192] =================
__global__ void rope_h_kernel(__half* __restrict__ x) {
    int idx = blockIdx.x * 256 + threadIdx.x;   // over 2048*24*64
    int d2 = (idx & 63) * 2;
    int hh = (idx >> 6) % 24;
    int s = idx / (64 * 24);
    int col = (hh < 16) ? hh * 256 : 4096 + (hh - 16) * 256;
    size_t base = (size_t)s * QKVD + col;
    float2 a = __half22float2(*(__half2*)(x + base + d2));
    float2 b = __half22float2(*(__half2*)(x + base + d2 + 128));
    float c0, s0, c1, s1;
    {
        float invf = (float)exp(-((double)(2 * d2) / (double)HD) * log(10000.0));
        float ang = (float)s * invf;
        c0 = (float)cos((double)ang); s0 = (float)sin((double)ang);
    }
    {
        float invf = (float)exp(-((double)(2 * (d2 + 1)) / (double)HD) * log(10000.0));
        float ang = (float)s * invf;
        c1 = (float)cos((double)ang); s1 = (float)sin((double)ang);
    }
    *(__half2*)(x + base + d2)       = __floats2half2_rn(a.x * c0 - b.x * s0, a.y * c1 - b.y * s1);
    *(__half2*)(x + base + d2 + 128) = __floats2half2_rn(b.x * c0 + a.x * s0, b.y * c1 + a.y * s1);
}

// ====== HMMA flash attention: softcap + online softmax (FA2), causal; fp16 in/out ======
#define AQROW 264
#define AVROW 72
#define SMEM_ATT ((64*AQROW*2 + 256*AVROW) * 2)   // 104448 bytes

__global__ void __launch_bounds__(256, 1)
attn_mma_kernel(const __half* __restrict__ qkv, __half* __restrict__ act) {
    extern __shared__ __half hsm[];
    __half* Qs = hsm;
    __half* Ks = hsm + 64 * AQROW;
    __half* Vs = hsm + 128 * AQROW;

    int qb = gridDim.x - 1 - blockIdx.x;   // longest-first scheduling
    int head = blockIdx.y, kvh = head >> 1;
    int t = threadIdx.x, lane = t & 31, wid = t >> 5;
    int rg = wid & 3, dh = wid >> 2;

    for (int idx = t; idx < 64 * 32; idx += 256) {
        int i = idx >> 5, ch = (idx & 31) * 8;
        *(uint4*)&Qs[i * AQROW + ch] =
            *(const uint4*)&qkv[(size_t)(qb * 64 + i) * QKVD + head * HD + ch];
    }

    float oacc[16][4];
#pragma unroll
    for (int i = 0; i < 16; i++)
#pragma unroll
        for (int e = 0; e < 4; e++) oacc[i][e] = 0.f;
    float sl0 = 0.f, sl1 = 0.f;
    float M0 = -1e30f, M1 = -1e30f;

    uint32_t qAddr = smem_u32(Qs) + (uint32_t)((rg * 16 + (lane & 15)) * AQROW + (lane >> 4) * 8) * 2;
    uint32_t kBase = smem_u32(Ks) + (uint32_t)((lane & 15) * AQROW + (lane >> 4) * 8) * 2;
    uint32_t vBase = smem_u32(Vs) + (uint32_t)((dh * 128 + (lane & 15)) * AVROW + (lane >> 4) * 8) * 2;

    int lrow = rg * 16 + (lane >> 2);

    for (int kb = 0; kb <= qb; kb++) {
        __syncthreads();
        for (int idx = t; idx < 64 * 32; idx += 256) {
            int j = idx >> 5, ch = (idx & 31) * 8;
            *(uint4*)&Ks[j * AQROW + ch] =
                *(const uint4*)&qkv[(size_t)(kb * 64 + j) * QKVD + 4096 + kvh * HD + ch];
        }
        for (int idx = t; idx < 64 * 64; idx += 256) {
            int j = idx >> 6, c = (idx & 63) * 4;
            const __half* gv = &qkv[(size_t)(kb * 64 + j) * QKVD + 6144 + kvh * HD + c];
            __half2 v01 = *(const __half2*)gv;
            __half2 v23 = *(const __half2*)(gv + 2);
            Vs[(c + 0) * AVROW + j] = __low2half(v01);
            Vs[(c + 1) * AVROW + j] = __high2half(v01);
            Vs[(c + 2) * AVROW + j] = __low2half(v23);
            Vs[(c + 3) * AVROW + j] = __high2half(v23);
        }
        __syncthreads();

        float sacc[8][4];
#pragma unroll
        for (int i = 0; i < 8; i++)
#pragma unroll
            for (int e = 0; e < 4; e++) sacc[i][e] = 0.f;
#pragma unroll
        for (int ks = 0; ks < 16; ks++) {
            uint32_t a0, a1, a2, a3;
            ldx4(a0, a1, a2, a3, qAddr + ks * 32);
#pragma unroll
            for (int jt = 0; jt < 4; jt++) {
                uint32_t t0, t1, t2, t3;
                ldx4(t0, t1, t2, t3, kBase + (uint32_t)jt * 16 * AQROW * 2 + ks * 32);
                hmma(sacc[jt * 2],     a0, a1, a2, a3, t0, t2);
                hmma(sacc[jt * 2 + 1], a0, a1, a2, a3, t1, t3);
            }
        }

        bool diag = (kb == qb);
#pragma unroll
        for (int tt = 0; tt < 8; tt++) {
            int colb = tt * 8 + (lane & 3) * 2;
#pragma unroll
            for (int e = 0; e < 4; e++) {
                float sc = sacc[tt][e] * 0.0625f;
                sc = tanhf(sc * 0.02f) * 50.f;
                bool valid = !diag || (colb + (e & 1) <= lrow + (e >> 1) * 8);
                sacc[tt][e] = valid ? sc : -1e30f;
            }
        }

        float m0 = -1e30f, m1 = -1e30f;
#pragma unroll
        for (int tt = 0; tt < 8; tt++) {
            m0 = fmaxf(m0, fmaxf(sacc[tt][0], sacc[tt][1]));
            m1 = fmaxf(m1, fmaxf(sacc[tt][2], sacc[tt][3]));
        }
        m0 = fmaxf(m0, __shfl_xor_sync(0xFFFFFFFF, m0, 1));
        m0 = fmaxf(m0, __shfl_xor_sync(0xFFFFFFFF, m0, 2));
        m1 = fmaxf(m1, __shfl_xor_sync(0xFFFFFFFF, m1, 1));
        m1 = fmaxf(m1, __shfl_xor_sync(0xFFFFFFFF, m1, 2));
        float nM0 = fmaxf(M0, m0), nM1 = fmaxf(M1, m1);
        float f0 = __expf(M0 - nM0), f1 = __expf(M1 - nM1);
        M0 = nM0; M1 = nM1;
        sl0 *= f0; sl1 *= f1;
#pragma unroll
        for (int i = 0; i < 16; i++) {
            oacc[i][0] *= f0; oacc[i][1] *= f0;
            oacc[i][2] *= f1; oacc[i][3] *= f1;
        }

        uint32_t pf[4][4];
#pragma unroll
        for (int tt = 0; tt < 8; tt++) {
            __half2 h01 = __floats2half2_rn(__expf(sacc[tt][0] - M0), __expf(sacc[tt][1] - M0));
            __half2 h23 = __floats2half2_rn(__expf(sacc[tt][2] - M1), __expf(sacc[tt][3] - M1));
            pf[tt >> 1][(tt & 1) * 2]     = *(uint32_t*)&h01;
            pf[tt >> 1][(tt & 1) * 2 + 1] = *(uint32_t*)&h23;
            float2 f01 = __half22float2(h01), f23 = __half22float2(h23);
            sl0 += f01.x + f01.y;
            sl1 += f23.x + f23.y;
        }

#pragma unroll
        for (int s = 0; s < 4; s++) {
#pragma unroll
            for (int i = 0; i < 8; i++) {
                uint32_t t0, t1, t2, t3;
                ldx4(t0, t1, t2, t3, vBase + (uint32_t)i * 16 * AVROW * 2 + s * 32);
                hmma(oacc[i * 2],     pf[s][0], pf[s][1], pf[s][2], pf[s][3], t0, t2);
                hmma(oacc[i * 2 + 1], pf[s][0], pf[s][1], pf[s][2], pf[s][3], t1, t3);
            }
        }
    }

    sl0 += __shfl_xor_sync(0xFFFFFFFF, sl0, 1);
    sl0 += __shfl_xor_sync(0xFFFFFFFF, sl0, 2);
    sl1 += __shfl_xor_sync(0xFFFFFFFF, sl1, 1);
    sl1 += __shfl_xor_sync(0xFFFFFFFF, sl1, 2);
    float inv0 = 1.f / sl0, inv1 = 1.f / sl1;

    int grow = qb * 64 + lrow;
#pragma unroll
    for (int i = 0; i < 16; i++) {
        int gcol = head * HD + dh * 128 + i * 8 + (lane & 3) * 2;
        *(__half2*)&act[(size_t)grow * QD + gcol] =
            __floats2half2_rn(oacc[i][0] * inv0, oacc[i][1] * inv0);
        *(__half2*)&act[(size_t)(grow + 8) * QD + gcol] =
            __floats2half2_rn(oacc[i][2] * inv1, oacc[i][3] * inv1);
    }
}

extern "C" void kernel_launch(void* const* d_in, const int* in_sizes, int n_in,
                              void* d_out, int out_size) {
    const float* hidden      = (const float*)d_in[0];
    const float* w_in        = (const float*)d_in[3];
    const float* w_post_attn = (const float*)d_in[4];
    const float* w_pre_ff    = (const float*)d_in[5];
    const float* w_post_ff   = (const float*)d_in[6];
    const float* wq          = (const float*)d_in[7];
    const float* wk          = (const float*)d_in[8];
    const float* wv          = (const float*)d_in[9];
    const float* wo          = (const float*)d_in[10];
    const float* w_gate      = (const float*)d_in[11];
    const float* w_up        = (const float*)d_in[12];
    const float* w_down      = (const float*)d_in[13];
    float* out = (float*)d_out;

    float *proj, *x1, *down;
    __half *qkvh, *act, *act2, *wt;
    cudaGetSymbolAddress((void**)&proj, g_proj);
    cudaGetSymbolAddress((void**)&x1, g_x1);
    cudaGetSymbolAddress((void**)&down, g_down);
    cudaGetSymbolAddress((void**)&qkvh, g_qkvh);
    cudaGetSymbolAddress((void**)&act, g_act);
    cudaGetSymbolAddress((void**)&act2, g_act2);
    cudaGetSymbolAddress((void**)&wt, g_wt);

    cudaFuncSetAttribute(gemm_mma, cudaFuncAttributeMaxDynamicSharedMemorySize, SMEM_MMA);
    cudaFuncSetAttribute(gemm_mma_h, cudaFuncAttributeMaxDynamicSharedMemorySize, SMEM_MMA);
    cudaFuncSetAttribute(gemm_swiglu, cudaFuncAttributeMaxDynamicSharedMemorySize, SMEM_MMA);
    cudaFuncSetAttribute(attn_mma_kernel, cudaFuncAttributeMaxDynamicSharedMemorySize, SMEM_ATT);
    cudaFuncSetAttribute(rmsnorm_pair_kernel, cudaFuncAttributeMaxDynamicSharedMemorySize, HDIM * 4);

    // ---- attention block ----
    rmsnorm_h_kernel<<<SQ, 256>>>(hidden, w_in, act);
    convert_wt<<<dim3(QD/64,   HDIM/64), 256>>>(wq, wt, HDIM, QD,   0);
    convert_wt<<<dim3(2048/64, HDIM/64), 256>>>(wk, wt, HDIM, 2048, 4096);
    convert_wt<<<dim3(2048/64, HDIM/64), 256>>>(wv, wt, HDIM, 2048, 6144);
    gemm_mma_h<<<dim3(SQ/BM, QKVD/BN), 256, SMEM_MMA>>>(act, wt, qkvh, QKVD, HDIM);
    rope_h_kernel<<<SQ * 24 * 64 / 256, 256>>>(qkvh);
    attn_mma_kernel<<<dim3(SQ/64, NH), 256, SMEM_ATT>>>(qkvh, act);
    convert_wt<<<dim3(HDIM/64, QD/64), 256>>>(wo, wt, QD, HDIM, 0);
    gemm_mma<<<dim3(SQ/BM, HDIM/BN), 256, SMEM_MMA>>>(act, wt, proj, HDIM, QD);
    rmsnorm_pair_kernel<<<SQ, 256, HDIM * 4>>>(proj, w_post_attn, hidden, w_pre_ff, x1, act);

    // ---- MLP block ----
    convert_wt_swi<<<dim3(IDIM/64, HDIM/64), 256>>>(w_gate, wt, HDIM, IDIM, 0);
    convert_wt_swi<<<dim3(IDIM/64, HDIM/64), 256>>>(w_up,   wt, HDIM, IDIM, 1);
    gemm_swiglu<<<dim3(SQ/BM, 2*IDIM/BN), 256, SMEM_MMA>>>(act, wt, act2, HDIM);
    convert_wt<<<dim3(HDIM/64, IDIM/64), 256>>>(w_down, wt, IDIM, HDIM, 0);
    gemm_mma<<<dim3(SQ/BM, HDIM/BN), 256, SMEM_MMA>>>(act2, wt, down, HDIM, IDIM);
    rmsnorm_kernel<<<SQ, 256>>>(down, w_post_ff, x1, out);
}

// round 16
// speedup vs baseline: 2.4627x; 1.0637x over previous
#include <cuda_runtime.h>
#include <cuda_fp16.h>
#include <math.h>
#include <stdint.h>

#define SQ 2048
#define HDIM 3584
#define NH 16
#define NKV 8
#define HD 256
#define QKVD 8192           // 4096 q + 2048 k + 2048 v
#define QD 4096
#define IDIM 14336

// ---------------- scratch (allocation-free: __device__ globals) ----------------
static __device__ float g_proj[SQ*HDIM];
static __device__ float g_x1[SQ*HDIM];
static __device__ float g_down[SQ*HDIM];
static __device__ __half g_qkvh[SQ*QKVD];                 // fp16 qkv
static __device__ __half g_act[(size_t)SQ*IDIM];          // GEMM A operand
static __device__ __half g_act2[(size_t)SQ*IDIM];         // swiglu output (down-GEMM A)
static __device__ __half g_wt[(size_t)IDIM*2*HDIM];       // B fp16 [K][N] natural layout

// ---------------- PTX helpers (arch-agnostic only: sm_80-level) ----------------
__device__ __forceinline__ uint32_t smem_u32(const void* p) {
    uint32_t a;
    asm("{ .reg .u64 t; cvta.to.shared.u64 t, %1; cvt.u32.u64 %0, t; }" : "=r"(a) : "l"(p));
    return a;
}
__device__ __forceinline__ void ldx4(uint32_t& r0, uint32_t& r1, uint32_t& r2, uint32_t& r3, uint32_t a) {
    asm volatile("ldmatrix.sync.aligned.m8n8.x4.shared.b16 {%0,%1,%2,%3}, [%4];"
                 : "=r"(r0), "=r"(r1), "=r"(r2), "=r"(r3) : "r"(a));
}
__device__ __forceinline__ void ldx4t(uint32_t& r0, uint32_t& r1, uint32_t& r2, uint32_t& r3, uint32_t a) {
    asm volatile("ldmatrix.sync.aligned.m8n8.x4.trans.shared.b16 {%0,%1,%2,%3}, [%4];"
                 : "=r"(r0), "=r"(r1), "=r"(r2), "=r"(r3) : "r"(a));
}
__device__ __forceinline__ void hmma(float* c, uint32_t a0, uint32_t a1, uint32_t a2, uint32_t a3,
                                     uint32_t b0, uint32_t b1) {
    asm volatile("mma.sync.aligned.m16n8k16.row.col.f32.f16.f16.f32 "
                 "{%0,%1,%2,%3},{%4,%5,%6,%7},{%8,%9},{%0,%1,%2,%3};"
                 : "+f"(c[0]), "+f"(c[1]), "+f"(c[2]), "+f"(c[3])
                 : "r"(a0), "r"(a1), "r"(a2), "r"(a3), "r"(b0), "r"(b1));
}
#define CP_ASYNC16(dst, src) \
    asm volatile("cp.async.cg.shared.global [%0], [%1], 16;" :: "r"(dst), "l"(src))
#define CP_COMMIT() asm volatile("cp.async.commit_group;" ::: "memory")
#define CP_WAIT(n)  asm volatile("cp.async.wait_group %0;" :: "n"(n) : "memory")

// ============ HMMA fp16 GEMM: C[M,N] = A[M,K] @ B[K,N] (B natural row-major) ============
#define BM 128
#define BN 128
#define BK 64
#define STG 3
#define ROWH 72                               // A smem row: 64 + 8 pad halves
#define BROWH 136                             // B smem row: 128 + 8 pad halves
#define STAGE_A (BM*ROWH*2)                   // 18432
#define STAGE_BB (BK*BROWH*2)                 // 17408
#define STAGE_TOT (STAGE_A + STAGE_BB)        // 35840
#define SMEM_MMA (STG*STAGE_TOT)              // 107520

#define GEMM_MAINLOOP(A_, B_, N_, K_)                                                     \
    int lrA = tid >> 3, lcA = (tid & 7) * 8;                                              \
    const __half* gA0 = (A_) + (size_t)(m0 + lrA) * (K_) + lcA;                           \
    uint32_t sOffA = (uint32_t)(lrA * ROWH + lcA) * 2;                                    \
    int lrB = tid >> 4, lcB = (tid & 15) * 8;                                             \
    const __half* gB0 = (B_) + (size_t)lrB * (N_) + n0 + lcB;                             \
    uint32_t sOffB = (uint32_t)(lrB * BROWH + lcB) * 2;                                   \
    uint32_t foffA = (uint32_t)(((lane & 15) * ROWH) + ((lane >> 4) * 8)) * 2;            \
    uint32_t foffB = (uint32_t)(((lane & 15) * BROWH) + ((lane >> 4) * 8)) * 2;           \
    float acc[4][4][4];                                                                   \
    _Pragma("unroll") for (int a = 0; a < 4; a++)                                         \
        _Pragma("unroll") for (int b = 0; b < 4; b++)                                     \
            _Pragma("unroll") for (int c = 0; c < 4; c++) acc[a][b][c] = 0.f;             \
    int ntiles = (K_) / BK;                                                               \
    auto LOAD = [&](int kt, int s) {                                                      \
        int ak = kt * BK;                                                                 \
        uint32_t sA = sbase + s * STAGE_TOT;                                              \
        uint32_t sB = sA + STAGE_A;                                                       \
        _Pragma("unroll") for (int h = 0; h < 4; h++)                                     \
            CP_ASYNC16(sA + sOffA + h * 32 * ROWH * 2, gA0 + (size_t)h * 32 * (K_) + ak); \
        _Pragma("unroll") for (int h = 0; h < 4; h++)                                     \
            CP_ASYNC16(sB + sOffB + h * 16 * BROWH * 2, gB0 + (size_t)(ak + h * 16) * (N_)); \
    };                                                                                    \
    _Pragma("unroll") for (int s = 0; s < STG - 1; s++) { LOAD(s, s); CP_COMMIT(); }      \
    for (int i = 0; i < ntiles; i++) {                                                    \
        CP_WAIT(STG - 2);                                                                 \
        __syncthreads();                                                                  \
        int pf = i + STG - 1;                                                             \
        if (pf < ntiles) LOAD(pf, pf % STG);                                              \
        CP_COMMIT();                                                                      \
        int s = i % STG;                                                                  \
        uint32_t aB = sbase + s * STAGE_TOT;                                              \
        uint32_t bB = aB + STAGE_A;                                                       \
        uint32_t aAddr = aB + (uint32_t)wm * ROWH * 2 + foffA;                            \
        uint32_t bAddr = bB + (uint32_t)wn * 2 + foffB;                                   \
        _Pragma("unroll") for (int ks = 0; ks < 4; ks++) {                                \
            uint32_t af[4][4];                                                            \
            _Pragma("unroll") for (int fm = 0; fm < 4; fm++)                              \
                ldx4(af[fm][0], af[fm][1], af[fm][2], af[fm][3],                          \
                     aAddr + (uint32_t)fm * 16 * ROWH * 2 + ks * 32);                     \
            uint32_t base = bAddr + (uint32_t)ks * 16 * BROWH * 2;                        \
            uint32_t t0, t1, t2, t3, t4, t5, t6, t7;                                      \
            ldx4t(t0, t1, t2, t3, base);                                                  \
            ldx4t(t4, t5, t6, t7, base + 32);                                             \
            uint32_t b0[4] = {t0, t2, t4, t6};                                            \
            uint32_t b1[4] = {t1, t3, t5, t7};                                            \
            _Pragma("unroll") for (int fm = 0; fm < 4; fm++)                              \
                _Pragma("unroll") for (int fn = 0; fn < 4; fn++)                          \
                    hmma(acc[fm][fn], af[fm][0], af[fm][1], af[fm][2], af[fm][3],         \
                         b0[fn], b1[fn]);                                                 \
        }                                                                                 \
    }

__global__ void __launch_bounds__(256, 2)
gemm_mma(const __half* __restrict__ A, const __half* __restrict__ B,
         float* __restrict__ C, int N, int K) {
    extern __shared__ char smem[];
    uint32_t sbase = smem_u32(smem);
    int tid = threadIdx.x, lane = tid & 31, wid = tid >> 5;
    int m0 = blockIdx.x * BM, n0 = blockIdx.y * BN;
    int wm = (wid & 1) * 64, wn = (wid >> 1) * 32;
    GEMM_MAINLOOP(A, B, N, K)
#pragma unroll
    for (int fm = 0; fm < 4; fm++) {
        int r = m0 + wm + fm * 16 + (lane >> 2);
#pragma unroll
        for (int fn = 0; fn < 4; fn++) {
            int c = n0 + wn + fn * 8 + (lane & 3) * 2;
            *(float2*)&C[(size_t)r * N + c]       = make_float2(acc[fm][fn][0], acc[fm][fn][1]);
            *(float2*)&C[(size_t)(r + 8) * N + c] = make_float2(acc[fm][fn][2], acc[fm][fn][3]);
        }
    }
}

// fp16-output GEMM (for qkv)
__global__ void __launch_bounds__(256, 2)
gemm_mma_h(const __half* __restrict__ A, const __half* __restrict__ B,
           __half* __restrict__ C, int N, int K) {
    extern __shared__ char smem[];
    uint32_t sbase = smem_u32(smem);
    int tid = threadIdx.x, lane = tid & 31, wid = tid >> 5;
    int m0 = blockIdx.x * BM, n0 = blockIdx.y * BN;
    int wm = (wid & 1) * 64, wn = (wid >> 1) * 32;
    GEMM_MAINLOOP(A, B, N, K)
#pragma unroll
    for (int fm = 0; fm < 4; fm++) {
        int r = m0 + wm + fm * 16 + (lane >> 2);
#pragma unroll
        for (int fn = 0; fn < 4; fn++) {
            int c = n0 + wn + fn * 8 + (lane & 3) * 2;
            *(__half2*)&C[(size_t)r * N + c]       = __floats2half2_rn(acc[fm][fn][0], acc[fm][fn][1]);
            *(__half2*)&C[(size_t)(r + 8) * N + c] = __floats2half2_rn(acc[fm][fn][2], acc[fm][fn][3]);
        }
    }
}

// gate/up GEMM with fused SwiGLU epilogue (column-interleaved B)
__global__ void __launch_bounds__(256, 2)
gemm_swiglu(const __half* __restrict__ A, const __half* __restrict__ B,
            __half* __restrict__ O, int K) {
    extern __shared__ char smem[];
    uint32_t sbase = smem_u32(smem);
    int tid = threadIdx.x, lane = tid & 31, wid = tid >> 5;
    int m0 = blockIdx.x * BM, n0 = blockIdx.y * BN;
    int wm = (wid & 1) * 64, wn = (wid >> 1) * 32;
    GEMM_MAINLOOP(A, B, 2 * IDIM, K)
    __syncthreads();
    float* Cs = (float*)smem;              // [128][132]
#pragma unroll
    for (int fm = 0; fm < 4; fm++) {
        int r = wm + fm * 16 + (lane >> 2);
#pragma unroll
        for (int fn = 0; fn < 4; fn++) {
            int c = wn + fn * 8 + (lane & 3) * 2;
            *(float2*)&Cs[r * 132 + c]       = make_float2(acc[fm][fn][0], acc[fm][fn][1]);
            *(float2*)&Cs[(r + 8) * 132 + c] = make_float2(acc[fm][fn][2], acc[fm][fn][3]);
        }
    }
    __syncthreads();
    int colb = blockIdx.y * 64;
    for (int idx = tid; idx < 128 * 32; idx += 256) {
        int r = idx >> 5, c = (idx & 31) * 2;
        float2 g = *(float2*)&Cs[r * 132 + c];
        float2 u = *(float2*)&Cs[r * 132 + 64 + c];
        float t0 = tanhf(0.7978845608028654f * (g.x + 0.044715f * g.x * g.x * g.x));
        float t1 = tanhf(0.7978845608028654f * (g.y + 0.044715f * g.y * g.y * g.y));
        float v0 = 0.5f * g.x * (1.f + t0) * u.x;
        float v1 = 0.5f * g.y * (1.f + t1) * u.y;
        *(__half2*)&O[(size_t)(m0 + r) * IDIM + colb + c] =
            __halves2half2(__float2half(v0), __float2half(v1));
    }
}

// ===== elementwise fp32 -> fp16 cast, natural [K][N] layout, column offset =====
__global__ void convert_wt(const float* __restrict__ W, __half* __restrict__ out,
                           int N, int NOUT, int n_off) {
    size_t idx = (size_t)blockIdx.x * 256 + threadIdx.x;   // over K*N/4
    int nq = N >> 2;
    int k = (int)(idx / nq);
    int n4 = (int)(idx - (size_t)k * nq) * 4;
    float4 v = *(const float4*)&W[(size_t)k * N + n4];
    __half* o = out + (size_t)k * NOUT + n_off + n4;
    *(__half2*)o       = __floats2half2_rn(v.x, v.y);
    *(__half2*)(o + 2) = __floats2half2_rn(v.z, v.w);
}

// gate/up column-interleaved cast: col n -> (n/64)*128 + which*64 + (n%64)
__global__ void convert_wt_swi(const float* __restrict__ W, __half* __restrict__ out,
                               int N, int which) {
    size_t idx = (size_t)blockIdx.x * 256 + threadIdx.x;
    int nq = N >> 2;
    int k = (int)(idx / nq);
    int n4 = (int)(idx - (size_t)k * nq) * 4;
    float4 v = *(const float4*)&W[(size_t)k * N + n4];
    int ncol = (n4 >> 6) * 128 + which * 64 + (n4 & 63);
    __half* o = out + (size_t)k * (2 * IDIM) + ncol;
    *(__half2*)o       = __floats2half2_rn(v.x, v.y);
    *(__half2*)(o + 2) = __floats2half2_rn(v.z, v.w);
}

// ===== RMSNorm writing fp16 directly =====
__global__ void rmsnorm_h_kernel(const float* __restrict__ in, const float* __restrict__ w,
                                 __half* __restrict__ act) {
    int row = blockIdx.x;
    const float* x = in + (size_t)row * HDIM;
    float ss = 0.f;
    for (int c = threadIdx.x; c < HDIM; c += 256) { float v = x[c]; ss += v * v; }
    __shared__ float red[256];
    red[threadIdx.x] = ss;
    __syncthreads();
    for (int s = 128; s > 0; s >>= 1) {
        if (threadIdx.x < s) red[threadIdx.x] += red[threadIdx.x + s];
        __syncthreads();
    }
    float scale = rsqrtf(red[0] / (float)HDIM + 1e-6f);
    for (int c = threadIdx.x * 2; c < HDIM; c += 512) {
        float v0 = x[c] * scale * w[c];
        float v1 = x[c + 1] * scale * w[c + 1];
        *(__half2*)(act + (size_t)row * HDIM + c) =
            __halves2half2(__float2half(v0), __float2half(v1));
    }
}

// ===== fused: x1 = resid + rmsnorm(in, w1);  act = fp16(rmsnorm(x1, w2)) =====
__global__ void rmsnorm_pair_kernel(const float* __restrict__ in, const float* __restrict__ w1,
                                    const float* __restrict__ resid, const float* __restrict__ w2,
                                    float* __restrict__ x1, __half* __restrict__ act) {
    extern __shared__ float buf[];   // HDIM floats
    __shared__ float red[256];
    int row = blockIdx.x, t = threadIdx.x;
    const float* x = in + (size_t)row * HDIM;
    float ss = 0.f;
    for (int c = t; c < HDIM; c += 256) { float v = x[c]; buf[c] = v; ss += v * v; }
    red[t] = ss;
    __syncthreads();
    for (int s = 128; s > 0; s >>= 1) {
        if (t < s) red[t] += red[t + s];
        __syncthreads();
    }
    float scale = rsqrtf(red[0] / (float)HDIM + 1e-6f);
    __syncthreads();
    float ss2 = 0.f;
    for (int c = t; c < HDIM; c += 256) {
        float v = buf[c] * scale * w1[c] + resid[(size_t)row * HDIM + c];
        buf[c] = v;
        x1[(size_t)row * HDIM + c] = v;
        ss2 += v * v;
    }
    red[t] = ss2;
    __syncthreads();
    for (int s = 128; s > 0; s >>= 1) {
        if (t < s) red[t] += red[t + s];
        __syncthreads();
    }
    float scale2 = rsqrtf(red[0] / (float)HDIM + 1e-6f);
    for (int c = t * 2; c < HDIM; c += 512) {
        float v0 = buf[c] * scale2 * w2[c];
        float v1 = buf[c + 1] * scale2 * w2[c + 1];
        *(__half2*)(act + (size_t)row * HDIM + c) =
            __halves2half2(__float2half(v0), __float2half(v1));
    }
}

// ================= RMSNorm fp32 out (+ residual) =================
__global__ void rmsnorm_kernel(const float* __restrict__ in, const float* __restrict__ w,
                               const float* __restrict__ resid, float* __restrict__ out) {
    int row = blockIdx.x;
    const float* x = in + (size_t)row * HDIM;
    float ss = 0.f;
    for (int c = threadIdx.x; c < HDIM; c += 256) { float v = x[c]; ss += v * v; }
    __shared__ float red[256];
    red[threadIdx.x] = ss;
    __syncthreads();
    for (int s = 128; s > 0; s >>= 1) {
        if (threadIdx.x < s) red[threadIdx.x] += red[threadIdx.x + s];
        __syncthreads();
    }
    float scale = rsqrtf(red[0] / (float)HDIM + 1e-6f);
    for (int c = threadIdx.x; c < HDIM; c += 256) {
        float v = x[c] * scale * w[c];
        if (resid) v += resid[(size_t)row * HDIM + c];
        out[(size_t)row * HDIM + c] = v;
    }
}

// ================= RoPE in-place on fp16 qkv [2048, 8192] =================
__global__ void rope_h_kernel(__half* __restrict__ x) {
    int idx = blockIdx.x * 256 + threadIdx.x;   // over 2048*24*64
    int d2 = (idx & 63) * 2;
    int hh = (idx >> 6) % 24;
    int s = idx / (64 * 24);
    int col = (hh < 16) ? hh * 256 : 4096 + (hh - 16) * 256;
    size_t base = (size_t)s * QKVD + col;
    float2 a = __half22float2(*(__half2*)(x + base + d2));
    float2 b = __half22float2(*(__half2*)(x + base + d2 + 128));
    float c0, s0, c1, s1;
    {
        float invf = (float)exp(-((double)(2 * d2) / (double)HD) * log(10000.0));
        float ang = (float)s * invf;
        c0 = (float)cos((double)ang); s0 = (float)sin((double)ang);
    }
    {
        float invf = (float)exp(-((double)(2 * (d2 + 1)) / (double)HD) * log(10000.0));
        float ang = (float)s * invf;
        c1 = (float)cos((double)ang); s1 = (float)sin((double)ang);
    }
    *(__half2*)(x + base + d2)       = __floats2half2_rn(a.x * c0 - b.x * s0, a.y * c1 - b.y * s1);
    *(__half2*)(x + base + d2 + 128) = __floats2half2_rn(b.x * c0 + a.x * s0, b.y * c1 + a.y * s1);
}

// ====== HMMA flash attention: softcap + online softmax (FA2), causal; fp16 in/out ======
#define AQROW 264
#define AVROW 72
#define SMEM_ATT ((64*AQROW*2 + 256*AVROW) * 2)   // 104448 bytes

__global__ void __launch_bounds__(256, 1)
attn_mma_kernel(const __half* __restrict__ qkv, __half* __restrict__ act) {
    extern __shared__ __half hsm[];
    __half* Qs = hsm;
    __half* Ks = hsm + 64 * AQROW;
    __half* Vs = hsm + 128 * AQROW;

    int qb = gridDim.x - 1 - blockIdx.x;   // longest-first scheduling
    int head = blockIdx.y, kvh = head >> 1;
    int t = threadIdx.x, lane = t & 31, wid = t >> 5;
    int rg = wid & 3, dh = wid >> 2;

    for (int idx = t; idx < 64 * 32; idx += 256) {
        int i = idx >> 5, ch = (idx & 31) * 8;
        *(uint4*)&Qs[i * AQROW + ch] =
            *(const uint4*)&qkv[(size_t)(qb * 64 + i) * QKVD + head * HD + ch];
    }

    float oacc[16][4];
#pragma unroll
    for (int i = 0; i < 16; i++)
#pragma unroll
        for (int e = 0; e < 4; e++) oacc[i][e] = 0.f;
    float sl0 = 0.f, sl1 = 0.f;
    float M0 = -1e30f, M1 = -1e30f;

    uint32_t qAddr = smem_u32(Qs) + (uint32_t)((rg * 16 + (lane & 15)) * AQROW + (lane >> 4) * 8) * 2;
    uint32_t kBase = smem_u32(Ks) + (uint32_t)((lane & 15) * AQROW + (lane >> 4) * 8) * 2;
    uint32_t vBase = smem_u32(Vs) + (uint32_t)((dh * 128 + (lane & 15)) * AVROW + (lane >> 4) * 8) * 2;

    int lrow = rg * 16 + (lane >> 2);

    for (int kb = 0; kb <= qb; kb++) {
        __syncthreads();
        for (int idx = t; idx < 64 * 32; idx += 256) {
            int j = idx >> 5, ch = (idx & 31) * 8;
            *(uint4*)&Ks[j * AQROW + ch] =
                *(const uint4*)&qkv[(size_t)(kb * 64 + j) * QKVD + 4096 + kvh * HD + ch];
        }
        for (int idx = t; idx < 64 * 64; idx += 256) {
            int j = idx >> 6, c = (idx & 63) * 4;
            const __half* gv = &qkv[(size_t)(kb * 64 + j) * QKVD + 6144 + kvh * HD + c];
            __half2 v01 = *(const __half2*)gv;
            __half2 v23 = *(const __half2*)(gv + 2);
            Vs[(c + 0) * AVROW + j] = __low2half(v01);
            Vs[(c + 1) * AVROW + j] = __high2half(v01);
            Vs[(c + 2) * AVROW + j] = __low2half(v23);
            Vs[(c + 3) * AVROW + j] = __high2half(v23);
        }
        __syncthreads();

        float sacc[8][4];
#pragma unroll
        for (int i = 0; i < 8; i++)
#pragma unroll
            for (int e = 0; e < 4; e++) sacc[i][e] = 0.f;
#pragma unroll
        for (int ks = 0; ks < 16; ks++) {
            uint32_t a0, a1, a2, a3;
            ldx4(a0, a1, a2, a3, qAddr + ks * 32);
#pragma unroll
            for (int jt = 0; jt < 4; jt++) {
                uint32_t t0, t1, t2, t3;
                ldx4(t0, t1, t2, t3, kBase + (uint32_t)jt * 16 * AQROW * 2 + ks * 32);
                hmma(sacc[jt * 2],     a0, a1, a2, a3, t0, t2);
                hmma(sacc[jt * 2 + 1], a0, a1, a2, a3, t1, t3);
            }
        }

        bool diag = (kb == qb);
#pragma unroll
        for (int tt = 0; tt < 8; tt++) {
            int colb = tt * 8 + (lane & 3) * 2;
#pragma unroll
            for (int e = 0; e < 4; e++) {
                float sc = sacc[tt][e] * 0.0625f;
                sc = tanhf(sc * 0.02f) * 50.f;
                bool valid = !diag || (colb + (e & 1) <= lrow + (e >> 1) * 8);
                sacc[tt][e] = valid ? sc : -1e30f;
            }
        }

        float m0 = -1e30f, m1 = -1e30f;
#pragma unroll
        for (int tt = 0; tt < 8; tt++) {
            m0 = fmaxf(m0, fmaxf(sacc[tt][0], sacc[tt][1]));
            m1 = fmaxf(m1, fmaxf(sacc[tt][2], sacc[tt][3]));
        }
        m0 = fmaxf(m0, __shfl_xor_sync(0xFFFFFFFF, m0, 1));
        m0 = fmaxf(m0, __shfl_xor_sync(0xFFFFFFFF, m0, 2));
        m1 = fmaxf(m1, __shfl_xor_sync(0xFFFFFFFF, m1, 1));
        m1 = fmaxf(m1, __shfl_xor_sync(0xFFFFFFFF, m1, 2));
        float nM0 = fmaxf(M0, m0), nM1 = fmaxf(M1, m1);
        float f0 = __expf(M0 - nM0), f1 = __expf(M1 - nM1);
        M0 = nM0; M1 = nM1;
        sl0 *= f0; sl1 *= f1;
#pragma unroll
        for (int i = 0; i < 16; i++) {
            oacc[i][0] *= f0; oacc[i][1] *= f0;
            oacc[i][2] *= f1; oacc[i][3] *= f1;
        }

        uint32_t pf[4][4];
#pragma unroll
        for (int tt = 0; tt < 8; tt++) {
            __half2 h01 = __floats2half2_rn(__expf(sacc[tt][0] - M0), __expf(sacc[tt][1] - M0));
            __half2 h23 = __floats2half2_rn(__expf(sacc[tt][2] - M1), __expf(sacc[tt][3] - M1));
            pf[tt >> 1][(tt & 1) * 2]     = *(uint32_t*)&h01;
            pf[tt >> 1][(tt & 1) * 2 + 1] = *(uint32_t*)&h23;
            float2 f01 = __half22float2(h01), f23 = __half22float2(h23);
            sl0 += f01.x + f01.y;
            sl1 += f23.x + f23.y;
        }

#pragma unroll
        for (int s = 0; s < 4; s++) {
#pragma unroll
            for (int i = 0; i < 8; i++) {
                uint32_t t0, t1, t2, t3;
                ldx4(t0, t1, t2, t3, vBase + (uint32_t)i * 16 * AVROW * 2 + s * 32);
                hmma(oacc[i * 2],     pf[s][0], pf[s][1], pf[s][2], pf[s][3], t0, t2);
                hmma(oacc[i * 2 + 1], pf[s][0], pf[s][1], pf[s][2], pf[s][3], t1, t3);
            }
        }
    }

    sl0 += __shfl_xor_sync(0xFFFFFFFF, sl0, 1);
    sl0 += __shfl_xor_sync(0xFFFFFFFF, sl0, 2);
    sl1 += __shfl_xor_sync(0xFFFFFFFF, sl1, 1);
    sl1 += __shfl_xor_sync(0xFFFFFFFF, sl1, 2);
    float inv0 = 1.f / sl0, inv1 = 1.f / sl1;

    int grow = qb * 64 + lrow;
#pragma unroll
    for (int i = 0; i < 16; i++) {
        int gcol = head * HD + dh * 128 + i * 8 + (lane & 3) * 2;
        *(__half2*)&act[(size_t)grow * QD + gcol] =
            __floats2half2_rn(oacc[i][0] * inv0, oacc[i][1] * inv0);
        *(__half2*)&act[(size_t)(grow + 8) * QD + gcol] =
            __floats2half2_rn(oacc[i][2] * inv1, oacc[i][3] * inv1);
    }
}

extern "C" void kernel_launch(void* const* d_in, const int* in_sizes, int n_in,
                              void* d_out, int out_size) {
    const float* hidden      = (const float*)d_in[0];
    const float* w_in        = (const float*)d_in[3];
    const float* w_post_attn = (const float*)d_in[4];
    const float* w_pre_ff    = (const float*)d_in[5];
    const float* w_post_ff   = (const float*)d_in[6];
    const float* wq          = (const float*)d_in[7];
    const float* wk          = (const float*)d_in[8];
    const float* wv          = (const float*)d_in[9];
    const float* wo          = (const float*)d_in[10];
    const float* w_gate      = (const float*)d_in[11];
    const float* w_up        = (const float*)d_in[12];
    const float* w_down      = (const float*)d_in[13];
    float* out = (float*)d_out;

    float *proj, *x1, *down;
    __half *qkvh, *act, *act2, *wt;
    cudaGetSymbolAddress((void**)&proj, g_proj);
    cudaGetSymbolAddress((void**)&x1, g_x1);
    cudaGetSymbolAddress((void**)&down, g_down);
    cudaGetSymbolAddress((void**)&qkvh, g_qkvh);
    cudaGetSymbolAddress((void**)&act, g_act);
    cudaGetSymbolAddress((void**)&act2, g_act2);
    cudaGetSymbolAddress((void**)&wt, g_wt);

    cudaFuncSetAttribute(gemm_mma, cudaFuncAttributeMaxDynamicSharedMemorySize, SMEM_MMA);
    cudaFuncSetAttribute(gemm_mma_h, cudaFuncAttributeMaxDynamicSharedMemorySize, SMEM_MMA);
    cudaFuncSetAttribute(gemm_swiglu, cudaFuncAttributeMaxDynamicSharedMemorySize, SMEM_MMA);
    cudaFuncSetAttribute(attn_mma_kernel, cudaFuncAttributeMaxDynamicSharedMemorySize, SMEM_ATT);
    cudaFuncSetAttribute(rmsnorm_pair_kernel, cudaFuncAttributeMaxDynamicSharedMemorySize, HDIM * 4);

    // ---- attention block ----
    rmsnorm_h_kernel<<<SQ, 256>>>(hidden, w_in, act);
    convert_wt<<<HDIM * (QD/4)   / 256, 256>>>(wq, wt, QD,   QKVD, 0);
    convert_wt<<<HDIM * (2048/4) / 256, 256>>>(wk, wt, 2048, QKVD, 4096);
    convert_wt<<<HDIM * (2048/4) / 256, 256>>>(wv, wt, 2048, QKVD, 6144);
    gemm_mma_h<<<dim3(SQ/BM, QKVD/BN), 256, SMEM_MMA>>>(act, wt, qkvh, QKVD, HDIM);
    rope_h_kernel<<<SQ * 24 * 64 / 256, 256>>>(qkvh);
    attn_mma_kernel<<<dim3(SQ/64, NH), 256, SMEM_ATT>>>(qkvh, act);
    convert_wt<<<QD * (HDIM/4) / 256, 256>>>(wo, wt, HDIM, HDIM, 0);
    gemm_mma<<<dim3(SQ/BM, HDIM/BN), 256, SMEM_MMA>>>(act, wt, proj, HDIM, QD);
    rmsnorm_pair_kernel<<<SQ, 256, HDIM * 4>>>(proj, w_post_attn, hidden, w_pre_ff, x1, act);

    // ---- MLP block ----
    convert_wt_swi<<<HDIM * (IDIM/4) / 256, 256>>>(w_gate, wt, IDIM, 0);
    convert_wt_swi<<<HDIM * (IDIM/4) / 256, 256>>>(w_up,   wt, IDIM, 1);
    gemm_swiglu<<<dim3(SQ/BM, 2*IDIM/BN), 256, SMEM_MMA>>>(act, wt, act2, HDIM);
    convert_wt<<<IDIM * (HDIM/4) / 256, 256>>>(w_down, wt, HDIM, HDIM, 0);
    gemm_mma<<<dim3(SQ/BM, HDIM/BN), 256, SMEM_MMA>>>(act2, wt, down, HDIM, IDIM);
    rmsnorm_kernel<<<SQ, 256>>>(down, w_post_ff, x1, out);
}

// round 17
// speedup vs baseline: 3.0687x; 1.2461x over previous
#include <cuda_runtime.h>
#include <cuda_fp16.h>
#include <math.h>
#include <stdint.h>

#define SQ 2048
#define HDIM 3584
#define NH 16
#define NKV 8
#define HD 256
#define QKVD 8192           // 4096 q + 2048 k + 2048 v
#define QD 4096
#define IDIM 14336

// ---------------- scratch (allocation-free: __device__ globals) ----------------
static __device__ float g_proj[SQ*HDIM];
static __device__ float g_x1[SQ*HDIM];
static __device__ float g_down[SQ*HDIM];
static __device__ float2 g_ropetab[SQ*128];               // cos/sin per (s, d)
static __device__ __half g_qkvh[SQ*QKVD];                 // fp16 qkv
static __device__ __half g_act[(size_t)SQ*IDIM];          // GEMM A operand
static __device__ __half g_act2[(size_t)SQ*IDIM];         // swiglu output (down-GEMM A)
static __device__ __half g_wt[(size_t)IDIM*2*HDIM];       // B fp16 [K][N] natural layout

// ---------------- PTX helpers (arch-agnostic only: sm_80-level) ----------------
__device__ __forceinline__ uint32_t smem_u32(const void* p) {
    uint32_t a;
    asm("{ .reg .u64 t; cvta.to.shared.u64 t, %1; cvt.u32.u64 %0, t; }" : "=r"(a) : "l"(p));
    return a;
}
__device__ __forceinline__ void ldx4(uint32_t& r0, uint32_t& r1, uint32_t& r2, uint32_t& r3, uint32_t a) {
    asm volatile("ldmatrix.sync.aligned.m8n8.x4.shared.b16 {%0,%1,%2,%3}, [%4];"
                 : "=r"(r0), "=r"(r1), "=r"(r2), "=r"(r3) : "r"(a));
}
__device__ __forceinline__ void ldx4t(uint32_t& r0, uint32_t& r1, uint32_t& r2, uint32_t& r3, uint32_t a) {
    asm volatile("ldmatrix.sync.aligned.m8n8.x4.trans.shared.b16 {%0,%1,%2,%3}, [%4];"
                 : "=r"(r0), "=r"(r1), "=r"(r2), "=r"(r3) : "r"(a));
}
__device__ __forceinline__ void hmma(float* c, uint32_t a0, uint32_t a1, uint32_t a2, uint32_t a3,
                                     uint32_t b0, uint32_t b1) {
    asm volatile("mma.sync.aligned.m16n8k16.row.col.f32.f16.f16.f32 "
                 "{%0,%1,%2,%3},{%4,%5,%6,%7},{%8,%9},{%0,%1,%2,%3};"
                 : "+f"(c[0]), "+f"(c[1]), "+f"(c[2]), "+f"(c[3])
                 : "r"(a0), "r"(a1), "r"(a2), "r"(a3), "r"(b0), "r"(b1));
}
#define CP_ASYNC16(dst, src) \
    asm volatile("cp.async.cg.shared.global [%0], [%1], 16;" :: "r"(dst), "l"(src))
#define CP_COMMIT() asm volatile("cp.async.commit_group;" ::: "memory")
#define CP_WAIT(n)  asm volatile("cp.async.wait_group %0;" :: "n"(n) : "memory")

// ============ HMMA fp16 GEMM: C[M,N] = A[M,K] @ B[K,N] (B natural row-major) ============
#define BM 128
#define BN 128
#define BK 64
#define STG 3
#define ROWH 72                               // A smem row: 64 + 8 pad halves
#define BROWH 136                             // B smem row: 128 + 8 pad halves
#define STAGE_A (BM*ROWH*2)                   // 18432
#define STAGE_BB (BK*BROWH*2)                 // 17408
#define STAGE_TOT (STAGE_A + STAGE_BB)        // 35840
#define SMEM_MMA (STG*STAGE_TOT)              // 107520

#define GEMM_MAINLOOP(A_, B_, N_, K_)                                                     \
    int lrA = tid >> 3, lcA = (tid & 7) * 8;                                              \
    const __half* gA0 = (A_) + (size_t)(m0 + lrA) * (K_) + lcA;                           \
    uint32_t sOffA = (uint32_t)(lrA * ROWH + lcA) * 2;                                    \
    int lrB = tid >> 4, lcB = (tid & 15) * 8;                                             \
    const __half* gB0 = (B_) + (size_t)lrB * (N_) + n0 + lcB;                             \
    uint32_t sOffB = (uint32_t)(lrB * BROWH + lcB) * 2;                                   \
    uint32_t foffA = (uint32_t)(((lane & 15) * ROWH) + ((lane >> 4) * 8)) * 2;            \
    uint32_t foffB = (uint32_t)(((lane & 15) * BROWH) + ((lane >> 4) * 8)) * 2;           \
    float acc[4][4][4];                                                                   \
    _Pragma("unroll") for (int a = 0; a < 4; a++)                                         \
        _Pragma("unroll") for (int b = 0; b < 4; b++)                                     \
            _Pragma("unroll") for (int c = 0; c < 4; c++) acc[a][b][c] = 0.f;             \
    int ntiles = (K_) / BK;                                                               \
    auto LOAD = [&](int kt, int s) {                                                      \
        int ak = kt * BK;                                                                 \
        uint32_t sA = sbase + s * STAGE_TOT;                                              \
        uint32_t sB = sA + STAGE_A;                                                       \
        _Pragma("unroll") for (int h = 0; h < 4; h++)                                     \
            CP_ASYNC16(sA + sOffA + h * 32 * ROWH * 2, gA0 + (size_t)h * 32 * (K_) + ak); \
        _Pragma("unroll") for (int h = 0; h < 4; h++)                                     \
            CP_ASYNC16(sB + sOffB + h * 16 * BROWH * 2, gB0 + (size_t)(ak + h * 16) * (N_)); \
    };                                                                                    \
    _Pragma("unroll") for (int s = 0; s < STG - 1; s++) { LOAD(s, s); CP_COMMIT(); }      \
    for (int i = 0; i < ntiles; i++) {                                                    \
        CP_WAIT(STG - 2);                                                                 \
        __syncthreads();                                                                  \
        int pf = i + STG - 1;                                                             \
        if (pf < ntiles) LOAD(pf, pf % STG);                                              \
        CP_COMMIT();                                                                      \
        int s = i % STG;                                                                  \
        uint32_t aB = sbase + s * STAGE_TOT;                                              \
        uint32_t bB = aB + STAGE_A;                                                       \
        uint32_t aAddr = aB + (uint32_t)wm * ROWH * 2 + foffA;                            \
        uint32_t bAddr = bB + (uint32_t)wn * 2 + foffB;                                   \
        _Pragma("unroll") for (int ks = 0; ks < 4; ks++) {                                \
            uint32_t af[4][4];                                                            \
            _Pragma("unroll") for (int fm = 0; fm < 4; fm++)                              \
                ldx4(af[fm][0], af[fm][1], af[fm][2], af[fm][3],                          \
                     aAddr + (uint32_t)fm * 16 * ROWH * 2 + ks * 32);                     \
            uint32_t base = bAddr + (uint32_t)ks * 16 * BROWH * 2;                        \
            uint32_t t0, t1, t2, t3, t4, t5, t6, t7;                                      \
            ldx4t(t0, t1, t2, t3, base);                                                  \
            ldx4t(t4, t5, t6, t7, base + 32);                                             \
            uint32_t b0[4] = {t0, t2, t4, t6};                                            \
            uint32_t b1[4] = {t1, t3, t5, t7};                                            \
            _Pragma("unroll") for (int fm = 0; fm < 4; fm++)                              \
                _Pragma("unroll") for (int fn = 0; fn < 4; fn++)                          \
                    hmma(acc[fm][fn], af[fm][0], af[fm][1], af[fm][2], af[fm][3],         \
                         b0[fn], b1[fn]);                                                 \
        }                                                                                 \
    }

__global__ void __launch_bounds__(256, 2)
gemm_mma(const __half* __restrict__ A, const __half* __restrict__ B,
         float* __restrict__ C, int N, int K) {
    extern __shared__ char smem[];
    uint32_t sbase = smem_u32(smem);
    int tid = threadIdx.x, lane = tid & 31, wid = tid >> 5;
    int m0 = blockIdx.x * BM, n0 = blockIdx.y * BN;
    int wm = (wid & 1) * 64, wn = (wid >> 1) * 32;
    GEMM_MAINLOOP(A, B, N, K)
#pragma unroll
    for (int fm = 0; fm < 4; fm++) {
        int r = m0 + wm + fm * 16 + (lane >> 2);
#pragma unroll
        for (int fn = 0; fn < 4; fn++) {
            int c = n0 + wn + fn * 8 + (lane & 3) * 2;
            *(float2*)&C[(size_t)r * N + c]       = make_float2(acc[fm][fn][0], acc[fm][fn][1]);
            *(float2*)&C[(size_t)(r + 8) * N + c] = make_float2(acc[fm][fn][2], acc[fm][fn][3]);
        }
    }
}

// fp16-output GEMM (for qkv)
__global__ void __launch_bounds__(256, 2)
gemm_mma_h(const __half* __restrict__ A, const __half* __restrict__ B,
           __half* __restrict__ C, int N, int K) {
    extern __shared__ char smem[];
    uint32_t sbase = smem_u32(smem);
    int tid = threadIdx.x, lane = tid & 31, wid = tid >> 5;
    int m0 = blockIdx.x * BM, n0 = blockIdx.y * BN;
    int wm = (wid & 1) * 64, wn = (wid >> 1) * 32;
    GEMM_MAINLOOP(A, B, N, K)
#pragma unroll
    for (int fm = 0; fm < 4; fm++) {
        int r = m0 + wm + fm * 16 + (lane >> 2);
#pragma unroll
        for (int fn = 0; fn < 4; fn++) {
            int c = n0 + wn + fn * 8 + (lane & 3) * 2;
            *(__half2*)&C[(size_t)r * N + c]       = __floats2half2_rn(acc[fm][fn][0], acc[fm][fn][1]);
            *(__half2*)&C[(size_t)(r + 8) * N + c] = __floats2half2_rn(acc[fm][fn][2], acc[fm][fn][3]);
        }
    }
}

// gate/up GEMM with fused SwiGLU epilogue (column-interleaved B)
__global__ void __launch_bounds__(256, 2)
gemm_swiglu(const __half* __restrict__ A, const __half* __restrict__ B,
            __half* __restrict__ O, int K) {
    extern __shared__ char smem[];
    uint32_t sbase = smem_u32(smem);
    int tid = threadIdx.x, lane = tid & 31, wid = tid >> 5;
    int m0 = blockIdx.x * BM, n0 = blockIdx.y * BN;
    int wm = (wid & 1) * 64, wn = (wid >> 1) * 32;
    GEMM_MAINLOOP(A, B, 2 * IDIM, K)
    __syncthreads();
    float* Cs = (float*)smem;              // [128][132]
#pragma unroll
    for (int fm = 0; fm < 4; fm++) {
        int r = wm + fm * 16 + (lane >> 2);
#pragma unroll
        for (int fn = 0; fn < 4; fn++) {
            int c = wn + fn * 8 + (lane & 3) * 2;
            *(float2*)&Cs[r * 132 + c]       = make_float2(acc[fm][fn][0], acc[fm][fn][1]);
            *(float2*)&Cs[(r + 8) * 132 + c] = make_float2(acc[fm][fn][2], acc[fm][fn][3]);
        }
    }
    __syncthreads();
    int colb = blockIdx.y * 64;
    for (int idx = tid; idx < 128 * 32; idx += 256) {
        int r = idx >> 5, c = (idx & 31) * 2;
        float2 g = *(float2*)&Cs[r * 132 + c];
        float2 u = *(float2*)&Cs[r * 132 + 64 + c];
        float t0 = tanhf(0.7978845608028654f * (g.x + 0.044715f * g.x * g.x * g.x));
        float t1 = tanhf(0.7978845608028654f * (g.y + 0.044715f * g.y * g.y * g.y));
        float v0 = 0.5f * g.x * (1.f + t0) * u.x;
        float v1 = 0.5f * g.y * (1.f + t1) * u.y;
        *(__half2*)&O[(size_t)(m0 + r) * IDIM + colb + c] =
            __halves2half2(__float2half(v0), __float2half(v1));
    }
}

// ===== elementwise fp32 -> fp16 cast, 2D grid (no division), 8 floats/thread =====
// grid: (N/8/64, K), block 64. out column offset n_off, out row stride NOUT.
__global__ void convert_wt(const float* __restrict__ W, __half* __restrict__ out,
                           int N, int NOUT, int n_off) {
    int k = blockIdx.y;
    int n8 = (blockIdx.x * 64 + threadIdx.x) * 8;
    const float* src = W + (size_t)k * N + n8;
    float4 a = *(const float4*)src;
    float4 b = *(const float4*)(src + 4);
    __half2 h[4] = {__floats2half2_rn(a.x, a.y), __floats2half2_rn(a.z, a.w),
                    __floats2half2_rn(b.x, b.y), __floats2half2_rn(b.z, b.w)};
    *(uint4*)(out + (size_t)k * NOUT + n_off + n8) = *(uint4*)h;
}

// gate/up column-interleaved cast: col n -> (n/64)*128 + which*64 + (n%64)
__global__ void convert_wt_swi(const float* __restrict__ W, __half* __restrict__ out,
                               int N, int which) {
    int k = blockIdx.y;
    int n8 = (blockIdx.x * 64 + threadIdx.x) * 8;
    const float* src = W + (size_t)k * N + n8;
    float4 a = *(const float4*)src;
    float4 b = *(const float4*)(src + 4);
    __half2 h[4] = {__floats2half2_rn(a.x, a.y), __floats2half2_rn(a.z, a.w),
                    __floats2half2_rn(b.x, b.y), __floats2half2_rn(b.z, b.w)};
    int ncol = (n8 >> 6) * 128 + which * 64 + (n8 & 63);
    *(uint4*)(out + (size_t)k * (2 * IDIM) + ncol) = *(uint4*)h;
}

// ===== RMSNorm writing fp16 directly =====
__global__ void rmsnorm_h_kernel(const float* __restrict__ in, const float* __restrict__ w,
                                 __half* __restrict__ act) {
    int row = blockIdx.x;
    const float* x = in + (size_t)row * HDIM;
    float ss = 0.f;
    for (int c = threadIdx.x; c < HDIM; c += 256) { float v = x[c]; ss += v * v; }
    __shared__ float red[256];
    red[threadIdx.x] = ss;
    __syncthreads();
    for (int s = 128; s > 0; s >>= 1) {
        if (threadIdx.x < s) red[threadIdx.x] += red[threadIdx.x + s];
        __syncthreads();
    }
    float scale = rsqrtf(red[0] / (float)HDIM + 1e-6f);
    for (int c = threadIdx.x * 2; c < HDIM; c += 512) {
        float v0 = x[c] * scale * w[c];
        float v1 = x[c + 1] * scale * w[c + 1];
        *(__half2*)(act + (size_t)row * HDIM + c) =
            __halves2half2(__float2half(v0), __float2half(v1));
    }
}

// ===== fused: x1 = resid + rmsnorm(in, w1);  act = fp16(rmsnorm(x1, w2)) =====
__global__ void rmsnorm_pair_kernel(const float* __restrict__ in, const float* __restrict__ w1,
                                    const float* __restrict__ resid, const float* __restrict__ w2,
                                    float* __restrict__ x1, __half* __restrict__ act) {
    extern __shared__ float buf[];   // HDIM floats
    __shared__ float red[256];
    int row = blockIdx.x, t = threadIdx.x;
    const float* x = in + (size_t)row * HDIM;
    float ss = 0.f;
    for (int c = t; c < HDIM; c += 256) { float v = x[c]; buf[c] = v; ss += v * v; }
    red[t] = ss;
    __syncthreads();
    for (int s = 128; s > 0; s >>= 1) {
        if (t < s) red[t] += red[t + s];
        __syncthreads();
    }
    float scale = rsqrtf(red[0] / (float)HDIM + 1e-6f);
    __syncthreads();
    float ss2 = 0.f;
    for (int c = t; c < HDIM; c += 256) {
        float v = buf[c] * scale * w1[c] + resid[(size_t)row * HDIM + c];
        buf[c] = v;
        x1[(size_t)row * HDIM + c] = v;
        ss2 += v * v;
    }
    red[t] = ss2;
    __syncthreads();
    for (int s = 128; s > 0; s >>= 1) {
        if (t < s) red[t] += red[t + s];
        __syncthreads();
    }
    float scale2 = rsqrtf(red[0] / (float)HDIM + 1e-6f);
    for (int c = t * 2; c < HDIM; c += 512) {
        float v0 = buf[c] * scale2 * w2[c];
        float v1 = buf[c + 1] * scale2 * w2[c + 1];
        *(__half2*)(act + (size_t)row * HDIM + c) =
            __halves2half2(__float2half(v0), __float2half(v1));
    }
}

// ================= RMSNorm fp32 out (+ residual) =================
__global__ void rmsnorm_kernel(const float* __restrict__ in, const float* __restrict__ w,
                               const float* __restrict__ resid, float* __restrict__ out) {
    int row = blockIdx.x;
    const float* x = in + (size_t)row * HDIM;
    float ss = 0.f;
    for (int c = threadIdx.x; c < HDIM; c += 256) { float v = x[c]; ss += v * v; }
    __shared__ float red[256];
    red[threadIdx.x] = ss;
    __syncthreads();
    for (int s = 128; s > 0; s >>= 1) {
        if (threadIdx.x < s) red[threadIdx.x] += red[threadIdx.x + s];
        __syncthreads();
    }
    float scale = rsqrtf(red[0] / (float)HDIM + 1e-6f);
    for (int c = threadIdx.x; c < HDIM; c += 256) {
        float v = x[c] * scale * w[c];
        if (resid) v += resid[(size_t)row * HDIM + c];
        out[(size_t)row * HDIM + c] = v;
    }
}

// ===== RoPE cos/sin table: tab[s*128+d] = (cos, sin) of s * invfreq(d) =====
__global__ void rope_tab_kernel(float2* __restrict__ tab) {
    int idx = blockIdx.x * 256 + threadIdx.x;   // over 2048*128
    int d = idx & 127;
    int s = idx >> 7;
    float invf = (float)exp(-((double)(2 * d) / (double)HD) * log(10000.0));
    float ang = (float)s * invf;
    tab[idx] = make_float2((float)cos((double)ang), (float)sin((double)ang));
}

// ================= RoPE in-place on fp16 qkv [2048, 8192], table-driven =================
__global__ void rope_h_kernel(__half* __restrict__ x, const float2* __restrict__ tab) {
    int idx = blockIdx.x * 256 + threadIdx.x;   // over 2048*24*64
    int d2 = (idx & 63) * 2;
    int hh = (idx >> 6) % 24;
    int s = idx / (64 * 24);
    int col = (hh < 16) ? hh * 256 : 4096 + (hh - 16) * 256;
    size_t base = (size_t)s * QKVD + col;
    float2 a = __half22float2(*(__half2*)(x + base + d2));
    float2 b = __half22float2(*(__half2*)(x + base + d2 + 128));
    float2 cs0 = tab[s * 128 + d2];
    float2 cs1 = tab[s * 128 + d2 + 1];
    *(__half2*)(x + base + d2)       = __floats2half2_rn(a.x * cs0.x - b.x * cs0.y, a.y * cs1.x - b.y * cs1.y);
    *(__half2*)(x + base + d2 + 128) = __floats2half2_rn(b.x * cs0.x + a.x * cs0.y, b.y * cs1.x + a.y * cs1.y);
}

// ====== HMMA flash attention: softcap + online softmax (FA2), causal; fp16 in/out ======
#define AQROW 264
#define AVROW 72
#define SMEM_ATT ((64*AQROW*2 + 256*AVROW) * 2)   // 104448 bytes

__global__ void __launch_bounds__(256, 1)
attn_mma_kernel(const __half* __restrict__ qkv, __half* __restrict__ act) {
    extern __shared__ __half hsm[];
    __half* Qs = hsm;
    __half* Ks = hsm + 64 * AQROW;
    __half* Vs = hsm + 128 * AQROW;

    int qb = gridDim.x - 1 - blockIdx.x;   // longest-first scheduling
    int head = blockIdx.y, kvh = head >> 1;
    int t = threadIdx.x, lane = t & 31, wid = t >> 5;
    int rg = wid & 3, dh = wid >> 2;

    for (int idx = t; idx < 64 * 32; idx += 256) {
        int i = idx >> 5, ch = (idx & 31) * 8;
        *(uint4*)&Qs[i * AQROW + ch] =
            *(const uint4*)&qkv[(size_t)(qb * 64 + i) * QKVD + head * HD + ch];
    }

    float oacc[16][4];
#pragma unroll
    for (int i = 0; i < 16; i++)
#pragma unroll
        for (int e = 0; e < 4; e++) oacc[i][e] = 0.f;
    float sl0 = 0.f, sl1 = 0.f;
    float M0 = -1e30f, M1 = -1e30f;

    uint32_t qAddr = smem_u32(Qs) + (uint32_t)((rg * 16 + (lane & 15)) * AQROW + (lane >> 4) * 8) * 2;
    uint32_t kBase = smem_u32(Ks) + (uint32_t)((lane & 15) * AQROW + (lane >> 4) * 8) * 2;
    uint32_t vBase = smem_u32(Vs) + (uint32_t)((dh * 128 + (lane & 15)) * AVROW + (lane >> 4) * 8) * 2;

    int lrow = rg * 16 + (lane >> 2);

    for (int kb = 0; kb <= qb; kb++) {
        __syncthreads();
        for (int idx = t; idx < 64 * 32; idx += 256) {
            int j = idx >> 5, ch = (idx & 31) * 8;
            *(uint4*)&Ks[j * AQROW + ch] =
                *(const uint4*)&qkv[(size_t)(kb * 64 + j) * QKVD + 4096 + kvh * HD + ch];
        }
        for (int idx = t; idx < 64 * 64; idx += 256) {
            int j = idx >> 6, c = (idx & 63) * 4;
            const __half* gv = &qkv[(size_t)(kb * 64 + j) * QKVD + 6144 + kvh * HD + c];
            __half2 v01 = *(const __half2*)gv;
            __half2 v23 = *(const __half2*)(gv + 2);
            Vs[(c + 0) * AVROW + j] = __low2half(v01);
            Vs[(c + 1) * AVROW + j] = __high2half(v01);
            Vs[(c + 2) * AVROW + j] = __low2half(v23);
            Vs[(c + 3) * AVROW + j] = __high2half(v23);
        }
        __syncthreads();

        float sacc[8][4];
#pragma unroll
        for (int i = 0; i < 8; i++)
#pragma unroll
            for (int e = 0; e < 4; e++) sacc[i][e] = 0.f;
#pragma unroll
        for (int ks = 0; ks < 16; ks++) {
            uint32_t a0, a1, a2, a3;
            ldx4(a0, a1, a2, a3, qAddr + ks * 32);
#pragma unroll
            for (int jt = 0; jt < 4; jt++) {
                uint32_t t0, t1, t2, t3;
                ldx4(t0, t1, t2, t3, kBase + (uint32_t)jt * 16 * AQROW * 2 + ks * 32);
                hmma(sacc[jt * 2],     a0, a1, a2, a3, t0, t2);
                hmma(sacc[jt * 2 + 1], a0, a1, a2, a3, t1, t3);
            }
        }

        bool diag = (kb == qb);
#pragma unroll
        for (int tt = 0; tt < 8; tt++) {
            int colb = tt * 8 + (lane & 3) * 2;
#pragma unroll
            for (int e = 0; e < 4; e++) {
                float sc = sacc[tt][e] * 0.0625f;
                sc = tanhf(sc * 0.02f) * 50.f;
                bool valid = !diag || (colb + (e & 1) <= lrow + (e >> 1) * 8);
                sacc[tt][e] = valid ? sc : -1e30f;
            }
        }

        float m0 = -1e30f, m1 = -1e30f;
#pragma unroll
        for (int tt = 0; tt < 8; tt++) {
            m0 = fmaxf(m0, fmaxf(sacc[tt][0], sacc[tt][1]));
            m1 = fmaxf(m1, fmaxf(sacc[tt][2], sacc[tt][3]));
        }
        m0 = fmaxf(m0, __shfl_xor_sync(0xFFFFFFFF, m0, 1));
        m0 = fmaxf(m0, __shfl_xor_sync(0xFFFFFFFF, m0, 2));
        m1 = fmaxf(m1, __shfl_xor_sync(0xFFFFFFFF, m1, 1));
        m1 = fmaxf(m1, __shfl_xor_sync(0xFFFFFFFF, m1, 2));
        float nM0 = fmaxf(M0, m0), nM1 = fmaxf(M1, m1);
        float f0 = __expf(M0 - nM0), f1 = __expf(M1 - nM1);
        M0 = nM0; M1 = nM1;
        sl0 *= f0; sl1 *= f1;
#pragma unroll
        for (int i = 0; i < 16; i++) {
            oacc[i][0] *= f0; oacc[i][1] *= f0;
            oacc[i][2] *= f1; oacc[i][3] *= f1;
        }

        uint32_t pf[4][4];
#pragma unroll
        for (int tt = 0; tt < 8; tt++) {
            __half2 h01 = __floats2half2_rn(__expf(sacc[tt][0] - M0), __expf(sacc[tt][1] - M0));
            __half2 h23 = __floats2half2_rn(__expf(sacc[tt][2] - M1), __expf(sacc[tt][3] - M1));
            pf[tt >> 1][(tt & 1) * 2]     = *(uint32_t*)&h01;
            pf[tt >> 1][(tt & 1) * 2 + 1] = *(uint32_t*)&h23;
            float2 f01 = __half22float2(h01), f23 = __half22float2(h23);
            sl0 += f01.x + f01.y;
            sl1 += f23.x + f23.y;
        }

#pragma unroll
        for (int s = 0; s < 4; s++) {
#pragma unroll
            for (int i = 0; i < 8; i++) {
                uint32_t t0, t1, t2, t3;
                ldx4(t0, t1, t2, t3, vBase + (uint32_t)i * 16 * AVROW * 2 + s * 32);
                hmma(oacc[i * 2],     pf[s][0], pf[s][1], pf[s][2], pf[s][3], t0, t2);
                hmma(oacc[i * 2 + 1], pf[s][0], pf[s][1], pf[s][2], pf[s][3], t1, t3);
            }
        }
    }

    sl0 += __shfl_xor_sync(0xFFFFFFFF, sl0, 1);
    sl0 += __shfl_xor_sync(0xFFFFFFFF, sl0, 2);
    sl1 += __shfl_xor_sync(0xFFFFFFFF, sl1, 1);
    sl1 += __shfl_xor_sync(0xFFFFFFFF, sl1, 2);
    float inv0 = 1.f / sl0, inv1 = 1.f / sl1;

    int grow = qb * 64 + lrow;
#pragma unroll
    for (int i = 0; i < 16; i++) {
        int gcol = head * HD + dh * 128 + i * 8 + (lane & 3) * 2;
        *(__half2*)&act[(size_t)grow * QD + gcol] =
            __floats2half2_rn(oacc[i][0] * inv0, oacc[i][1] * inv0);
        *(__half2*)&act[(size_t)(grow + 8) * QD + gcol] =
            __floats2half2_rn(oacc[i][2] * inv1, oacc[i][3] * inv1);
    }
}

extern "C" void kernel_launch(void* const* d_in, const int* in_sizes, int n_in,
                              void* d_out, int out_size) {
    const float* hidden      = (const float*)d_in[0];
    const float* w_in        = (const float*)d_in[3];
    const float* w_post_attn = (const float*)d_in[4];
    const float* w_pre_ff    = (const float*)d_in[5];
    const float* w_post_ff   = (const float*)d_in[6];
    const float* wq          = (const float*)d_in[7];
    const float* wk          = (const float*)d_in[8];
    const float* wv          = (const float*)d_in[9];
    const float* wo          = (const float*)d_in[10];
    const float* w_gate      = (const float*)d_in[11];
    const float* w_up        = (const float*)d_in[12];
    const float* w_down      = (const float*)d_in[13];
    float* out = (float*)d_out;

    float *proj, *x1, *down;
    float2* ropetab;
    __half *qkvh, *act, *act2, *wt;
    cudaGetSymbolAddress((void**)&proj, g_proj);
    cudaGetSymbolAddress((void**)&x1, g_x1);
    cudaGetSymbolAddress((void**)&down, g_down);
    cudaGetSymbolAddress((void**)&ropetab, g_ropetab);
    cudaGetSymbolAddress((void**)&qkvh, g_qkvh);
    cudaGetSymbolAddress((void**)&act, g_act);
    cudaGetSymbolAddress((void**)&act2, g_act2);
    cudaGetSymbolAddress((void**)&wt, g_wt);

    cudaFuncSetAttribute(gemm_mma, cudaFuncAttributeMaxDynamicSharedMemorySize, SMEM_MMA);
    cudaFuncSetAttribute(gemm_mma_h, cudaFuncAttributeMaxDynamicSharedMemorySize, SMEM_MMA);
    cudaFuncSetAttribute(gemm_swiglu, cudaFuncAttributeMaxDynamicSharedMemorySize, SMEM_MMA);
    cudaFuncSetAttribute(attn_mma_kernel, cudaFuncAttributeMaxDynamicSharedMemorySize, SMEM_ATT);
    cudaFuncSetAttribute(rmsnorm_pair_kernel, cudaFuncAttributeMaxDynamicSharedMemorySize, HDIM * 4);

    // ---- attention block ----
    rope_tab_kernel<<<SQ * 128 / 256, 256>>>(ropetab);
    rmsnorm_h_kernel<<<SQ, 256>>>(hidden, w_in, act);
    convert_wt<<<dim3(QD/8/64,   HDIM), 64>>>(wq, wt, QD,   QKVD, 0);
    convert_wt<<<dim3(2048/8/64, HDIM), 64>>>(wk, wt, 2048, QKVD, 4096);
    convert_wt<<<dim3(2048/8/64, HDIM), 64>>>(wv, wt, 2048, QKVD, 6144);
    gemm_mma_h<<<dim3(SQ/BM, QKVD/BN), 256, SMEM_MMA>>>(act, wt, qkvh, QKVD, HDIM);
    rope_h_kernel<<<SQ * 24 * 64 / 256, 256>>>(qkvh, ropetab);
    attn_mma_kernel<<<dim3(SQ/64, NH), 256, SMEM_ATT>>>(qkvh, act);
    convert_wt<<<dim3(HDIM/8/64, QD), 64>>>(wo, wt, HDIM, HDIM, 0);
    gemm_mma<<<dim3(SQ/BM, HDIM/BN), 256, SMEM_MMA>>>(act, wt, proj, HDIM, QD);
    rmsnorm_pair_kernel<<<SQ, 256, HDIM * 4>>>(proj, w_post_attn, hidden, w_pre_ff, x1, act);

    // ---- MLP block ----
    convert_wt_swi<<<dim3(IDIM/8/64, HDIM), 64>>>(w_gate, wt, IDIM, 0);
    convert_wt_swi<<<dim3(IDIM/8/64, HDIM), 64>>>(w_up,   wt, IDIM, 1);
    gemm_swiglu<<<dim3(SQ/BM, 2*IDIM/BN), 256, SMEM_MMA>>>(act, wt, act2, HDIM);
    convert_wt<<<dim3(HDIM/8/64, IDIM), 64>>>(w_down, wt, HDIM, HDIM, 0);
    gemm_mma<<<dim3(SQ/BM, HDIM/BN), 256, SMEM_MMA>>>(act2, wt, down, HDIM, IDIM);
    rmsnorm_kernel<<<SQ, 256>>>(down, w_post_ff, x1, out);
}